// round 2
// baseline (speedup 1.0000x reference)
#include <cuda_runtime.h>
#include <math_constants.h>
#include <math.h>

#define Bsz 2
#define Nn 1024
#define N1 1025
#define Dm 128
#define Hh 8
#define Dk 16
#define Dff 512
#define NBk 32
#define KNN 10
#define AW 33          // 33 x 32-bit words cover 1025 mask bits per row
#define EPSf 1e-5f
#define SCALEf 0.25f   // 1/sqrt(16)

// ------------------------- persistent device scratch -------------------------
__device__ float    d_HG [Bsz*N1*Dm];     // state: rows 0..1023 = h, row 1024 = g
__device__ float    d_POOL[Bsz*Dm];
__device__ float    d_SQ [Bsz*Nn];
__device__ float    d_D2 [(size_t)Bsz*Nn*Nn];
__device__ unsigned d_ADJ[Bsz*N1*AW];
__device__ float    d_Q  [Bsz*N1*Dm];
__device__ float    d_Kb [Bsz*N1*Dm];
__device__ float    d_Vb [Bsz*N1*Dm];
__device__ float    d_CTX[Bsz*N1*Dm];
__device__ float    d_QE [Bsz*N1*Hh*NBk];
__device__ float    d_Y  [Bsz*N1*Dm];
__device__ float    d_T1 [Bsz*N1*Dff];
__device__ float    d_T2 [Bsz*N1*Dm];
__device__ float    d_X  [Bsz*Nn*Dm];

// ------------------------- input embedding + state init ----------------------
__global__ void k_input(const float* __restrict__ coords, const float* __restrict__ inW,
                        const float* __restrict__ inb, const float* __restrict__ gnode)
{
    int gid = blockIdx.x*blockDim.x + threadIdx.x;
    if (gid < Bsz*Dm) d_POOL[gid] = 0.f;
    if (gid >= Bsz*N1*Dm) return;
    int d = gid % Dm;
    int n = (gid / Dm) % N1;
    int b = gid / (Dm*N1);
    float v;
    if (n < Nn) {
        float x = coords[(b*Nn+n)*2+0];
        float y = coords[(b*Nn+n)*2+1];
        v = x*inW[d*2+0] + y*inW[d*2+1] + inb[d];
    } else {
        v = gnode[d];
    }
    d_HG[gid] = v;
}

// ------------------------- layer-0 g update: g += mean(h) --------------------
__global__ void k_colmean()
{
    __shared__ float red[8][Dm];
    int b = blockIdx.x;
    int d = threadIdx.x & 127;
    int g = threadIdx.x >> 7;
    const float* base = d_HG + (size_t)b*N1*Dm;
    float s = 0.f;
    for (int n = g; n < Nn; n += 8) s += base[n*Dm + d];
    red[g][d] = s;
    __syncthreads();
    if (g == 0) {
        float t = 0.f;
        #pragma unroll
        for (int i = 0; i < 8; i++) t += red[i][d];
        d_HG[(size_t)b*N1*Dm + Nn*Dm + d] += t * (1.f/Nn);
    }
}

// ------------------------- prologue: adjacency base + sq norms ---------------
__global__ void k_prol()
{
    int row = blockIdx.x;              // b*N1 + i
    int i   = row % N1;
    int b   = row / N1;
    int tid = threadIdx.x;
    if (tid < AW) {
        int w = tid;
        unsigned bits = 0u;
        #pragma unroll 4
        for (int t = 0; t < 32; t++) {
            int m = w*32 + t;
            if (m > Nn) break;
            bool on;
            if (i == Nn || m == Nn || i == m || i == 0 || m == 0) on = true;
            else {
                int di = i - m; if (di < 0) di = -di;
                on = ((i >> 7) == (m >> 7)) && (di <= 11);   // hier adjacency
            }
            if (on) bits |= 1u << t;
        }
        d_ADJ[row*AW + w] = bits;
    }
    if (tid >= 32 && i < Nn) {         // warp 1: squared norm
        int lane = tid - 32;
        const float* p = d_HG + (size_t)row*Dm;
        float s = 0.f;
        #pragma unroll
        for (int t = 0; t < 4; t++) { float v = p[lane + t*32]; s += v*v; }
        #pragma unroll
        for (int o = 16; o; o >>= 1) s += __shfl_xor_sync(0xffffffffu, s, o);
        if (!lane) d_SQ[b*Nn + i] = s;
    }
}

// ------------------------- D2 matrix (tiled) ---------------------------------
__global__ void k_d2()
{
    __shared__ float As[16][65];
    __shared__ float Bs[16][65];
    int b = blockIdx.z;
    const float* A = d_HG + (size_t)b*N1*Dm;
    int tid = threadIdx.x;
    int tr = tid >> 4, tc = tid & 15;
    int r0 = blockIdx.y*64, c0 = blockIdx.x*64;
    float acc[4][4] = {};
    for (int k0 = 0; k0 < Dm; k0 += 16) {
        #pragma unroll
        for (int i = 0; i < 4; i++) {
            int e = tid + i*256;
            int rr = e >> 4, cc = e & 15;
            As[cc][rr] = A[(size_t)(r0+rr)*Dm + k0 + cc];
            Bs[cc][rr] = A[(size_t)(c0+rr)*Dm + k0 + cc];
        }
        __syncthreads();
        #pragma unroll
        for (int k = 0; k < 16; k++) {
            float a[4], bv[4];
            #pragma unroll
            for (int i = 0; i < 4; i++) a[i]  = As[k][tr + i*16];
            #pragma unroll
            for (int j = 0; j < 4; j++) bv[j] = Bs[k][tc + j*16];
            #pragma unroll
            for (int i = 0; i < 4; i++)
                #pragma unroll
                for (int j = 0; j < 4; j++) acc[i][j] += a[i]*bv[j];
        }
        __syncthreads();
    }
    #pragma unroll
    for (int i = 0; i < 4; i++) {
        int r = r0 + tr + i*16;
        float sqr = d_SQ[b*Nn + r];
        #pragma unroll
        for (int j = 0; j < 4; j++) {
            int c = c0 + tc + j*16;
            float v = sqr + d_SQ[b*Nn + c] - 2.f*acc[i][j];
            if (r == c) v = CUDART_INF_F;
            d_D2[((size_t)b*Nn + r)*Nn + c] = v;
        }
    }
}

// ------------------------- exact top-10 kNN -> adjacency bits ----------------
__global__ void k_topk()
{
    int warp = (blockIdx.x*blockDim.x + threadIdx.x) >> 5;
    int lane = threadIdx.x & 31;
    if (warp >= Bsz*Nn) return;
    int b = warp >> 10, i = warp & 1023;
    const float* row = d_D2 + (size_t)warp*Nn;
    float vals[32];
    #pragma unroll
    for (int t = 0; t < 32; t++) vals[t] = row[t*32 + lane];
    unsigned used = 0u;
    unsigned* adjb = d_ADJ + (size_t)b*N1*AW;
    for (int r = 0; r < KNN; r++) {
        float bv = CUDART_INF_F; int bj = 1 << 30;
        #pragma unroll
        for (int t = 0; t < 32; t++) {
            if (!((used >> t) & 1u)) {
                float v = vals[t]; int j = t*32 + lane;
                if (v < bv || (v == bv && j < bj)) { bv = v; bj = j; }
            }
        }
        #pragma unroll
        for (int o = 16; o; o >>= 1) {
            float ov = __shfl_xor_sync(0xffffffffu, bv, o);
            int   oj = __shfl_xor_sync(0xffffffffu, bj, o);
            if (ov < bv || (ov == bv && oj < bj)) { bv = ov; bj = oj; }
        }
        if (lane == (bj & 31)) used |= 1u << (bj >> 5);
        if (lane == 0) {
            atomicOr(&adjb[i*AW + (bj >> 5)], 1u << (bj & 31));
            atomicOr(&adjb[bj*AW + (i >> 5)], 1u << (i & 31));
        }
    }
}

// ------------------------- generic SGEMM: C = A[M,K] * W[N,K]^T --------------
// flags: 1 = +bias[N], 2 = +res[M,N], 4 = relu
__global__ void k_gemm(const float* __restrict__ A, const float* __restrict__ Bm,
                       const float* __restrict__ bias, const float* __restrict__ res,
                       float* __restrict__ C, int M, int Nc, int K, int flags)
{
    __shared__ float As[16][65];
    __shared__ float Bs[16][65];
    int tid = threadIdx.x;
    int tr = tid >> 4, tc = tid & 15;
    int r0 = blockIdx.y*64, c0 = blockIdx.x*64;
    float acc[4][4] = {};
    for (int k0 = 0; k0 < K; k0 += 16) {
        #pragma unroll
        for (int i = 0; i < 4; i++) {
            int e = tid + i*256;
            int rr = e >> 4, cc = e & 15;
            int gr = r0 + rr;
            As[cc][rr] = (gr < M) ? A[(size_t)gr*K + k0 + cc] : 0.f;
            int gn = c0 + rr;
            Bs[cc][rr] = (gn < Nc) ? Bm[(size_t)gn*K + k0 + cc] : 0.f;
        }
        __syncthreads();
        #pragma unroll
        for (int k = 0; k < 16; k++) {
            float a[4], bv[4];
            #pragma unroll
            for (int i = 0; i < 4; i++) a[i]  = As[k][tr + i*16];
            #pragma unroll
            for (int j = 0; j < 4; j++) bv[j] = Bs[k][tc + j*16];
            #pragma unroll
            for (int i = 0; i < 4; i++)
                #pragma unroll
                for (int j = 0; j < 4; j++) acc[i][j] += a[i]*bv[j];
        }
        __syncthreads();
    }
    #pragma unroll
    for (int i = 0; i < 4; i++) {
        int r = r0 + tr + i*16;
        if (r >= M) continue;
        #pragma unroll
        for (int j = 0; j < 4; j++) {
            int c = c0 + tc + j*16;
            if (c >= Nc) continue;
            float v = acc[i][j];
            if (flags & 1) v += bias[c];
            if (flags & 2) v += res[(size_t)r*Nc + c];
            if (flags & 4) v = fmaxf(v, 0.f);
            C[(size_t)r*Nc + c] = v;
        }
    }
}

// ------------------------- fused QKV GEMM (one launch) -----------------------
__global__ void k_qkv(const float* __restrict__ A, const float* __restrict__ wq,
                      const float* __restrict__ wk, const float* __restrict__ wv)
{
    __shared__ float As[16][65];
    __shared__ float Bs[16][65];
    int sel = blockIdx.x >> 1;
    const float* Bm = (sel == 0) ? wq : (sel == 1) ? wk : wv;
    float* C = (sel == 0) ? d_Q : (sel == 1) ? d_Kb : d_Vb;
    const int M = Bsz*N1;
    int tid = threadIdx.x;
    int tr = tid >> 4, tc = tid & 15;
    int r0 = blockIdx.y*64, c0 = (blockIdx.x & 1)*64;
    float acc[4][4] = {};
    for (int k0 = 0; k0 < Dm; k0 += 16) {
        #pragma unroll
        for (int i = 0; i < 4; i++) {
            int e = tid + i*256;
            int rr = e >> 4, cc = e & 15;
            int gr = r0 + rr;
            As[cc][rr] = (gr < M) ? A[(size_t)gr*Dm + k0 + cc] : 0.f;
            Bs[cc][rr] = Bm[(size_t)(c0+rr)*Dm + k0 + cc];
        }
        __syncthreads();
        #pragma unroll
        for (int k = 0; k < 16; k++) {
            float a[4], bv[4];
            #pragma unroll
            for (int i = 0; i < 4; i++) a[i]  = As[k][tr + i*16];
            #pragma unroll
            for (int j = 0; j < 4; j++) bv[j] = Bs[k][tc + j*16];
            #pragma unroll
            for (int i = 0; i < 4; i++)
                #pragma unroll
                for (int j = 0; j < 4; j++) acc[i][j] += a[i]*bv[j];
        }
        __syncthreads();
    }
    #pragma unroll
    for (int i = 0; i < 4; i++) {
        int r = r0 + tr + i*16;
        if (r >= M) continue;
        #pragma unroll
        for (int j = 0; j < 4; j++) {
            int c = c0 + tc + j*16;
            C[(size_t)r*Dm + c] = acc[i][j];
        }
    }
}

// ------------------------- qe = Q . emb per (head,bucket) --------------------
__global__ void k_qe(const float* __restrict__ emb)
{
    __shared__ float qs[Dm];
    int row = blockIdx.x;              // b*N1 + n
    int tid = threadIdx.x;
    if (tid < Dm) qs[tid] = d_Q[(size_t)row*Dm + tid];
    __syncthreads();
    int h = tid >> 5, kb = tid & 31;
    const float* e = emb + kb*Dm + h*Dk;
    const float* q = qs + h*Dk;
    float s = 0.f;
    #pragma unroll
    for (int dd = 0; dd < Dk; dd++) s += q[dd]*e[dd];
    d_QE[(size_t)row*(Hh*NBk) + h*NBk + kb] = s;
}

// ------------------------- sparse attention: warp per query ------------------
// Lane-groups of 4 own one head each (Dk=16 -> 4 floats per lane).
__global__ void k_attn(const float* __restrict__ coords)
{
    __shared__ float qes[8][Hh*NBk];
    int wid  = threadIdx.x >> 5;
    int lane = threadIdx.x & 31;
    int row  = blockIdx.x*8 + wid;
    if (row >= Bsz*N1) return;
    int b = (row >= N1) ? 1 : 0;
    int n = row - b*N1;
    int hh = lane >> 2;
    const float4 qv = *(const float4*)(d_Q + (size_t)row*Dm + lane*4);
    const float* qep = d_QE + (size_t)row*(Hh*NBk);
    #pragma unroll
    for (int i = 0; i < 8; i++) qes[wid][lane + i*32] = qep[lane + i*32];
    __syncwarp();
    float cqx = 0.f, cqy = 0.f;
    if (n < Nn) { cqx = coords[(b*Nn+n)*2]; cqy = coords[(b*Nn+n)*2+1]; }
    float mrun = -CUDART_INF_F, lrun = 0.f;
    float4 acc = make_float4(0.f, 0.f, 0.f, 0.f);
    const unsigned* rowadj = d_ADJ + (size_t)row*AW;
    const float* Kbase = d_Kb + (size_t)b*N1*Dm;
    const float* Vbase = d_Vb + (size_t)b*N1*Dm;
    const float* qerow = qes[wid] + hh*NBk;
    for (int w = 0; w < AW; w++) {
        unsigned word = rowadj[w];
        while (word) {
            int m = w*32 + (__ffs((int)word) - 1);
            word &= word - 1u;
            const float4 kv = *(const float4*)(Kbase + (size_t)m*Dm + lane*4);
            float pr = qv.x*kv.x + qv.y*kv.y + qv.z*kv.z + qv.w*kv.w;
            pr += __shfl_xor_sync(0xffffffffu, pr, 1);
            pr += __shfl_xor_sync(0xffffffffu, pr, 2);
            float cmx = 0.f, cmy = 0.f;
            if (m < Nn) { cmx = coords[(b*Nn+m)*2]; cmy = coords[(b*Nn+m)*2+1]; }
            float dx = cqx - cmx, dy = cqy - cmy;
            float dist = sqrtf(dx*dx + dy*dy);
            int bk = (int)(dist * 32.f); if (bk > 31) bk = 31;
            float s = pr*SCALEf + qerow[bk];
            const float4 vv = *(const float4*)(Vbase + (size_t)m*Dm + lane*4);
            if (s > mrun) {
                float cr = __expf(mrun - s);     // first edge: exp(-inf)=0
                lrun = lrun*cr + 1.f;
                acc.x = acc.x*cr + vv.x; acc.y = acc.y*cr + vv.y;
                acc.z = acc.z*cr + vv.z; acc.w = acc.w*cr + vv.w;
                mrun = s;
            } else {
                float p = __expf(s - mrun);
                lrun += p;
                acc.x += p*vv.x; acc.y += p*vv.y;
                acc.z += p*vv.z; acc.w += p*vv.w;
            }
        }
    }
    float inv = 1.f / lrun;
    float4 o = make_float4(acc.x*inv, acc.y*inv, acc.z*inv, acc.w*inv);
    *(float4*)(d_CTX + (size_t)row*Dm + lane*4) = o;
}

// ------------------------- instance norm over sequence axis ------------------
// grid (Bsz, 4): each block owns a 32-wide d slice. fuse=1 additionally does
// POOL += mean(out_h) and out[g-row] += mean(out_h)  (next layer's g update).
__global__ void k_inorm(const float* __restrict__ src, float* __restrict__ dst,
                        const float* __restrict__ w, const float* __restrict__ bb, int fuse)
{
    __shared__ float red[32][33];
    __shared__ float s_mu[32], s_sc[32], s_mh[32];
    int b  = blockIdx.x;
    int dl = threadIdx.x & 31;
    int g  = threadIdx.x >> 5;
    int d  = blockIdx.y*32 + dl;
    const float* p = src + (size_t)b*N1*Dm + d;
    float s = 0.f;
    for (int n = g; n < N1; n += 32) s += p[(size_t)n*Dm];
    red[g][dl] = s;
    __syncthreads();
    if (g == 0) {
        float t = 0.f;
        #pragma unroll
        for (int i = 0; i < 32; i++) t += red[i][dl];
        s_mu[dl] = t * (1.f/N1);
        if (fuse) s_mh[dl] = (t - p[(size_t)Nn*Dm]) * (1.f/Nn);  // mean_{n<N} of src
    }
    __syncthreads();
    float mu = s_mu[dl];
    float v = 0.f;
    for (int n = g; n < N1; n += 32) { float x = p[(size_t)n*Dm] - mu; v += x*x; }
    __syncthreads();
    red[g][dl] = v;
    __syncthreads();
    if (g == 0) {
        float t = 0.f;
        #pragma unroll
        for (int i = 0; i < 32; i++) t += red[i][dl];
        s_sc[dl] = rsqrtf(t*(1.f/N1) + EPSf) * w[d];
    }
    __syncthreads();
    float sc = s_sc[dl], sh = bb[d];
    float mo = 0.f;
    if (fuse) mo = (s_mh[dl] - mu)*sc + sh;      // mean over n<N of normalized out
    float* o = dst + (size_t)b*N1*Dm + d;
    for (int n = g; n < N1; n += 32) {
        float val = (p[(size_t)n*Dm] - mu)*sc + sh;
        if (fuse && n == Nn) val += mo;          // g += mean(h) for next layer
        o[(size_t)n*Dm] = val;
    }
    if (fuse && g == 0) d_POOL[b*Dm + d] += mo;  // pools.append(mean(h))
}

// ------------------------- final prep: X = h + p_multi; write p_multi --------
__global__ void k_final(float* __restrict__ out)
{
    int gid = blockIdx.x*blockDim.x + threadIdx.x;
    if (gid < Bsz*Dm) out[Bsz*Nn*Dm + gid] = d_POOL[gid] * (1.f/3.f);
    if (gid >= Bsz*Nn*Dm) return;
    int d = gid & 127;
    int n = (gid >> 7) & 1023;
    int b = gid >> 17;
    d_X[gid] = d_HG[((size_t)b*N1 + n)*Dm + d] + d_POOL[b*Dm + d]*(1.f/3.f);
}

// ------------------------- host driver ---------------------------------------
extern "C" void kernel_launch(void* const* d_in, const int* in_sizes, int n_in,
                              void* d_out, int out_size)
{
    const float* coords = (const float*)d_in[0];
    const float* in_W   = (const float*)d_in[1];
    const float* in_b   = (const float*)d_in[2];
    const float* gnode  = (const float*)d_in[3];
    const float* Wq     = (const float*)d_in[4];
    const float* Wk     = (const float*)d_in[5];
    const float* Wv     = (const float*)d_in[6];
    const float* Wo     = (const float*)d_in[7];
    const float* emb    = (const float*)d_in[8];
    const float* W1     = (const float*)d_in[9];
    const float* b1     = (const float*)d_in[10];
    const float* W2     = (const float*)d_in[11];
    const float* b2     = (const float*)d_in[12];
    const float* n1w    = (const float*)d_in[13];
    const float* n1b    = (const float*)d_in[14];
    const float* n2w    = (const float*)d_in[15];
    const float* n2b    = (const float*)d_in[16];
    const float* outW   = (const float*)d_in[17];
    const float* outb   = (const float*)d_in[18];
    float* out = (float*)d_out;

    float *HG, *CTX, *Y, *T1, *T2, *X;
    cudaGetSymbolAddress((void**)&HG,  d_HG);
    cudaGetSymbolAddress((void**)&CTX, d_CTX);
    cudaGetSymbolAddress((void**)&Y,   d_Y);
    cudaGetSymbolAddress((void**)&T1,  d_T1);
    cudaGetSymbolAddress((void**)&T2,  d_T2);
    cudaGetSymbolAddress((void**)&X,   d_X);

    const int Mall = Bsz*N1;  // 2050

    k_input<<<(Bsz*N1*Dm + 255)/256, 256>>>(coords, in_W, in_b, gnode);
    k_colmean<<<Bsz, 1024>>>();                            // layer-0 g update

    for (int l = 0; l < 3; l++) {
        k_prol<<<Bsz*N1, 64>>>();
        { dim3 g(Nn/64, Nn/64, Bsz); k_d2<<<g, 256>>>(); }
        k_topk<<<(Bsz*Nn)/8, 256>>>();

        { dim3 gqkv(6, (Mall + 63)/64);
          k_qkv<<<gqkv, 256>>>(HG, Wq + (size_t)l*Dm*Dm, Wk + (size_t)l*Dm*Dm, Wv + (size_t)l*Dm*Dm); }
        k_qe<<<Mall, 256>>>(emb + (size_t)l*NBk*Dm);
        k_attn<<<(Mall + 7)/8, 256>>>(coords);

        dim3 gq(Dm/64, (Mall + 63)/64);
        k_gemm<<<gq, 256>>>(CTX, Wo + (size_t)l*Dm*Dm, nullptr, HG, Y, Mall, Dm, Dm, 2);
        { dim3 gi(Bsz, 4); k_inorm<<<gi, 1024>>>(Y, Y, n1w + l*Dm, n1b + l*Dm, 0); }

        dim3 g1(Dff/64, (Mall + 63)/64);
        k_gemm<<<g1, 256>>>(Y,  W1 + (size_t)l*Dff*Dm, b1 + l*Dff, nullptr, T1, Mall, Dff, Dm, 1|4);
        k_gemm<<<gq, 256>>>(T1, W2 + (size_t)l*Dm*Dff, b2 + l*Dm,  Y,      T2, Mall, Dm, Dff, 1|2);
        { dim3 gi(Bsz, 4); k_inorm<<<gi, 1024>>>(T2, HG, n2w + l*Dm, n2b + l*Dm, 1); }
    }

    k_final<<<(Bsz*Nn*Dm + 255)/256, 256>>>(out);
    { dim3 ge(Dm/64, (Bsz*Nn + 63)/64);
      k_gemm<<<ge, 256>>>(X, outW, outb, nullptr, out, Bsz*Nn, Dm, Dm, 1); }
}

// round 3
// speedup vs baseline: 1.7686x; 1.7686x over previous
#include <cuda_runtime.h>
#include <math_constants.h>
#include <math.h>

#define Bsz 2
#define Nn 1024
#define N1 1025
#define Dm 128
#define Hh 8
#define Dk 16
#define Dff 512
#define NBk 32
#define KNN 10
#define AW 33          // 33 x 32-bit words cover 1025 mask bits per row
#define EPSf 1e-5f
#define SCALEf 0.25f   // 1/sqrt(16)

// ------------------------- persistent device scratch -------------------------
__device__ float    d_HG [Bsz*N1*Dm];     // state: rows 0..1023 = h, row 1024 = g
__device__ float    d_POOL[Bsz*Dm];
__device__ float    d_SQ [Bsz*Nn];
__device__ float    d_D2 [(size_t)Bsz*Nn*Nn];
__device__ unsigned d_ADJ[Bsz*N1*AW];
__device__ float    d_Q  [Bsz*N1*Dm];
__device__ float    d_Kb [Bsz*N1*Dm];
__device__ float    d_Vb [Bsz*N1*Dm];
__device__ float    d_CTX[Bsz*N1*Dm];
__device__ float    d_QE [Bsz*N1*Hh*NBk];
__device__ float    d_Y  [Bsz*N1*Dm];
__device__ float    d_T1 [Bsz*N1*Dff];
__device__ float    d_T2 [Bsz*N1*Dm];
__device__ float    d_X  [Bsz*Nn*Dm];

// ------------------------- input embedding + state init ----------------------
__global__ void k_input(const float* __restrict__ coords, const float* __restrict__ inW,
                        const float* __restrict__ inb, const float* __restrict__ gnode)
{
    int gid = blockIdx.x*blockDim.x + threadIdx.x;
    if (gid < Bsz*Dm) d_POOL[gid] = 0.f;
    if (gid >= Bsz*N1*Dm) return;
    int d = gid % Dm;
    int n = (gid / Dm) % N1;
    int b = gid / (Dm*N1);
    float v;
    if (n < Nn) {
        float x = coords[(b*Nn+n)*2+0];
        float y = coords[(b*Nn+n)*2+1];
        v = x*inW[d*2+0] + y*inW[d*2+1] + inb[d];
    } else {
        v = gnode[d];
    }
    d_HG[gid] = v;
}

// ------------------------- layer-0 g update: g += mean(h) --------------------
__global__ void k_colmean()
{
    __shared__ float red[8][Dm];
    int b = blockIdx.x;
    int d = threadIdx.x & 127;
    int g = threadIdx.x >> 7;
    const float* base = d_HG + (size_t)b*N1*Dm;
    float s = 0.f;
    for (int n = g; n < Nn; n += 8) s += base[n*Dm + d];
    red[g][d] = s;
    __syncthreads();
    if (g == 0) {
        float t = 0.f;
        #pragma unroll
        for (int i = 0; i < 8; i++) t += red[i][d];
        d_HG[(size_t)b*N1*Dm + Nn*Dm + d] += t * (1.f/Nn);
    }
}

// ------------------------- prologue: adjacency base + sq norms ---------------
__global__ void k_prol()
{
    int row = blockIdx.x;              // b*N1 + i
    int i   = row % N1;
    int b   = row / N1;
    int tid = threadIdx.x;
    if (tid < AW) {
        int w = tid;
        unsigned bits = 0u;
        #pragma unroll 4
        for (int t = 0; t < 32; t++) {
            int m = w*32 + t;
            if (m > Nn) break;
            bool on;
            if (i == Nn || m == Nn || i == m || i == 0 || m == 0) on = true;
            else {
                int di = i - m; if (di < 0) di = -di;
                on = ((i >> 7) == (m >> 7)) && (di <= 11);   // hier adjacency
            }
            if (on) bits |= 1u << t;
        }
        d_ADJ[row*AW + w] = bits;
    }
    if (tid >= 32 && i < Nn) {         // warp 1: squared norm
        int lane = tid - 32;
        const float* p = d_HG + (size_t)row*Dm;
        float s = 0.f;
        #pragma unroll
        for (int t = 0; t < 4; t++) { float v = p[lane + t*32]; s += v*v; }
        #pragma unroll
        for (int o = 16; o; o >>= 1) s += __shfl_xor_sync(0xffffffffu, s, o);
        if (!lane) d_SQ[b*Nn + i] = s;
    }
}

// ------------------------- D2 matrix (tiled, float4) -------------------------
__global__ void k_d2()
{
    __shared__ float As[16][68];
    __shared__ float Bs[16][68];
    int b = blockIdx.z;
    const float* A = d_HG + (size_t)b*N1*Dm;
    int tid = threadIdx.x;
    int tr = tid >> 4, tc = tid & 15;
    int r0 = blockIdx.y*64, c0 = blockIdx.x*64;
    int lr = tid >> 2;           // 0..63
    int lc = (tid & 3) * 4;      // 0,4,8,12
    float acc[4][4] = {};
    for (int k0 = 0; k0 < Dm; k0 += 16) {
        float4 va = *(const float4*)(A + (size_t)(r0+lr)*Dm + k0 + lc);
        float4 vb = *(const float4*)(A + (size_t)(c0+lr)*Dm + k0 + lc);
        As[lc+0][lr] = va.x; As[lc+1][lr] = va.y; As[lc+2][lr] = va.z; As[lc+3][lr] = va.w;
        Bs[lc+0][lr] = vb.x; Bs[lc+1][lr] = vb.y; Bs[lc+2][lr] = vb.z; Bs[lc+3][lr] = vb.w;
        __syncthreads();
        #pragma unroll
        for (int k = 0; k < 16; k++) {
            float4 a4 = *(const float4*)&As[k][tr*4];
            float4 b4 = *(const float4*)&Bs[k][tc*4];
            float a[4] = {a4.x, a4.y, a4.z, a4.w};
            float bv[4] = {b4.x, b4.y, b4.z, b4.w};
            #pragma unroll
            for (int i = 0; i < 4; i++)
                #pragma unroll
                for (int j = 0; j < 4; j++) acc[i][j] += a[i]*bv[j];
        }
        __syncthreads();
    }
    #pragma unroll
    for (int i = 0; i < 4; i++) {
        int r = r0 + tr*4 + i;
        float sqr = d_SQ[b*Nn + r];
        #pragma unroll
        for (int j = 0; j < 4; j++) {
            int c = c0 + tc*4 + j;
            float v = sqr + d_SQ[b*Nn + c] - 2.f*acc[i][j];
            if (r == c) v = CUDART_INF_F;
            d_D2[((size_t)b*Nn + r)*Nn + c] = v;
        }
    }
}

// ------------------------- exact top-10 kNN -> adjacency bits ----------------
__global__ void k_topk()
{
    int warp = (blockIdx.x*blockDim.x + threadIdx.x) >> 5;
    int lane = threadIdx.x & 31;
    if (warp >= Bsz*Nn) return;
    int b = warp >> 10, i = warp & 1023;
    const float* row = d_D2 + (size_t)warp*Nn;
    float vals[32];
    #pragma unroll
    for (int t = 0; t < 32; t++) vals[t] = row[t*32 + lane];
    unsigned used = 0u;
    unsigned* adjb = d_ADJ + (size_t)b*N1*AW;
    for (int r = 0; r < KNN; r++) {
        float bv = CUDART_INF_F; int bj = 1 << 30;
        #pragma unroll
        for (int t = 0; t < 32; t++) {
            if (!((used >> t) & 1u)) {
                float v = vals[t]; int j = t*32 + lane;
                if (v < bv || (v == bv && j < bj)) { bv = v; bj = j; }
            }
        }
        #pragma unroll
        for (int o = 16; o; o >>= 1) {
            float ov = __shfl_xor_sync(0xffffffffu, bv, o);
            int   oj = __shfl_xor_sync(0xffffffffu, bj, o);
            if (ov < bv || (ov == bv && oj < bj)) { bv = ov; bj = oj; }
        }
        if (lane == (bj & 31)) used |= 1u << (bj >> 5);
        if (lane == 0) {
            atomicOr(&adjb[i*AW + (bj >> 5)], 1u << (bj & 31));
            atomicOr(&adjb[bj*AW + (i >> 5)], 1u << (i & 31));
        }
    }
}

// ------------------------- generic SGEMM: C = A[M,K] * W[N,K]^T --------------
// flags: 1 = +bias[N], 2 = +res[M,N], 4 = relu.  Nc must be a multiple of 64.
__global__ void k_gemm(const float* __restrict__ A, const float* __restrict__ Bm,
                       const float* __restrict__ bias, const float* __restrict__ res,
                       float* __restrict__ C, int M, int Nc, int K, int flags)
{
    __shared__ float As[16][68];
    __shared__ float Bs[16][68];
    int tid = threadIdx.x;
    int tr = tid >> 4, tc = tid & 15;
    int r0 = blockIdx.y*64, c0 = blockIdx.x*64;
    int lr = tid >> 2;
    int lc = (tid & 3) * 4;
    float acc[4][4] = {};
    for (int k0 = 0; k0 < K; k0 += 16) {
        int gr = r0 + lr;
        float4 va = (gr < M) ? *(const float4*)(A + (size_t)gr*K + k0 + lc)
                             : make_float4(0.f,0.f,0.f,0.f);
        float4 vb = *(const float4*)(Bm + (size_t)(c0+lr)*K + k0 + lc);
        As[lc+0][lr] = va.x; As[lc+1][lr] = va.y; As[lc+2][lr] = va.z; As[lc+3][lr] = va.w;
        Bs[lc+0][lr] = vb.x; Bs[lc+1][lr] = vb.y; Bs[lc+2][lr] = vb.z; Bs[lc+3][lr] = vb.w;
        __syncthreads();
        #pragma unroll
        for (int k = 0; k < 16; k++) {
            float4 a4 = *(const float4*)&As[k][tr*4];
            float4 b4 = *(const float4*)&Bs[k][tc*4];
            float a[4] = {a4.x, a4.y, a4.z, a4.w};
            float bv[4] = {b4.x, b4.y, b4.z, b4.w};
            #pragma unroll
            for (int i = 0; i < 4; i++)
                #pragma unroll
                for (int j = 0; j < 4; j++) acc[i][j] += a[i]*bv[j];
        }
        __syncthreads();
    }
    int c = c0 + tc*4;
    float4 bz = make_float4(0.f,0.f,0.f,0.f);
    if (flags & 1) bz = *(const float4*)(bias + c);
    #pragma unroll
    for (int i = 0; i < 4; i++) {
        int r = r0 + tr*4 + i;
        if (r >= M) continue;
        float4 v = make_float4(acc[i][0]+bz.x, acc[i][1]+bz.y, acc[i][2]+bz.z, acc[i][3]+bz.w);
        if (flags & 2) {
            float4 rv = *(const float4*)(res + (size_t)r*Nc + c);
            v.x += rv.x; v.y += rv.y; v.z += rv.z; v.w += rv.w;
        }
        if (flags & 4) {
            v.x = fmaxf(v.x, 0.f); v.y = fmaxf(v.y, 0.f);
            v.z = fmaxf(v.z, 0.f); v.w = fmaxf(v.w, 0.f);
        }
        *(float4*)(C + (size_t)r*Nc + c) = v;
    }
}

// ------------------------- fused QKV GEMM (one launch) -----------------------
__global__ void k_qkv(const float* __restrict__ A, const float* __restrict__ wq,
                      const float* __restrict__ wk, const float* __restrict__ wv)
{
    __shared__ float As[16][68];
    __shared__ float Bs[16][68];
    int sel = blockIdx.x >> 1;
    const float* Bm = (sel == 0) ? wq : (sel == 1) ? wk : wv;
    float* C = (sel == 0) ? d_Q : (sel == 1) ? d_Kb : d_Vb;
    const int M = Bsz*N1;
    int tid = threadIdx.x;
    int tr = tid >> 4, tc = tid & 15;
    int r0 = blockIdx.y*64, c0 = (blockIdx.x & 1)*64;
    int lr = tid >> 2;
    int lc = (tid & 3) * 4;
    float acc[4][4] = {};
    for (int k0 = 0; k0 < Dm; k0 += 16) {
        int gr = r0 + lr;
        float4 va = (gr < M) ? *(const float4*)(A + (size_t)gr*Dm + k0 + lc)
                             : make_float4(0.f,0.f,0.f,0.f);
        float4 vb = *(const float4*)(Bm + (size_t)(c0+lr)*Dm + k0 + lc);
        As[lc+0][lr] = va.x; As[lc+1][lr] = va.y; As[lc+2][lr] = va.z; As[lc+3][lr] = va.w;
        Bs[lc+0][lr] = vb.x; Bs[lc+1][lr] = vb.y; Bs[lc+2][lr] = vb.z; Bs[lc+3][lr] = vb.w;
        __syncthreads();
        #pragma unroll
        for (int k = 0; k < 16; k++) {
            float4 a4 = *(const float4*)&As[k][tr*4];
            float4 b4 = *(const float4*)&Bs[k][tc*4];
            float a[4] = {a4.x, a4.y, a4.z, a4.w};
            float bv[4] = {b4.x, b4.y, b4.z, b4.w};
            #pragma unroll
            for (int i = 0; i < 4; i++)
                #pragma unroll
                for (int j = 0; j < 4; j++) acc[i][j] += a[i]*bv[j];
        }
        __syncthreads();
    }
    int c = c0 + tc*4;
    #pragma unroll
    for (int i = 0; i < 4; i++) {
        int r = r0 + tr*4 + i;
        if (r >= M) continue;
        *(float4*)(C + (size_t)r*Dm + c) =
            make_float4(acc[i][0], acc[i][1], acc[i][2], acc[i][3]);
    }
}

// ------------------------- qe = Q . emb per (head,bucket) --------------------
__global__ void k_qe(const float* __restrict__ emb)
{
    __shared__ float qs[Dm];
    int row = blockIdx.x;              // b*N1 + n
    int tid = threadIdx.x;
    if (tid < Dm) qs[tid] = d_Q[(size_t)row*Dm + tid];
    __syncthreads();
    int h = tid >> 5, kb = tid & 31;
    const float* e = emb + kb*Dm + h*Dk;
    const float* q = qs + h*Dk;
    float s = 0.f;
    #pragma unroll
    for (int dd = 0; dd < Dk; dd++) s += q[dd]*e[dd];
    d_QE[(size_t)row*(Hh*NBk) + h*NBk + kb] = s;
}

// ------------------------- sparse masked attention (block-tile, R1) ----------
__device__ __forceinline__ void attn_word(unsigned word, int base,
    const float q[16], float cqx, float cqy,
    const float (*Ks)[17], const float (*Vs)[17],
    const float* ckx, const float* cky, const float* qerow,
    float& mrun, float& lrun, float acc[16])
{
    while (word) {
        int mm = base + (__ffs((int)word) - 1);
        word &= word - 1u;
        float s = 0.f;
        #pragma unroll
        for (int d = 0; d < 16; d++) s += q[d]*Ks[mm][d];
        float dx = cqx - ckx[mm], dy = cqy - cky[mm];
        float dist = sqrtf(dx*dx + dy*dy);
        int bk = (int)(dist * 32.f); if (bk > 31) bk = 31;
        s = s*SCALEf + qerow[bk];
        if (s > mrun) {
            float cr = __expf(mrun - s);        // first hit: exp(-inf)=0
            lrun = lrun*cr + 1.f;
            #pragma unroll
            for (int d = 0; d < 16; d++) acc[d] = acc[d]*cr + Vs[mm][d];
            mrun = s;
        } else {
            float p = __expf(s - mrun);
            lrun += p;
            #pragma unroll
            for (int d = 0; d < 16; d++) acc[d] += p*Vs[mm][d];
        }
    }
}

__global__ void k_attn(const float* __restrict__ coords)
{
    __shared__ float Ks[128][17];
    __shared__ float Vs[128][17];
    __shared__ float ckx[128], cky[128];
    __shared__ float qes[128][33];
    int b = blockIdx.z, h = blockIdx.y;
    int q0 = blockIdx.x * 128;
    int tid = threadIdx.x;
    int n = q0 + tid;
    bool qv = (n < N1);
    float q[16], acc[16];
    float cqx = 0.f, cqy = 0.f, mrun = -CUDART_INF_F, lrun = 0.f;
    #pragma unroll
    for (int d = 0; d < 16; d++) { q[d] = 0.f; acc[d] = 0.f; }
    const unsigned* rowadj = d_ADJ;
    if (qv) {
        const float* qp = d_Q + ((size_t)(b*N1 + n))*Dm + h*Dk;
        #pragma unroll
        for (int d = 0; d < 16; d++) q[d] = qp[d];
        if (n < Nn) { cqx = coords[(b*Nn+n)*2]; cqy = coords[(b*Nn+n)*2+1]; }
        const float* qep = d_QE + ((size_t)(b*N1 + n))*(Hh*NBk) + h*NBk;
        #pragma unroll
        for (int kb = 0; kb < 32; kb++) qes[tid][kb] = qep[kb];
        rowadj = d_ADJ + (size_t)(b*N1 + n)*AW;
    }
    for (int kt = 0; kt < 9; kt++) {
        int m0 = kt*128;
        int tlen = N1 - m0; if (tlen > 128) tlen = 128;
        __syncthreads();
        if (tid < tlen) {
            int m = m0 + tid;
            const float* kp = d_Kb + ((size_t)(b*N1 + m))*Dm + h*Dk;
            const float* vp = d_Vb + ((size_t)(b*N1 + m))*Dm + h*Dk;
            #pragma unroll
            for (int d = 0; d < 16; d++) { Ks[tid][d] = kp[d]; Vs[tid][d] = vp[d]; }
            if (m < Nn) { ckx[tid] = coords[(b*Nn+m)*2]; cky[tid] = coords[(b*Nn+m)*2+1]; }
            else        { ckx[tid] = 0.f; cky[tid] = 0.f; }
        }
        __syncthreads();
        if (!qv) continue;
        int wb = m0 >> 5;
        unsigned w0 = rowadj[wb];
        unsigned w1 = (wb+1 < AW) ? rowadj[wb+1] : 0u;
        unsigned w2 = (wb+2 < AW) ? rowadj[wb+2] : 0u;
        unsigned w3 = (wb+3 < AW) ? rowadj[wb+3] : 0u;
        attn_word(w0,  0, q, cqx, cqy, Ks, Vs, ckx, cky, qes[tid], mrun, lrun, acc);
        attn_word(w1, 32, q, cqx, cqy, Ks, Vs, ckx, cky, qes[tid], mrun, lrun, acc);
        attn_word(w2, 64, q, cqx, cqy, Ks, Vs, ckx, cky, qes[tid], mrun, lrun, acc);
        attn_word(w3, 96, q, cqx, cqy, Ks, Vs, ckx, cky, qes[tid], mrun, lrun, acc);
    }
    if (qv) {
        float inv = 1.f / lrun;
        float* o = d_CTX + ((size_t)(b*N1 + n))*Dm + h*Dk;
        #pragma unroll
        for (int d = 0; d < 16; d++) o[d] = acc[d]*inv;
    }
}

// ------------------------- instance norm over sequence axis ------------------
// grid (Bsz, 4): each block owns a 32-wide d slice. fuse=1 additionally does
// POOL += mean(out_h) and out[g-row] += mean(out_h)  (next layer's g update).
__global__ void k_inorm(const float* __restrict__ src, float* __restrict__ dst,
                        const float* __restrict__ w, const float* __restrict__ bb, int fuse)
{
    __shared__ float red[32][33];
    __shared__ float s_mu[32], s_sc[32], s_mh[32];
    int b  = blockIdx.x;
    int dl = threadIdx.x & 31;
    int g  = threadIdx.x >> 5;
    int d  = blockIdx.y*32 + dl;
    const float* p = src + (size_t)b*N1*Dm + d;
    float s = 0.f;
    for (int n = g; n < N1; n += 32) s += p[(size_t)n*Dm];
    red[g][dl] = s;
    __syncthreads();
    if (g == 0) {
        float t = 0.f;
        #pragma unroll
        for (int i = 0; i < 32; i++) t += red[i][dl];
        s_mu[dl] = t * (1.f/N1);
        if (fuse) s_mh[dl] = (t - p[(size_t)Nn*Dm]) * (1.f/Nn);  // mean_{n<N} of src
    }
    __syncthreads();
    float mu = s_mu[dl];
    float v = 0.f;
    for (int n = g; n < N1; n += 32) { float x = p[(size_t)n*Dm] - mu; v += x*x; }
    __syncthreads();
    red[g][dl] = v;
    __syncthreads();
    if (g == 0) {
        float t = 0.f;
        #pragma unroll
        for (int i = 0; i < 32; i++) t += red[i][dl];
        s_sc[dl] = rsqrtf(t*(1.f/N1) + EPSf) * w[d];
    }
    __syncthreads();
    float sc = s_sc[dl], sh = bb[d];
    float mo = 0.f;
    if (fuse) mo = (s_mh[dl] - mu)*sc + sh;      // mean over n<N of normalized out
    float* o = dst + (size_t)b*N1*Dm + d;
    for (int n = g; n < N1; n += 32) {
        float val = (p[(size_t)n*Dm] - mu)*sc + sh;
        if (fuse && n == Nn) val += mo;          // g += mean(h) for next layer
        o[(size_t)n*Dm] = val;
    }
    if (fuse && g == 0) d_POOL[b*Dm + d] += mo;  // pools.append(mean(h))
}

// ------------------------- final prep: X = h + p_multi; write p_multi --------
__global__ void k_final(float* __restrict__ out)
{
    int gid = blockIdx.x*blockDim.x + threadIdx.x;
    if (gid < Bsz*Dm) out[Bsz*Nn*Dm + gid] = d_POOL[gid] * (1.f/3.f);
    if (gid >= Bsz*Nn*Dm) return;
    int d = gid & 127;
    int n = (gid >> 7) & 1023;
    int b = gid >> 17;
    d_X[gid] = d_HG[((size_t)b*N1 + n)*Dm + d] + d_POOL[b*Dm + d]*(1.f/3.f);
}

// ------------------------- host driver ---------------------------------------
extern "C" void kernel_launch(void* const* d_in, const int* in_sizes, int n_in,
                              void* d_out, int out_size)
{
    const float* coords = (const float*)d_in[0];
    const float* in_W   = (const float*)d_in[1];
    const float* in_b   = (const float*)d_in[2];
    const float* gnode  = (const float*)d_in[3];
    const float* Wq     = (const float*)d_in[4];
    const float* Wk     = (const float*)d_in[5];
    const float* Wv     = (const float*)d_in[6];
    const float* Wo     = (const float*)d_in[7];
    const float* emb    = (const float*)d_in[8];
    const float* W1     = (const float*)d_in[9];
    const float* b1     = (const float*)d_in[10];
    const float* W2     = (const float*)d_in[11];
    const float* b2     = (const float*)d_in[12];
    const float* n1w    = (const float*)d_in[13];
    const float* n1b    = (const float*)d_in[14];
    const float* n2w    = (const float*)d_in[15];
    const float* n2b    = (const float*)d_in[16];
    const float* outW   = (const float*)d_in[17];
    const float* outb   = (const float*)d_in[18];
    float* out = (float*)d_out;

    float *HG, *CTX, *Y, *T1, *T2, *X;
    cudaGetSymbolAddress((void**)&HG,  d_HG);
    cudaGetSymbolAddress((void**)&CTX, d_CTX);
    cudaGetSymbolAddress((void**)&Y,   d_Y);
    cudaGetSymbolAddress((void**)&T1,  d_T1);
    cudaGetSymbolAddress((void**)&T2,  d_T2);
    cudaGetSymbolAddress((void**)&X,   d_X);

    const int Mall = Bsz*N1;  // 2050

    k_input<<<(Bsz*N1*Dm + 255)/256, 256>>>(coords, in_W, in_b, gnode);
    k_colmean<<<Bsz, 1024>>>();                            // layer-0 g update

    for (int l = 0; l < 3; l++) {
        k_prol<<<Bsz*N1, 64>>>();
        { dim3 g(Nn/64, Nn/64, Bsz); k_d2<<<g, 256>>>(); }
        k_topk<<<(Bsz*Nn)/8, 256>>>();

        { dim3 gqkv(6, (Mall + 63)/64);
          k_qkv<<<gqkv, 256>>>(HG, Wq + (size_t)l*Dm*Dm, Wk + (size_t)l*Dm*Dm, Wv + (size_t)l*Dm*Dm); }
        k_qe<<<Mall, 256>>>(emb + (size_t)l*NBk*Dm);
        { dim3 ga(9, Hh, Bsz); k_attn<<<ga, 128>>>(coords); }

        dim3 gq(Dm/64, (Mall + 63)/64);
        k_gemm<<<gq, 256>>>(CTX, Wo + (size_t)l*Dm*Dm, nullptr, HG, Y, Mall, Dm, Dm, 2);
        { dim3 gi(Bsz, 4); k_inorm<<<gi, 1024>>>(Y, Y, n1w + l*Dm, n1b + l*Dm, 0); }

        dim3 g1(Dff/64, (Mall + 63)/64);
        k_gemm<<<g1, 256>>>(Y,  W1 + (size_t)l*Dff*Dm, b1 + l*Dff, nullptr, T1, Mall, Dff, Dm, 1|4);
        k_gemm<<<gq, 256>>>(T1, W2 + (size_t)l*Dm*Dff, b2 + l*Dm,  Y,      T2, Mall, Dm, Dff, 1|2);
        { dim3 gi(Bsz, 4); k_inorm<<<gi, 1024>>>(T2, HG, n2w + l*Dm, n2b + l*Dm, 1); }
    }

    k_final<<<(Bsz*Nn*Dm + 255)/256, 256>>>(out);
    { dim3 ge(Dm/64, (Bsz*Nn + 63)/64);
      k_gemm<<<ge, 256>>>(X, outW, outb, nullptr, out, Bsz*Nn, Dm, Dm, 1); }
}

// round 4
// speedup vs baseline: 3.2989x; 1.8653x over previous
#include <cuda_runtime.h>
#include <math_constants.h>
#include <math.h>

#define Bsz 2
#define Nn 1024
#define N1 1025
#define Dm 128
#define Hh 8
#define Dk 16
#define Dff 512
#define NBk 32
#define KNN 10
#define AW 33          // 33 x 32-bit words cover 1025 mask bits per row
#define EPSf 1e-5f
#define SCALEf 0.25f   // 1/sqrt(16)

// ------------------------- persistent device scratch -------------------------
__device__ float    d_HG [Bsz*N1*Dm];     // state: rows 0..1023 = h, row 1024 = g
__device__ float    d_POOL[Bsz*Dm];
__device__ float    d_SQ [Bsz*Nn];
__device__ float    d_D2 [(size_t)Bsz*Nn*Nn];
__device__ unsigned d_ADJ[Bsz*N1*AW];
__device__ float    d_Q  [Bsz*Hh*N1*Dk];  // head-major: [b][h][n][dk]
__device__ float    d_Kb [Bsz*Hh*N1*Dk];
__device__ float    d_Vb [Bsz*Hh*N1*Dk];
__device__ float    d_CTX[Bsz*N1*Dm];
__device__ float    d_QE [Bsz*Hh*N1*NBk]; // head-major: [b][h][n][bucket]
__device__ float    d_Y  [Bsz*N1*Dm];
__device__ float    d_T1 [Bsz*N1*Dff];
__device__ float    d_T2 [Bsz*N1*Dm];
__device__ float    d_X  [Bsz*Nn*Dm];

// ------------------------- input embedding + state init ----------------------
__global__ void k_input(const float* __restrict__ coords, const float* __restrict__ inW,
                        const float* __restrict__ inb, const float* __restrict__ gnode)
{
    int gid = blockIdx.x*blockDim.x + threadIdx.x;
    if (gid < Bsz*Dm) d_POOL[gid] = 0.f;
    if (gid >= Bsz*N1*Dm) return;
    int d = gid % Dm;
    int n = (gid / Dm) % N1;
    int b = gid / (Dm*N1);
    float v;
    if (n < Nn) {
        float x = coords[(b*Nn+n)*2+0];
        float y = coords[(b*Nn+n)*2+1];
        v = x*inW[d*2+0] + y*inW[d*2+1] + inb[d];
    } else {
        v = gnode[d];
    }
    d_HG[gid] = v;
}

// ------------------------- layer-0 g update: g += mean(h) --------------------
__global__ void k_colmean()
{
    __shared__ float red[8][Dm];
    int b = blockIdx.x;
    int d = threadIdx.x & 127;
    int g = threadIdx.x >> 7;
    const float* base = d_HG + (size_t)b*N1*Dm;
    float s = 0.f;
    for (int n = g; n < Nn; n += 8) s += base[n*Dm + d];
    red[g][d] = s;
    __syncthreads();
    if (g == 0) {
        float t = 0.f;
        #pragma unroll
        for (int i = 0; i < 8; i++) t += red[i][d];
        d_HG[(size_t)b*N1*Dm + Nn*Dm + d] += t * (1.f/Nn);
    }
}

// ------------------------- prologue: adjacency base + sq norms ---------------
__global__ void k_prol()
{
    int row = blockIdx.x;              // b*N1 + i
    int i   = row % N1;
    int b   = row / N1;
    int tid = threadIdx.x;
    if (tid < AW) {
        int w = tid;
        unsigned bits = 0u;
        #pragma unroll 4
        for (int t = 0; t < 32; t++) {
            int m = w*32 + t;
            if (m > Nn) break;
            bool on;
            if (i == Nn || m == Nn || i == m || i == 0 || m == 0) on = true;
            else {
                int di = i - m; if (di < 0) di = -di;
                on = ((i >> 7) == (m >> 7)) && (di <= 11);   // hier adjacency
            }
            if (on) bits |= 1u << t;
        }
        d_ADJ[row*AW + w] = bits;
    }
    if (tid >= 32 && i < Nn) {         // warp 1: squared norm
        int lane = tid - 32;
        const float* p = d_HG + (size_t)row*Dm;
        float s = 0.f;
        #pragma unroll
        for (int t = 0; t < 4; t++) { float v = p[lane + t*32]; s += v*v; }
        #pragma unroll
        for (int o = 16; o; o >>= 1) s += __shfl_xor_sync(0xffffffffu, s, o);
        if (!lane) d_SQ[b*Nn + i] = s;
    }
}

// ------------------------- D2 matrix (tiled, float4) -------------------------
__global__ void k_d2()
{
    __shared__ float As[16][68];
    __shared__ float Bs[16][68];
    int b = blockIdx.z;
    const float* A = d_HG + (size_t)b*N1*Dm;
    int tid = threadIdx.x;
    int tr = tid >> 4, tc = tid & 15;
    int r0 = blockIdx.y*64, c0 = blockIdx.x*64;
    int lr = tid >> 2;           // 0..63
    int lc = (tid & 3) * 4;      // 0,4,8,12
    float acc[4][4] = {};
    for (int k0 = 0; k0 < Dm; k0 += 16) {
        float4 va = *(const float4*)(A + (size_t)(r0+lr)*Dm + k0 + lc);
        float4 vb = *(const float4*)(A + (size_t)(c0+lr)*Dm + k0 + lc);
        As[lc+0][lr] = va.x; As[lc+1][lr] = va.y; As[lc+2][lr] = va.z; As[lc+3][lr] = va.w;
        Bs[lc+0][lr] = vb.x; Bs[lc+1][lr] = vb.y; Bs[lc+2][lr] = vb.z; Bs[lc+3][lr] = vb.w;
        __syncthreads();
        #pragma unroll
        for (int k = 0; k < 16; k++) {
            float4 a4 = *(const float4*)&As[k][tr*4];
            float4 b4 = *(const float4*)&Bs[k][tc*4];
            float a[4] = {a4.x, a4.y, a4.z, a4.w};
            float bv[4] = {b4.x, b4.y, b4.z, b4.w};
            #pragma unroll
            for (int i = 0; i < 4; i++)
                #pragma unroll
                for (int j = 0; j < 4; j++) acc[i][j] += a[i]*bv[j];
        }
        __syncthreads();
    }
    #pragma unroll
    for (int i = 0; i < 4; i++) {
        int r = r0 + tr*4 + i;
        float sqr = d_SQ[b*Nn + r];
        #pragma unroll
        for (int j = 0; j < 4; j++) {
            int c = c0 + tc*4 + j;
            float v = sqr + d_SQ[b*Nn + c] - 2.f*acc[i][j];
            if (r == c) v = CUDART_INF_F;
            d_D2[((size_t)b*Nn + r)*Nn + c] = v;
        }
    }
}

// ------------------------- exact top-10 kNN -> adjacency bits ----------------
__global__ void k_topk()
{
    int warp = (blockIdx.x*blockDim.x + threadIdx.x) >> 5;
    int lane = threadIdx.x & 31;
    if (warp >= Bsz*Nn) return;
    int b = warp >> 10, i = warp & 1023;
    const float* row = d_D2 + (size_t)warp*Nn;
    float vals[32];
    #pragma unroll
    for (int t = 0; t < 32; t++) vals[t] = row[t*32 + lane];
    unsigned used = 0u;
    unsigned* adjb = d_ADJ + (size_t)b*N1*AW;
    for (int r = 0; r < KNN; r++) {
        float bv = CUDART_INF_F; int bj = 1 << 30;
        #pragma unroll
        for (int t = 0; t < 32; t++) {
            if (!((used >> t) & 1u)) {
                float v = vals[t]; int j = t*32 + lane;
                if (v < bv || (v == bv && j < bj)) { bv = v; bj = j; }
            }
        }
        #pragma unroll
        for (int o = 16; o; o >>= 1) {
            float ov = __shfl_xor_sync(0xffffffffu, bv, o);
            int   oj = __shfl_xor_sync(0xffffffffu, bj, o);
            if (ov < bv || (ov == bv && oj < bj)) { bv = ov; bj = oj; }
        }
        if (lane == (bj & 31)) used |= 1u << (bj >> 5);
        if (lane == 0) {
            atomicOr(&adjb[i*AW + (bj >> 5)], 1u << (bj & 31));
            atomicOr(&adjb[bj*AW + (i >> 5)], 1u << (i & 31));
        }
    }
}

// ------------------------- generic SGEMM: C = A[M,K] * W[N,K]^T --------------
// flags: 1 = +bias[N], 2 = +res[M,N], 4 = relu.  Nc must be a multiple of 64.
__global__ void k_gemm(const float* __restrict__ A, const float* __restrict__ Bm,
                       const float* __restrict__ bias, const float* __restrict__ res,
                       float* __restrict__ C, int M, int Nc, int K, int flags)
{
    __shared__ float As[16][68];
    __shared__ float Bs[16][68];
    int tid = threadIdx.x;
    int tr = tid >> 4, tc = tid & 15;
    int r0 = blockIdx.y*64, c0 = blockIdx.x*64;
    int lr = tid >> 2;
    int lc = (tid & 3) * 4;
    float acc[4][4] = {};
    for (int k0 = 0; k0 < K; k0 += 16) {
        int gr = r0 + lr;
        float4 va = (gr < M) ? *(const float4*)(A + (size_t)gr*K + k0 + lc)
                             : make_float4(0.f,0.f,0.f,0.f);
        float4 vb = *(const float4*)(Bm + (size_t)(c0+lr)*K + k0 + lc);
        As[lc+0][lr] = va.x; As[lc+1][lr] = va.y; As[lc+2][lr] = va.z; As[lc+3][lr] = va.w;
        Bs[lc+0][lr] = vb.x; Bs[lc+1][lr] = vb.y; Bs[lc+2][lr] = vb.z; Bs[lc+3][lr] = vb.w;
        __syncthreads();
        #pragma unroll
        for (int k = 0; k < 16; k++) {
            float4 a4 = *(const float4*)&As[k][tr*4];
            float4 b4 = *(const float4*)&Bs[k][tc*4];
            float a[4] = {a4.x, a4.y, a4.z, a4.w};
            float bv[4] = {b4.x, b4.y, b4.z, b4.w};
            #pragma unroll
            for (int i = 0; i < 4; i++)
                #pragma unroll
                for (int j = 0; j < 4; j++) acc[i][j] += a[i]*bv[j];
        }
        __syncthreads();
    }
    int c = c0 + tc*4;
    float4 bz = make_float4(0.f,0.f,0.f,0.f);
    if (flags & 1) bz = *(const float4*)(bias + c);
    #pragma unroll
    for (int i = 0; i < 4; i++) {
        int r = r0 + tr*4 + i;
        if (r >= M) continue;
        float4 v = make_float4(acc[i][0]+bz.x, acc[i][1]+bz.y, acc[i][2]+bz.z, acc[i][3]+bz.w);
        if (flags & 2) {
            float4 rv = *(const float4*)(res + (size_t)r*Nc + c);
            v.x += rv.x; v.y += rv.y; v.z += rv.z; v.w += rv.w;
        }
        if (flags & 4) {
            v.x = fmaxf(v.x, 0.f); v.y = fmaxf(v.y, 0.f);
            v.z = fmaxf(v.z, 0.f); v.w = fmaxf(v.w, 0.f);
        }
        *(float4*)(C + (size_t)r*Nc + c) = v;
    }
}

// ------------------------- fused QKV GEMM -> head-major outputs --------------
__global__ void k_qkv(const float* __restrict__ A, const float* __restrict__ wq,
                      const float* __restrict__ wk, const float* __restrict__ wv)
{
    __shared__ float As[16][68];
    __shared__ float Bs[16][68];
    int sel = blockIdx.x >> 1;
    const float* Bm = (sel == 0) ? wq : (sel == 1) ? wk : wv;
    float* C = (sel == 0) ? d_Q : (sel == 1) ? d_Kb : d_Vb;
    const int M = Bsz*N1;
    int tid = threadIdx.x;
    int tr = tid >> 4, tc = tid & 15;
    int r0 = blockIdx.y*64, c0 = (blockIdx.x & 1)*64;
    int lr = tid >> 2;
    int lc = (tid & 3) * 4;
    float acc[4][4] = {};
    for (int k0 = 0; k0 < Dm; k0 += 16) {
        int gr = r0 + lr;
        float4 va = (gr < M) ? *(const float4*)(A + (size_t)gr*Dm + k0 + lc)
                             : make_float4(0.f,0.f,0.f,0.f);
        float4 vb = *(const float4*)(Bm + (size_t)(c0+lr)*Dm + k0 + lc);
        As[lc+0][lr] = va.x; As[lc+1][lr] = va.y; As[lc+2][lr] = va.z; As[lc+3][lr] = va.w;
        Bs[lc+0][lr] = vb.x; Bs[lc+1][lr] = vb.y; Bs[lc+2][lr] = vb.z; Bs[lc+3][lr] = vb.w;
        __syncthreads();
        #pragma unroll
        for (int k = 0; k < 16; k++) {
            float4 a4 = *(const float4*)&As[k][tr*4];
            float4 b4 = *(const float4*)&Bs[k][tc*4];
            float a[4] = {a4.x, a4.y, a4.z, a4.w};
            float bv[4] = {b4.x, b4.y, b4.z, b4.w};
            #pragma unroll
            for (int i = 0; i < 4; i++)
                #pragma unroll
                for (int j = 0; j < 4; j++) acc[i][j] += a[i]*bv[j];
        }
        __syncthreads();
    }
    int c = c0 + tc*4;
    int h  = c >> 4;           // head
    int dk = c & 15;           // offset within head (0,4,8,12)
    #pragma unroll
    for (int i = 0; i < 4; i++) {
        int r = r0 + tr*4 + i;
        if (r >= M) continue;
        int bb = (r >= N1) ? 1 : 0;
        int n  = r - bb*N1;
        *(float4*)(C + ((size_t)(bb*Hh + h)*N1 + n)*Dk + dk) =
            make_float4(acc[i][0], acc[i][1], acc[i][2], acc[i][3]);
    }
}

// ------------------------- qe = Q . emb per (head,bucket), head-major --------
__global__ void k_qe(const float* __restrict__ emb)
{
    __shared__ float qs[Dm];
    int row = blockIdx.x;              // b*N1 + n
    int b = (row >= N1) ? 1 : 0;
    int n = row - b*N1;
    int tid = threadIdx.x;
    if (tid < Dm) {
        int hh = tid >> 4, dk = tid & 15;
        qs[tid] = d_Q[((size_t)(b*Hh + hh)*N1 + n)*Dk + dk];
    }
    __syncthreads();
    int h = tid >> 5, kb = tid & 31;
    const float* e = emb + kb*Dm + h*Dk;
    const float* q = qs + h*Dk;
    float s = 0.f;
    #pragma unroll
    for (int dd = 0; dd < Dk; dd++) s += q[dd]*e[dd];
    d_QE[((size_t)(b*Hh + h)*N1 + n)*NBk + kb] = s;
}

// ------------------------- sparse masked attention (block-tile) --------------
__device__ __forceinline__ void attn_word(unsigned word, int base,
    const float q[16], float cqx, float cqy,
    const float (*Ks)[17], const float (*Vs)[17],
    const float* ckx, const float* cky, const float* qerow,
    float& mrun, float& lrun, float acc[16])
{
    while (word) {
        int mm = base + (__ffs((int)word) - 1);
        word &= word - 1u;
        float s = 0.f;
        #pragma unroll
        for (int d = 0; d < 16; d++) s += q[d]*Ks[mm][d];
        float dx = cqx - ckx[mm], dy = cqy - cky[mm];
        float dist = sqrtf(dx*dx + dy*dy);
        int bk = (int)(dist * 32.f); if (bk > 31) bk = 31;
        s = s*SCALEf + qerow[bk];
        if (s > mrun) {
            float cr = __expf(mrun - s);        // first hit: exp(-inf)=0
            lrun = lrun*cr + 1.f;
            #pragma unroll
            for (int d = 0; d < 16; d++) acc[d] = acc[d]*cr + Vs[mm][d];
            mrun = s;
        } else {
            float p = __expf(s - mrun);
            lrun += p;
            #pragma unroll
            for (int d = 0; d < 16; d++) acc[d] += p*Vs[mm][d];
        }
    }
}

__global__ void k_attn(const float* __restrict__ coords)
{
    __shared__ float Ks[128][17];
    __shared__ float Vs[128][17];
    __shared__ float ckx[128], cky[128];
    __shared__ float qes[128][33];
    int b = blockIdx.z, h = blockIdx.y;
    int q0 = blockIdx.x * 128;
    int tid = threadIdx.x;
    int n = q0 + tid;
    bool qv = (n < N1) && (n != 0) && (n != Nn);   // dense rows handled by k_dense
    float q[16], acc[16];
    float cqx = 0.f, cqy = 0.f, mrun = -CUDART_INF_F, lrun = 0.f;
    #pragma unroll
    for (int d = 0; d < 16; d++) { q[d] = 0.f; acc[d] = 0.f; }
    const size_t hb = (size_t)(b*Hh + h)*N1;
    const unsigned* rowadj = d_ADJ;
    if (qv) {
        const float4* qp = (const float4*)(d_Q + (hb + n)*Dk);
        #pragma unroll
        for (int i = 0; i < 4; i++) {
            float4 v = qp[i];
            q[i*4+0]=v.x; q[i*4+1]=v.y; q[i*4+2]=v.z; q[i*4+3]=v.w;
        }
        if (n < Nn) { cqx = coords[(b*Nn+n)*2]; cqy = coords[(b*Nn+n)*2+1]; }
        const float4* qep = (const float4*)(d_QE + (hb + n)*NBk);
        #pragma unroll
        for (int i = 0; i < 8; i++) {
            float4 v = qep[i];
            qes[tid][i*4+0]=v.x; qes[tid][i*4+1]=v.y;
            qes[tid][i*4+2]=v.z; qes[tid][i*4+3]=v.w;
        }
        rowadj = d_ADJ + (size_t)(b*N1 + n)*AW;
    }
    for (int kt = 0; kt < 9; kt++) {
        int m0 = kt*128;
        int tlen = N1 - m0; if (tlen > 128) tlen = 128;
        const float4* Kt = (const float4*)(d_Kb + (hb + m0)*Dk);
        const float4* Vt = (const float4*)(d_Vb + (hb + m0)*Dk);
        __syncthreads();
        #pragma unroll
        for (int i = 0; i < 4; i++) {
            int f = tid + i*128;          // float4 index within 128x16 tile
            int row = f >> 2, j = (f & 3)*4;
            if (row < tlen) {
                float4 kv = Kt[f];
                Ks[row][j+0]=kv.x; Ks[row][j+1]=kv.y; Ks[row][j+2]=kv.z; Ks[row][j+3]=kv.w;
                float4 vv = Vt[f];
                Vs[row][j+0]=vv.x; Vs[row][j+1]=vv.y; Vs[row][j+2]=vv.z; Vs[row][j+3]=vv.w;
            }
        }
        if (tid < tlen) {
            int m = m0 + tid;
            if (m < Nn) { ckx[tid] = coords[(b*Nn+m)*2]; cky[tid] = coords[(b*Nn+m)*2+1]; }
            else        { ckx[tid] = 0.f; cky[tid] = 0.f; }
        }
        __syncthreads();
        if (!qv) continue;
        int wb = m0 >> 5;
        unsigned w0 = rowadj[wb];
        unsigned w1 = (wb+1 < AW) ? rowadj[wb+1] : 0u;
        unsigned w2 = (wb+2 < AW) ? rowadj[wb+2] : 0u;
        unsigned w3 = (wb+3 < AW) ? rowadj[wb+3] : 0u;
        attn_word(w0,  0, q, cqx, cqy, Ks, Vs, ckx, cky, qes[tid], mrun, lrun, acc);
        attn_word(w1, 32, q, cqx, cqy, Ks, Vs, ckx, cky, qes[tid], mrun, lrun, acc);
        attn_word(w2, 64, q, cqx, cqy, Ks, Vs, ckx, cky, qes[tid], mrun, lrun, acc);
        attn_word(w3, 96, q, cqx, cqy, Ks, Vs, ckx, cky, qes[tid], mrun, lrun, acc);
    }
    if (qv) {
        float inv = 1.f / lrun;
        float* o = d_CTX + ((size_t)(b*N1 + n))*Dm + h*Dk;
        #pragma unroll
        for (int d = 0; d < 16; d++) o[d] = acc[d]*inv;
    }
}

// ------------------------- dense attention for rows {0, Nn} ------------------
// grid (2, Hh, Bsz), 128 threads. Full softmax over all 1025 keys in parallel.
__global__ void k_dense(const float* __restrict__ coords)
{
    __shared__ float qsh[16], qesh[32];
    __shared__ float pm[4], pl[4], pa[4][16];
    int b = blockIdx.z, h = blockIdx.y;
    int n = blockIdx.x ? Nn : 0;
    int tid = threadIdx.x, lane = tid & 31, w = tid >> 5;
    const size_t hb = (size_t)(b*Hh + h)*N1;
    if (tid < 16) qsh[tid] = d_Q[(hb + n)*Dk + tid];
    if (tid >= 32 && tid < 64) qesh[tid-32] = d_QE[(hb + n)*NBk + (tid-32)];
    __syncthreads();
    float q[16];
    #pragma unroll
    for (int d = 0; d < 16; d++) q[d] = qsh[d];
    float cqx = 0.f, cqy = 0.f;
    if (n < Nn) { cqx = coords[(b*Nn+n)*2]; cqy = coords[(b*Nn+n)*2+1]; }
    float m = -CUDART_INF_F, l = 0.f, acc[16];
    #pragma unroll
    for (int d = 0; d < 16; d++) acc[d] = 0.f;
    const float* Kt = d_Kb + hb*Dk;
    const float* Vt = d_Vb + hb*Dk;
    for (int mk = tid; mk < N1; mk += 128) {
        const float4* kp = (const float4*)(Kt + (size_t)mk*Dk);
        float s = 0.f;
        #pragma unroll
        for (int i = 0; i < 4; i++) {
            float4 kv = kp[i];
            s += q[i*4+0]*kv.x + q[i*4+1]*kv.y + q[i*4+2]*kv.z + q[i*4+3]*kv.w;
        }
        float cmx = 0.f, cmy = 0.f;
        if (mk < Nn) { cmx = coords[(b*Nn+mk)*2]; cmy = coords[(b*Nn+mk)*2+1]; }
        float dx = cqx - cmx, dy = cqy - cmy;
        float dist = sqrtf(dx*dx + dy*dy);
        int bk = (int)(dist * 32.f); if (bk > 31) bk = 31;
        s = s*SCALEf + qesh[bk];
        const float4* vp = (const float4*)(Vt + (size_t)mk*Dk);
        if (s > m) {
            float cr = __expf(m - s);
            l = l*cr + 1.f;
            #pragma unroll
            for (int i = 0; i < 4; i++) {
                float4 vv = vp[i];
                acc[i*4+0] = acc[i*4+0]*cr + vv.x;
                acc[i*4+1] = acc[i*4+1]*cr + vv.y;
                acc[i*4+2] = acc[i*4+2]*cr + vv.z;
                acc[i*4+3] = acc[i*4+3]*cr + vv.w;
            }
            m = s;
        } else {
            float p = __expf(s - m);
            l += p;
            #pragma unroll
            for (int i = 0; i < 4; i++) {
                float4 vv = vp[i];
                acc[i*4+0] += p*vv.x; acc[i*4+1] += p*vv.y;
                acc[i*4+2] += p*vv.z; acc[i*4+3] += p*vv.w;
            }
        }
    }
    // warp merge
    #pragma unroll
    for (int o = 16; o; o >>= 1) {
        float m2 = __shfl_xor_sync(0xffffffffu, m, o);
        float l2 = __shfl_xor_sync(0xffffffffu, l, o);
        float a2[16];
        #pragma unroll
        for (int d = 0; d < 16; d++) a2[d] = __shfl_xor_sync(0xffffffffu, acc[d], o);
        float M = fmaxf(m, m2);
        float e1 = __expf(m - M), e2 = __expf(m2 - M);
        l = l*e1 + l2*e2;
        #pragma unroll
        for (int d = 0; d < 16; d++) acc[d] = acc[d]*e1 + a2[d]*e2;
        m = M;
    }
    if (lane == 0) {
        pm[w] = m; pl[w] = l;
        #pragma unroll
        for (int d = 0; d < 16; d++) pa[w][d] = acc[d];
    }
    __syncthreads();
    if (w == 0) {
        if (lane < 4) {
            m = pm[lane]; l = pl[lane];
            #pragma unroll
            for (int d = 0; d < 16; d++) acc[d] = pa[lane][d];
        } else {
            m = -CUDART_INF_F; l = 0.f;
            #pragma unroll
            for (int d = 0; d < 16; d++) acc[d] = 0.f;
        }
        #pragma unroll
        for (int o = 1; o <= 2; o <<= 1) {
            float m2 = __shfl_xor_sync(0xffffffffu, m, o);
            float l2 = __shfl_xor_sync(0xffffffffu, l, o);
            float a2[16];
            #pragma unroll
            for (int d = 0; d < 16; d++) a2[d] = __shfl_xor_sync(0xffffffffu, acc[d], o);
            float M = fmaxf(m, m2);
            float e1 = __expf(m - M), e2 = __expf(m2 - M);
            l = l*e1 + l2*e2;
            #pragma unroll
            for (int d = 0; d < 16; d++) acc[d] = acc[d]*e1 + a2[d]*e2;
            m = M;
        }
        if (lane == 0) {
            float inv = 1.f / l;
            float* o = d_CTX + ((size_t)(b*N1 + n))*Dm + h*Dk;
            #pragma unroll
            for (int d = 0; d < 16; d++) o[d] = acc[d]*inv;
        }
    }
}

// ------------------------- instance norm over sequence axis ------------------
// grid (Bsz, 4): each block owns a 32-wide d slice. fuse=1 additionally does
// POOL += mean(out_h) and out[g-row] += mean(out_h)  (next layer's g update).
__global__ void k_inorm(const float* __restrict__ src, float* __restrict__ dst,
                        const float* __restrict__ w, const float* __restrict__ bb, int fuse)
{
    __shared__ float red[32][33];
    __shared__ float s_mu[32], s_sc[32], s_mh[32];
    int b  = blockIdx.x;
    int dl = threadIdx.x & 31;
    int g  = threadIdx.x >> 5;
    int d  = blockIdx.y*32 + dl;
    const float* p = src + (size_t)b*N1*Dm + d;
    float s = 0.f;
    for (int n = g; n < N1; n += 32) s += p[(size_t)n*Dm];
    red[g][dl] = s;
    __syncthreads();
    if (g == 0) {
        float t = 0.f;
        #pragma unroll
        for (int i = 0; i < 32; i++) t += red[i][dl];
        s_mu[dl] = t * (1.f/N1);
        if (fuse) s_mh[dl] = (t - p[(size_t)Nn*Dm]) * (1.f/Nn);  // mean_{n<N} of src
    }
    __syncthreads();
    float mu = s_mu[dl];
    float v = 0.f;
    for (int n = g; n < N1; n += 32) { float x = p[(size_t)n*Dm] - mu; v += x*x; }
    __syncthreads();
    red[g][dl] = v;
    __syncthreads();
    if (g == 0) {
        float t = 0.f;
        #pragma unroll
        for (int i = 0; i < 32; i++) t += red[i][dl];
        s_sc[dl] = rsqrtf(t*(1.f/N1) + EPSf) * w[d];
    }
    __syncthreads();
    float sc = s_sc[dl], sh = bb[d];
    float mo = 0.f;
    if (fuse) mo = (s_mh[dl] - mu)*sc + sh;      // mean over n<N of normalized out
    float* o = dst + (size_t)b*N1*Dm + d;
    for (int n = g; n < N1; n += 32) {
        float val = (p[(size_t)n*Dm] - mu)*sc + sh;
        if (fuse && n == Nn) val += mo;          // g += mean(h) for next layer
        o[(size_t)n*Dm] = val;
    }
    if (fuse && g == 0) d_POOL[b*Dm + d] += mo;  // pools.append(mean(h))
}

// ------------------------- final prep: X = h + p_multi; write p_multi --------
__global__ void k_final(float* __restrict__ out)
{
    int gid = blockIdx.x*blockDim.x + threadIdx.x;
    if (gid < Bsz*Dm) out[Bsz*Nn*Dm + gid] = d_POOL[gid] * (1.f/3.f);
    if (gid >= Bsz*Nn*Dm) return;
    int d = gid & 127;
    int n = (gid >> 7) & 1023;
    int b = gid >> 17;
    d_X[gid] = d_HG[((size_t)b*N1 + n)*Dm + d] + d_POOL[b*Dm + d]*(1.f/3.f);
}

// ------------------------- host driver ---------------------------------------
extern "C" void kernel_launch(void* const* d_in, const int* in_sizes, int n_in,
                              void* d_out, int out_size)
{
    const float* coords = (const float*)d_in[0];
    const float* in_W   = (const float*)d_in[1];
    const float* in_b   = (const float*)d_in[2];
    const float* gnode  = (const float*)d_in[3];
    const float* Wq     = (const float*)d_in[4];
    const float* Wk     = (const float*)d_in[5];
    const float* Wv     = (const float*)d_in[6];
    const float* Wo     = (const float*)d_in[7];
    const float* emb    = (const float*)d_in[8];
    const float* W1     = (const float*)d_in[9];
    const float* b1     = (const float*)d_in[10];
    const float* W2     = (const float*)d_in[11];
    const float* b2     = (const float*)d_in[12];
    const float* n1w    = (const float*)d_in[13];
    const float* n1b    = (const float*)d_in[14];
    const float* n2w    = (const float*)d_in[15];
    const float* n2b    = (const float*)d_in[16];
    const float* outW   = (const float*)d_in[17];
    const float* outb   = (const float*)d_in[18];
    float* out = (float*)d_out;

    float *HG, *CTX, *Y, *T1, *T2, *X;
    cudaGetSymbolAddress((void**)&HG,  d_HG);
    cudaGetSymbolAddress((void**)&CTX, d_CTX);
    cudaGetSymbolAddress((void**)&Y,   d_Y);
    cudaGetSymbolAddress((void**)&T1,  d_T1);
    cudaGetSymbolAddress((void**)&T2,  d_T2);
    cudaGetSymbolAddress((void**)&X,   d_X);

    const int Mall = Bsz*N1;  // 2050

    k_input<<<(Bsz*N1*Dm + 255)/256, 256>>>(coords, in_W, in_b, gnode);
    k_colmean<<<Bsz, 1024>>>();                            // layer-0 g update

    for (int l = 0; l < 3; l++) {
        k_prol<<<Bsz*N1, 64>>>();
        { dim3 g(Nn/64, Nn/64, Bsz); k_d2<<<g, 256>>>(); }
        k_topk<<<(Bsz*Nn)/8, 256>>>();

        { dim3 gqkv(6, (Mall + 63)/64);
          k_qkv<<<gqkv, 256>>>(HG, Wq + (size_t)l*Dm*Dm, Wk + (size_t)l*Dm*Dm, Wv + (size_t)l*Dm*Dm); }
        k_qe<<<Mall, 256>>>(emb + (size_t)l*NBk*Dm);
        { dim3 ga(9, Hh, Bsz); k_attn<<<ga, 128>>>(coords); }
        { dim3 gd(2, Hh, Bsz); k_dense<<<gd, 128>>>(coords); }

        dim3 gq(Dm/64, (Mall + 63)/64);
        k_gemm<<<gq, 256>>>(CTX, Wo + (size_t)l*Dm*Dm, nullptr, HG, Y, Mall, Dm, Dm, 2);
        { dim3 gi(Bsz, 4); k_inorm<<<gi, 1024>>>(Y, Y, n1w + l*Dm, n1b + l*Dm, 0); }

        dim3 g1(Dff/64, (Mall + 63)/64);
        k_gemm<<<g1, 256>>>(Y,  W1 + (size_t)l*Dff*Dm, b1 + l*Dff, nullptr, T1, Mall, Dff, Dm, 1|4);
        k_gemm<<<gq, 256>>>(T1, W2 + (size_t)l*Dm*Dff, b2 + l*Dm,  Y,      T2, Mall, Dm, Dff, 1|2);
        { dim3 gi(Bsz, 4); k_inorm<<<gi, 1024>>>(T2, HG, n2w + l*Dm, n2b + l*Dm, 1); }
    }

    k_final<<<(Bsz*Nn*Dm + 255)/256, 256>>>(out);
    { dim3 ge(Dm/64, (Bsz*Nn + 63)/64);
      k_gemm<<<ge, 256>>>(X, outW, outb, nullptr, out, Bsz*Nn, Dm, Dm, 1); }
}

// round 5
// speedup vs baseline: 3.4029x; 1.0315x over previous
#include <cuda_runtime.h>
#include <math_constants.h>
#include <math.h>

#define Bsz 2
#define Nn 1024
#define N1 1025
#define Dm 128
#define Hh 8
#define Dk 16
#define Dff 512
#define NBk 32
#define KNN 10
#define AW 33          // 33 x 32-bit words cover 1025 mask bits per row
#define EPSf 1e-5f
#define SCALEf 0.25f   // 1/sqrt(16)
#define NCH 17         // inorm stat chunks (16x64 rows + 1 for row 1024)

// ------------------------- persistent device scratch -------------------------
__device__ float    d_HG [Bsz*N1*Dm];     // state: rows 0..1023 = h, row 1024 = g
__device__ float    d_POOL[Bsz*Dm];
__device__ float    d_SQ [Bsz*Nn];
__device__ float    d_D2 [(size_t)Bsz*Nn*Nn];
__device__ unsigned d_ADJ[Bsz*N1*AW];
__device__ float    d_Q  [Bsz*Hh*N1*Dk];  // head-major: [b][h][n][dk]
__device__ float    d_Kb [Bsz*Hh*N1*Dk];
__device__ float    d_Vb [Bsz*Hh*N1*Dk];
__device__ float    d_CTX[Bsz*N1*Dm];
__device__ float    d_QE [Bsz*Hh*N1*NBk]; // head-major: [b][h][n][bucket]
__device__ float    d_Y  [Bsz*N1*Dm];
__device__ float    d_T1 [Bsz*N1*Dff];
__device__ float    d_T2 [Bsz*N1*Dm];
__device__ float    d_X  [Bsz*Nn*Dm];
__device__ float    d_PS1[Bsz*NCH*Dm];
__device__ float    d_PS2[Bsz*NCH*Dm];

// ------------------------- input embedding + state init ----------------------
__global__ void k_input(const float* __restrict__ coords, const float* __restrict__ inW,
                        const float* __restrict__ inb, const float* __restrict__ gnode)
{
    int gid = blockIdx.x*blockDim.x + threadIdx.x;
    if (gid < Bsz*Dm) d_POOL[gid] = 0.f;
    if (gid >= Bsz*N1*Dm) return;
    int d = gid % Dm;
    int n = (gid / Dm) % N1;
    int b = gid / (Dm*N1);
    float v;
    if (n < Nn) {
        float x = coords[(b*Nn+n)*2+0];
        float y = coords[(b*Nn+n)*2+1];
        v = x*inW[d*2+0] + y*inW[d*2+1] + inb[d];
    } else {
        v = gnode[d];
    }
    d_HG[gid] = v;
}

// ------------------------- layer-0 g update: g += mean(h) --------------------
__global__ void k_colmean()
{
    __shared__ float red[8][Dm];
    int b = blockIdx.x;
    int d = threadIdx.x & 127;
    int g = threadIdx.x >> 7;
    const float* base = d_HG + (size_t)b*N1*Dm;
    float s = 0.f;
    for (int n = g; n < Nn; n += 8) s += base[n*Dm + d];
    red[g][d] = s;
    __syncthreads();
    if (g == 0) {
        float t = 0.f;
        #pragma unroll
        for (int i = 0; i < 8; i++) t += red[i][d];
        d_HG[(size_t)b*N1*Dm + Nn*Dm + d] += t * (1.f/Nn);
    }
}

// ------------------------- prologue: adjacency base + sq norms ---------------
__global__ void k_prol()
{
    int row = blockIdx.x;              // b*N1 + i
    int i   = row % N1;
    int b   = row / N1;
    int tid = threadIdx.x;
    if (tid < AW) {
        int w = tid;
        unsigned bits = 0u;
        #pragma unroll 4
        for (int t = 0; t < 32; t++) {
            int m = w*32 + t;
            if (m > Nn) break;
            bool on;
            if (i == Nn || m == Nn || i == m || i == 0 || m == 0) on = true;
            else {
                int di = i - m; if (di < 0) di = -di;
                on = ((i >> 7) == (m >> 7)) && (di <= 11);   // hier adjacency
            }
            if (on) bits |= 1u << t;
        }
        d_ADJ[row*AW + w] = bits;
    }
    if (tid >= 32 && i < Nn) {         // warp 1: squared norm
        int lane = tid - 32;
        const float* p = d_HG + (size_t)row*Dm;
        float s = 0.f;
        #pragma unroll
        for (int t = 0; t < 4; t++) { float v = p[lane + t*32]; s += v*v; }
        #pragma unroll
        for (int o = 16; o; o >>= 1) s += __shfl_xor_sync(0xffffffffu, s, o);
        if (!lane) d_SQ[b*Nn + i] = s;
    }
}

// ------------------------- D2 matrix (128x128 tile, 8x8/thread) --------------
__global__ void k_d2()
{
    __shared__ float As[16][132];
    __shared__ float Bs[16][132];
    int b = blockIdx.z;
    const float* A = d_HG + (size_t)b*N1*Dm;
    int tid = threadIdx.x;             // 256
    int tr = tid >> 4, tc = tid & 15;
    int r0 = blockIdx.y*128, c0 = blockIdx.x*128;
    int lr = tid >> 1;                 // 0..127
    int lc = (tid & 1) * 8;            // 0 or 8
    float acc[8][8] = {};
    for (int k0 = 0; k0 < Dm; k0 += 16) {
        const float* ar = A + (size_t)(r0+lr)*Dm + k0 + lc;
        const float* br = A + (size_t)(c0+lr)*Dm + k0 + lc;
        float4 a0 = *(const float4*)ar;
        float4 a1 = *(const float4*)(ar+4);
        float4 b0 = *(const float4*)br;
        float4 b1 = *(const float4*)(br+4);
        As[lc+0][lr]=a0.x; As[lc+1][lr]=a0.y; As[lc+2][lr]=a0.z; As[lc+3][lr]=a0.w;
        As[lc+4][lr]=a1.x; As[lc+5][lr]=a1.y; As[lc+6][lr]=a1.z; As[lc+7][lr]=a1.w;
        Bs[lc+0][lr]=b0.x; Bs[lc+1][lr]=b0.y; Bs[lc+2][lr]=b0.z; Bs[lc+3][lr]=b0.w;
        Bs[lc+4][lr]=b1.x; Bs[lc+5][lr]=b1.y; Bs[lc+6][lr]=b1.z; Bs[lc+7][lr]=b1.w;
        __syncthreads();
        #pragma unroll
        for (int k = 0; k < 16; k++) {
            float a[8], bv[8];
            *(float4*)(a+0) = *(const float4*)&As[k][tr*8+0];
            *(float4*)(a+4) = *(const float4*)&As[k][tr*8+4];
            *(float4*)(bv+0) = *(const float4*)&Bs[k][tc*8+0];
            *(float4*)(bv+4) = *(const float4*)&Bs[k][tc*8+4];
            #pragma unroll
            for (int i = 0; i < 8; i++)
                #pragma unroll
                for (int j = 0; j < 8; j++) acc[i][j] += a[i]*bv[j];
        }
        __syncthreads();
    }
    #pragma unroll
    for (int i = 0; i < 8; i++) {
        int r = r0 + tr*8 + i;
        float sqr = d_SQ[b*Nn + r];
        float* orow = d_D2 + ((size_t)b*Nn + r)*Nn + c0 + tc*8;
        float o[8];
        #pragma unroll
        for (int j = 0; j < 8; j++) {
            int c = c0 + tc*8 + j;
            float v = sqr + d_SQ[b*Nn + c] - 2.f*acc[i][j];
            o[j] = (r == c) ? CUDART_INF_F : v;
        }
        *(float4*)(orow+0) = make_float4(o[0],o[1],o[2],o[3]);
        *(float4*)(orow+4) = make_float4(o[4],o[5],o[6],o[7]);
    }
}

// ------------------------- exact top-10 kNN -> adjacency bits ----------------
__global__ void k_topk()
{
    int warp = (blockIdx.x*blockDim.x + threadIdx.x) >> 5;
    int lane = threadIdx.x & 31;
    if (warp >= Bsz*Nn) return;
    int b = warp >> 10, i = warp & 1023;
    const float* row = d_D2 + (size_t)warp*Nn;
    float vals[32];
    #pragma unroll
    for (int t = 0; t < 32; t++) vals[t] = row[t*32 + lane];
    unsigned used = 0u;
    unsigned* adjb = d_ADJ + (size_t)b*N1*AW;
    for (int r = 0; r < KNN; r++) {
        float bv = CUDART_INF_F; int bj = 1 << 30;
        #pragma unroll
        for (int t = 0; t < 32; t++) {
            if (!((used >> t) & 1u)) {
                float v = vals[t]; int j = t*32 + lane;
                if (v < bv || (v == bv && j < bj)) { bv = v; bj = j; }
            }
        }
        #pragma unroll
        for (int o = 16; o; o >>= 1) {
            float ov = __shfl_xor_sync(0xffffffffu, bv, o);
            int   oj = __shfl_xor_sync(0xffffffffu, bj, o);
            if (ov < bv || (ov == bv && oj < bj)) { bv = ov; bj = oj; }
        }
        if (lane == (bj & 31)) used |= 1u << (bj >> 5);
        if (lane == 0) {
            atomicOr(&adjb[i*AW + (bj >> 5)], 1u << (bj & 31));
            atomicOr(&adjb[bj*AW + (i >> 5)], 1u << (i & 31));
        }
    }
}

// ------------------------- generic SGEMM: C = A[M,K] * W[N,K]^T --------------
// flags: 1 = +bias[N], 2 = +res[M,N], 4 = relu.  Nc must be a multiple of 64.
__global__ void k_gemm(const float* __restrict__ A, const float* __restrict__ Bm,
                       const float* __restrict__ bias, const float* __restrict__ res,
                       float* __restrict__ C, int M, int Nc, int K, int flags)
{
    __shared__ float As[16][68];
    __shared__ float Bs[16][68];
    int tid = threadIdx.x;
    int tr = tid >> 4, tc = tid & 15;
    int r0 = blockIdx.y*64, c0 = blockIdx.x*64;
    int lr = tid >> 2;
    int lc = (tid & 3) * 4;
    float acc[4][4] = {};
    for (int k0 = 0; k0 < K; k0 += 16) {
        int gr = r0 + lr;
        float4 va = (gr < M) ? *(const float4*)(A + (size_t)gr*K + k0 + lc)
                             : make_float4(0.f,0.f,0.f,0.f);
        float4 vb = *(const float4*)(Bm + (size_t)(c0+lr)*K + k0 + lc);
        As[lc+0][lr] = va.x; As[lc+1][lr] = va.y; As[lc+2][lr] = va.z; As[lc+3][lr] = va.w;
        Bs[lc+0][lr] = vb.x; Bs[lc+1][lr] = vb.y; Bs[lc+2][lr] = vb.z; Bs[lc+3][lr] = vb.w;
        __syncthreads();
        #pragma unroll
        for (int k = 0; k < 16; k++) {
            float4 a4 = *(const float4*)&As[k][tr*4];
            float4 b4 = *(const float4*)&Bs[k][tc*4];
            float a[4] = {a4.x, a4.y, a4.z, a4.w};
            float bv[4] = {b4.x, b4.y, b4.z, b4.w};
            #pragma unroll
            for (int i = 0; i < 4; i++)
                #pragma unroll
                for (int j = 0; j < 4; j++) acc[i][j] += a[i]*bv[j];
        }
        __syncthreads();
    }
    int c = c0 + tc*4;
    float4 bz = make_float4(0.f,0.f,0.f,0.f);
    if (flags & 1) bz = *(const float4*)(bias + c);
    #pragma unroll
    for (int i = 0; i < 4; i++) {
        int r = r0 + tr*4 + i;
        if (r >= M) continue;
        float4 v = make_float4(acc[i][0]+bz.x, acc[i][1]+bz.y, acc[i][2]+bz.z, acc[i][3]+bz.w);
        if (flags & 2) {
            float4 rv = *(const float4*)(res + (size_t)r*Nc + c);
            v.x += rv.x; v.y += rv.y; v.z += rv.z; v.w += rv.w;
        }
        if (flags & 4) {
            v.x = fmaxf(v.x, 0.f); v.y = fmaxf(v.y, 0.f);
            v.z = fmaxf(v.z, 0.f); v.w = fmaxf(v.w, 0.f);
        }
        *(float4*)(C + (size_t)r*Nc + c) = v;
    }
}

// ------------------------- fused QKV GEMM -> head-major outputs --------------
__global__ void k_qkv(const float* __restrict__ A, const float* __restrict__ wq,
                      const float* __restrict__ wk, const float* __restrict__ wv)
{
    __shared__ float As[16][68];
    __shared__ float Bs[16][68];
    int sel = blockIdx.x >> 1;
    const float* Bm = (sel == 0) ? wq : (sel == 1) ? wk : wv;
    float* C = (sel == 0) ? d_Q : (sel == 1) ? d_Kb : d_Vb;
    const int M = Bsz*N1;
    int tid = threadIdx.x;
    int tr = tid >> 4, tc = tid & 15;
    int r0 = blockIdx.y*64, c0 = (blockIdx.x & 1)*64;
    int lr = tid >> 2;
    int lc = (tid & 3) * 4;
    float acc[4][4] = {};
    for (int k0 = 0; k0 < Dm; k0 += 16) {
        int gr = r0 + lr;
        float4 va = (gr < M) ? *(const float4*)(A + (size_t)gr*Dm + k0 + lc)
                             : make_float4(0.f,0.f,0.f,0.f);
        float4 vb = *(const float4*)(Bm + (size_t)(c0+lr)*Dm + k0 + lc);
        As[lc+0][lr] = va.x; As[lc+1][lr] = va.y; As[lc+2][lr] = va.z; As[lc+3][lr] = va.w;
        Bs[lc+0][lr] = vb.x; Bs[lc+1][lr] = vb.y; Bs[lc+2][lr] = vb.z; Bs[lc+3][lr] = vb.w;
        __syncthreads();
        #pragma unroll
        for (int k = 0; k < 16; k++) {
            float4 a4 = *(const float4*)&As[k][tr*4];
            float4 b4 = *(const float4*)&Bs[k][tc*4];
            float a[4] = {a4.x, a4.y, a4.z, a4.w};
            float bv[4] = {b4.x, b4.y, b4.z, b4.w};
            #pragma unroll
            for (int i = 0; i < 4; i++)
                #pragma unroll
                for (int j = 0; j < 4; j++) acc[i][j] += a[i]*bv[j];
        }
        __syncthreads();
    }
    int c = c0 + tc*4;
    int h  = c >> 4;           // head
    int dk = c & 15;           // offset within head (0,4,8,12)
    #pragma unroll
    for (int i = 0; i < 4; i++) {
        int r = r0 + tr*4 + i;
        if (r >= M) continue;
        int bb = (r >= N1) ? 1 : 0;
        int n  = r - bb*N1;
        *(float4*)(C + ((size_t)(bb*Hh + h)*N1 + n)*Dk + dk) =
            make_float4(acc[i][0], acc[i][1], acc[i][2], acc[i][3]);
    }
}

// ------------------------- qe = Q . emb per (head,bucket), head-major --------
__global__ void k_qe(const float* __restrict__ emb)
{
    __shared__ float qs[Dm];
    int row = blockIdx.x;              // b*N1 + n
    int b = (row >= N1) ? 1 : 0;
    int n = row - b*N1;
    int tid = threadIdx.x;
    if (tid < Dm) {
        int hh = tid >> 4, dk = tid & 15;
        qs[tid] = d_Q[((size_t)(b*Hh + hh)*N1 + n)*Dk + dk];
    }
    __syncthreads();
    int h = tid >> 5, kb = tid & 31;
    const float* e = emb + kb*Dm + h*Dk;
    const float* q = qs + h*Dk;
    float s = 0.f;
    #pragma unroll
    for (int dd = 0; dd < Dk; dd++) s += q[dd]*e[dd];
    d_QE[((size_t)(b*Hh + h)*N1 + n)*NBk + kb] = s;
}

// ------------------------- sparse masked attention (raw-exp softmax) ---------
__device__ __forceinline__ void attn_word(unsigned word, int base,
    const float q[16], float cqx, float cqy,
    const float (*Ks)[17], const float (*Vs)[17],
    const float* ckx, const float* cky, const float* qerow,
    float& lrun, float acc[16])
{
    while (word) {
        int mm = base + (__ffs((int)word) - 1);
        word &= word - 1u;
        float s = 0.f;
        #pragma unroll
        for (int d = 0; d < 16; d++) s += q[d]*Ks[mm][d];
        float dx = cqx - ckx[mm], dy = cqy - cky[mm];
        float dist = sqrtf(dx*dx + dy*dy);
        int bk = (int)(dist * 32.f); if (bk > 31) bk = 31;
        float p = __expf(s*SCALEf + qerow[bk]);
        lrun += p;
        #pragma unroll
        for (int d = 0; d < 16; d++) acc[d] += p*Vs[mm][d];
    }
}

__global__ void k_attn(const float* __restrict__ coords)
{
    __shared__ float Ks[128][17];
    __shared__ float Vs[128][17];
    __shared__ float ckx[128], cky[128];
    __shared__ float qes[128][33];
    int b = blockIdx.z, h = blockIdx.y;
    int q0 = blockIdx.x * 128;
    int tid = threadIdx.x;
    int n = q0 + tid;
    bool qv = (n < N1) && (n != 0) && (n != Nn);   // dense rows handled by k_dense
    float q[16], acc[16];
    float cqx = 0.f, cqy = 0.f, lrun = 0.f;
    #pragma unroll
    for (int d = 0; d < 16; d++) { q[d] = 0.f; acc[d] = 0.f; }
    const size_t hb = (size_t)(b*Hh + h)*N1;
    const unsigned* rowadj = d_ADJ;
    if (qv) {
        const float4* qp = (const float4*)(d_Q + (hb + n)*Dk);
        #pragma unroll
        for (int i = 0; i < 4; i++) {
            float4 v = qp[i];
            q[i*4+0]=v.x; q[i*4+1]=v.y; q[i*4+2]=v.z; q[i*4+3]=v.w;
        }
        if (n < Nn) { cqx = coords[(b*Nn+n)*2]; cqy = coords[(b*Nn+n)*2+1]; }
        const float4* qep = (const float4*)(d_QE + (hb + n)*NBk);
        #pragma unroll
        for (int i = 0; i < 8; i++) {
            float4 v = qep[i];
            qes[tid][i*4+0]=v.x; qes[tid][i*4+1]=v.y;
            qes[tid][i*4+2]=v.z; qes[tid][i*4+3]=v.w;
        }
        rowadj = d_ADJ + (size_t)(b*N1 + n)*AW;
    }
    for (int kt = 0; kt < 9; kt++) {
        int m0 = kt*128;
        int tlen = N1 - m0; if (tlen > 128) tlen = 128;
        const float4* Kt = (const float4*)(d_Kb + (hb + m0)*Dk);
        const float4* Vt = (const float4*)(d_Vb + (hb + m0)*Dk);
        __syncthreads();
        #pragma unroll
        for (int i = 0; i < 4; i++) {
            int f = tid + i*128;          // float4 index within 128x16 tile
            int row = f >> 2, j = (f & 3)*4;
            if (row < tlen) {
                float4 kv = Kt[f];
                Ks[row][j+0]=kv.x; Ks[row][j+1]=kv.y; Ks[row][j+2]=kv.z; Ks[row][j+3]=kv.w;
                float4 vv = Vt[f];
                Vs[row][j+0]=vv.x; Vs[row][j+1]=vv.y; Vs[row][j+2]=vv.z; Vs[row][j+3]=vv.w;
            }
        }
        if (tid < tlen) {
            int m = m0 + tid;
            if (m < Nn) { ckx[tid] = coords[(b*Nn+m)*2]; cky[tid] = coords[(b*Nn+m)*2+1]; }
            else        { ckx[tid] = 0.f; cky[tid] = 0.f; }
        }
        __syncthreads();
        if (!qv) continue;
        int wb = m0 >> 5;
        unsigned w0 = rowadj[wb];
        unsigned w1 = (wb+1 < AW) ? rowadj[wb+1] : 0u;
        unsigned w2 = (wb+2 < AW) ? rowadj[wb+2] : 0u;
        unsigned w3 = (wb+3 < AW) ? rowadj[wb+3] : 0u;
        attn_word(w0,  0, q, cqx, cqy, Ks, Vs, ckx, cky, qes[tid], lrun, acc);
        attn_word(w1, 32, q, cqx, cqy, Ks, Vs, ckx, cky, qes[tid], lrun, acc);
        attn_word(w2, 64, q, cqx, cqy, Ks, Vs, ckx, cky, qes[tid], lrun, acc);
        attn_word(w3, 96, q, cqx, cqy, Ks, Vs, ckx, cky, qes[tid], lrun, acc);
    }
    if (qv) {
        float inv = 1.f / lrun;
        float* o = d_CTX + ((size_t)(b*N1 + n))*Dm + h*Dk;
        #pragma unroll
        for (int d = 0; d < 16; d++) o[d] = acc[d]*inv;
    }
}

// ------------------------- dense attention for rows {0, Nn} ------------------
// grid (2, Hh, Bsz), 128 threads. Raw-exp softmax over all 1025 keys.
__global__ void k_dense(const float* __restrict__ coords)
{
    __shared__ float qsh[16], qesh[32];
    __shared__ float pl[4], pa[4][16];
    int b = blockIdx.z, h = blockIdx.y;
    int n = blockIdx.x ? Nn : 0;
    int tid = threadIdx.x, lane = tid & 31, w = tid >> 5;
    const size_t hb = (size_t)(b*Hh + h)*N1;
    if (tid < 16) qsh[tid] = d_Q[(hb + n)*Dk + tid];
    if (tid >= 32 && tid < 64) qesh[tid-32] = d_QE[(hb + n)*NBk + (tid-32)];
    __syncthreads();
    float q[16];
    #pragma unroll
    for (int d = 0; d < 16; d++) q[d] = qsh[d];
    float cqx = 0.f, cqy = 0.f;
    if (n < Nn) { cqx = coords[(b*Nn+n)*2]; cqy = coords[(b*Nn+n)*2+1]; }
    float l = 0.f, acc[16];
    #pragma unroll
    for (int d = 0; d < 16; d++) acc[d] = 0.f;
    const float* Kt = d_Kb + hb*Dk;
    const float* Vt = d_Vb + hb*Dk;
    for (int mk = tid; mk < N1; mk += 128) {
        const float4* kp = (const float4*)(Kt + (size_t)mk*Dk);
        float s = 0.f;
        #pragma unroll
        for (int i = 0; i < 4; i++) {
            float4 kv = kp[i];
            s += q[i*4+0]*kv.x + q[i*4+1]*kv.y + q[i*4+2]*kv.z + q[i*4+3]*kv.w;
        }
        float cmx = 0.f, cmy = 0.f;
        if (mk < Nn) { cmx = coords[(b*Nn+mk)*2]; cmy = coords[(b*Nn+mk)*2+1]; }
        float dx = cqx - cmx, dy = cqy - cmy;
        float dist = sqrtf(dx*dx + dy*dy);
        int bk = (int)(dist * 32.f); if (bk > 31) bk = 31;
        float p = __expf(s*SCALEf + qesh[bk]);
        l += p;
        const float4* vp = (const float4*)(Vt + (size_t)mk*Dk);
        #pragma unroll
        for (int i = 0; i < 4; i++) {
            float4 vv = vp[i];
            acc[i*4+0] += p*vv.x; acc[i*4+1] += p*vv.y;
            acc[i*4+2] += p*vv.z; acc[i*4+3] += p*vv.w;
        }
    }
    #pragma unroll
    for (int o = 16; o; o >>= 1) {
        l += __shfl_xor_sync(0xffffffffu, l, o);
        #pragma unroll
        for (int d = 0; d < 16; d++) acc[d] += __shfl_xor_sync(0xffffffffu, acc[d], o);
    }
    if (lane == 0) {
        pl[w] = l;
        #pragma unroll
        for (int d = 0; d < 16; d++) pa[w][d] = acc[d];
    }
    __syncthreads();
    if (tid == 0) {
        float L = pl[0] + pl[1] + pl[2] + pl[3];
        float inv = 1.f / L;
        float* o = d_CTX + ((size_t)(b*N1 + n))*Dm + h*Dk;
        #pragma unroll
        for (int d = 0; d < 16; d++)
            o[d] = (pa[0][d] + pa[1][d] + pa[2][d] + pa[3][d]) * inv;
    }
}

// ------------------------- instance norm: stats (partials) -------------------
// grid (Bsz, NCH), 256 threads; chunk z covers rows [z*64, min(z*64+64, N1))
__global__ void k_istat(const float* __restrict__ src)
{
    __shared__ float s1[2][Dm], s2[2][Dm];
    int b = blockIdx.x, z = blockIdx.y;
    int d = threadIdx.x & 127, g = threadIdx.x >> 7;
    int nend = z*64 + 64; if (nend > N1) nend = N1;
    const float* p = src + (size_t)b*N1*Dm + d;
    float a = 0.f, qq = 0.f;
    for (int n = z*64 + g; n < nend; n += 2) {
        float x = p[(size_t)n*Dm];
        a += x; qq += x*x;
    }
    s1[g][d] = a; s2[g][d] = qq;
    __syncthreads();
    if (g == 0) {
        d_PS1[(b*NCH + z)*Dm + d] = s1[0][d] + s1[1][d];
        d_PS2[(b*NCH + z)*Dm + d] = s2[0][d] + s2[1][d];
    }
}

// ------------------------- instance norm: apply ------------------------------
// grid (Bsz, 4, 8), 1024 threads; z chunk rows [z*128, z==7 ? N1 : (z+1)*128)
// fuse=1: POOL += mean(out_h), out[g-row] += mean(out_h)
__global__ void k_iapply(const float* __restrict__ src, float* __restrict__ dst,
                         const float* __restrict__ w, const float* __restrict__ bb, int fuse)
{
    int b  = blockIdx.x;
    int dl = threadIdx.x & 31;
    int g  = threadIdx.x >> 5;
    int d  = blockIdx.y*32 + dl;
    int z  = blockIdx.z;
    float S1 = 0.f, S2 = 0.f;
    #pragma unroll
    for (int t = 0; t < NCH; t++) {
        S1 += d_PS1[(b*NCH + t)*Dm + d];
        S2 += d_PS2[(b*NCH + t)*Dm + d];
    }
    float mu  = S1 * (1.f/N1);
    float var = S2 * (1.f/N1) - mu*mu;
    float sc  = rsqrtf(var + EPSf) * w[d];
    float sh  = bb[d];
    const float* p = src + (size_t)b*N1*Dm + d;
    float* o = dst + (size_t)b*N1*Dm + d;
    float mo = 0.f;
    if (fuse) mo = ((S1 - p[(size_t)Nn*Dm])*(1.f/Nn) - mu)*sc + sh;
    int n0 = z*128, n1 = (z == 7) ? N1 : (z+1)*128;
    for (int n = n0 + g; n < n1; n += 32) {
        float val = (p[(size_t)n*Dm] - mu)*sc + sh;
        if (fuse && n == Nn) val += mo;
        o[(size_t)n*Dm] = val;
    }
    if (fuse && z == 7 && g == 0) d_POOL[b*Dm + d] += mo;
}

// ------------------------- final prep: X = h + p_multi; write p_multi --------
__global__ void k_final(float* __restrict__ out)
{
    int gid = blockIdx.x*blockDim.x + threadIdx.x;
    if (gid < Bsz*Dm) out[Bsz*Nn*Dm + gid] = d_POOL[gid] * (1.f/3.f);
    if (gid >= Bsz*Nn*Dm) return;
    int d = gid & 127;
    int n = (gid >> 7) & 1023;
    int b = gid >> 17;
    d_X[gid] = d_HG[((size_t)b*N1 + n)*Dm + d] + d_POOL[b*Dm + d]*(1.f/3.f);
}

// ------------------------- host driver ---------------------------------------
extern "C" void kernel_launch(void* const* d_in, const int* in_sizes, int n_in,
                              void* d_out, int out_size)
{
    const float* coords = (const float*)d_in[0];
    const float* in_W   = (const float*)d_in[1];
    const float* in_b   = (const float*)d_in[2];
    const float* gnode  = (const float*)d_in[3];
    const float* Wq     = (const float*)d_in[4];
    const float* Wk     = (const float*)d_in[5];
    const float* Wv     = (const float*)d_in[6];
    const float* Wo     = (const float*)d_in[7];
    const float* emb    = (const float*)d_in[8];
    const float* W1     = (const float*)d_in[9];
    const float* b1     = (const float*)d_in[10];
    const float* W2     = (const float*)d_in[11];
    const float* b2     = (const float*)d_in[12];
    const float* n1w    = (const float*)d_in[13];
    const float* n1b    = (const float*)d_in[14];
    const float* n2w    = (const float*)d_in[15];
    const float* n2b    = (const float*)d_in[16];
    const float* outW   = (const float*)d_in[17];
    const float* outb   = (const float*)d_in[18];
    float* out = (float*)d_out;

    float *HG, *CTX, *Y, *T1, *T2, *X;
    cudaGetSymbolAddress((void**)&HG,  d_HG);
    cudaGetSymbolAddress((void**)&CTX, d_CTX);
    cudaGetSymbolAddress((void**)&Y,   d_Y);
    cudaGetSymbolAddress((void**)&T1,  d_T1);
    cudaGetSymbolAddress((void**)&T2,  d_T2);
    cudaGetSymbolAddress((void**)&X,   d_X);

    const int Mall = Bsz*N1;  // 2050

    k_input<<<(Bsz*N1*Dm + 255)/256, 256>>>(coords, in_W, in_b, gnode);
    k_colmean<<<Bsz, 1024>>>();                            // layer-0 g update

    for (int l = 0; l < 3; l++) {
        k_prol<<<Bsz*N1, 64>>>();
        { dim3 g(Nn/128, Nn/128, Bsz); k_d2<<<g, 256>>>(); }
        k_topk<<<(Bsz*Nn)/8, 256>>>();

        { dim3 gqkv(6, (Mall + 63)/64);
          k_qkv<<<gqkv, 256>>>(HG, Wq + (size_t)l*Dm*Dm, Wk + (size_t)l*Dm*Dm, Wv + (size_t)l*Dm*Dm); }
        k_qe<<<Mall, 256>>>(emb + (size_t)l*NBk*Dm);
        { dim3 ga(9, Hh, Bsz); k_attn<<<ga, 128>>>(coords); }
        { dim3 gd(2, Hh, Bsz); k_dense<<<gd, 128>>>(coords); }

        dim3 gq(Dm/64, (Mall + 63)/64);
        k_gemm<<<gq, 256>>>(CTX, Wo + (size_t)l*Dm*Dm, nullptr, HG, Y, Mall, Dm, Dm, 2);
        { dim3 gs(Bsz, NCH); k_istat<<<gs, 256>>>(Y); }
        { dim3 gi(Bsz, 4, 8); k_iapply<<<gi, 1024>>>(Y, Y, n1w + l*Dm, n1b + l*Dm, 0); }

        dim3 g1(Dff/64, (Mall + 63)/64);
        k_gemm<<<g1, 256>>>(Y,  W1 + (size_t)l*Dff*Dm, b1 + l*Dff, nullptr, T1, Mall, Dff, Dm, 1|4);
        k_gemm<<<gq, 256>>>(T1, W2 + (size_t)l*Dm*Dff, b2 + l*Dm,  Y,      T2, Mall, Dm, Dff, 1|2);
        { dim3 gs(Bsz, NCH); k_istat<<<gs, 256>>>(T2); }
        { dim3 gi(Bsz, 4, 8); k_iapply<<<gi, 1024>>>(T2, HG, n2w + l*Dm, n2b + l*Dm, 1); }
    }

    k_final<<<(Bsz*Nn*Dm + 255)/256, 256>>>(out);
    { dim3 ge(Dm/64, (Bsz*Nn + 63)/64);
      k_gemm<<<ge, 256>>>(X, outW, outb, nullptr, out, Bsz*Nn, Dm, Dm, 1); }
}

// round 6
// speedup vs baseline: 3.9621x; 1.1643x over previous
#include <cuda_runtime.h>
#include <math_constants.h>
#include <math.h>

#define Bsz 2
#define Nn 1024
#define N1 1025
#define Dm 128
#define Hh 8
#define Dk 16
#define Dff 512
#define NBk 32
#define KNN 10
#define AW 33          // 33 x 32-bit words cover 1025 mask bits per row
#define EPSf 1e-5f
#define SCALEf 0.25f   // 1/sqrt(16)
#define NCH 17         // inorm stat chunks

// ------------------------- persistent device scratch -------------------------
__device__ float    d_HG [Bsz*N1*Dm];     // state: rows 0..1023 = h, row 1024 = g
__device__ float    d_POOL[Bsz*Dm];
__device__ float    d_SQ [Bsz*Nn];
__device__ float    d_D2 [(size_t)Bsz*Nn*Nn];
__device__ unsigned d_ADJ[Bsz*N1*AW];
__device__ float    d_Q  [Bsz*Hh*N1*Dk];  // head-major: [b][h][n][dk]
__device__ float    d_Kb [Bsz*Hh*N1*Dk];
__device__ float    d_Vb [Bsz*Hh*N1*Dk];
__device__ float    d_CTX[Bsz*N1*Dm];
__device__ float    d_QE [Bsz*Hh*N1*NBk]; // head-major: [b][h][n][bucket]
__device__ float    d_Y  [Bsz*N1*Dm];
__device__ float    d_T1 [Bsz*N1*Dff];
__device__ float    d_T2 [Bsz*N1*Dm];
__device__ float    d_X  [Bsz*Nn*Dm];
__device__ float    d_PS1[Bsz*NCH*Dm];
__device__ float    d_PS2[Bsz*NCH*Dm];
__device__ float    d_PA [3*Bsz*N1*Hh*17];  // split-K partials: acc[16]+lrun

// ------------------------- input embedding + state init ----------------------
__global__ void k_input(const float* __restrict__ coords, const float* __restrict__ inW,
                        const float* __restrict__ inb, const float* __restrict__ gnode)
{
    int gid = blockIdx.x*blockDim.x + threadIdx.x;
    if (gid < Bsz*Dm) d_POOL[gid] = 0.f;
    if (gid >= Bsz*N1*Dm) return;
    int d = gid % Dm;
    int n = (gid / Dm) % N1;
    int b = gid / (Dm*N1);
    float v;
    if (n < Nn) {
        float x = coords[(b*Nn+n)*2+0];
        float y = coords[(b*Nn+n)*2+1];
        v = x*inW[d*2+0] + y*inW[d*2+1] + inb[d];
    } else {
        v = gnode[d];
    }
    d_HG[gid] = v;
}

// ------------------------- layer-0 g update: g += mean(h) --------------------
__global__ void k_colmean()
{
    __shared__ float red[8][Dm];
    int b = blockIdx.x;
    int d = threadIdx.x & 127;
    int g = threadIdx.x >> 7;
    const float* base = d_HG + (size_t)b*N1*Dm;
    float s = 0.f;
    for (int n = g; n < Nn; n += 8) s += base[n*Dm + d];
    red[g][d] = s;
    __syncthreads();
    if (g == 0) {
        float t = 0.f;
        #pragma unroll
        for (int i = 0; i < 8; i++) t += red[i][d];
        d_HG[(size_t)b*N1*Dm + Nn*Dm + d] += t * (1.f/Nn);
    }
}

// ------------------------- prologue: adjacency base + sq norms ---------------
__global__ void k_prol()
{
    int row = blockIdx.x;              // b*N1 + i
    int i   = row % N1;
    int b   = row / N1;
    int tid = threadIdx.x;
    if (tid < AW) {
        int w = tid;
        unsigned bits = 0u;
        #pragma unroll 4
        for (int t = 0; t < 32; t++) {
            int m = w*32 + t;
            if (m > Nn) break;
            bool on;
            if (i == Nn || m == Nn || i == m || i == 0 || m == 0) on = true;
            else {
                int di = i - m; if (di < 0) di = -di;
                on = ((i >> 7) == (m >> 7)) && (di <= 11);   // hier adjacency
            }
            if (on) bits |= 1u << t;
        }
        d_ADJ[row*AW + w] = bits;
    }
    if (tid >= 32 && i < Nn) {         // warp 1: squared norm
        int lane = tid - 32;
        const float* p = d_HG + (size_t)row*Dm;
        float s = 0.f;
        #pragma unroll
        for (int t = 0; t < 4; t++) { float v = p[lane + t*32]; s += v*v; }
        #pragma unroll
        for (int o = 16; o; o >>= 1) s += __shfl_xor_sync(0xffffffffu, s, o);
        if (!lane) d_SQ[b*Nn + i] = s;
    }
}

// ------------------------- D2 matrix (64x64 tile, 4x4/thread) ----------------
__global__ void k_d2()
{
    __shared__ float As[16][68];
    __shared__ float Bs[16][68];
    int b = blockIdx.z;
    const float* A = d_HG + (size_t)b*N1*Dm;
    int tid = threadIdx.x;
    int tr = tid >> 4, tc = tid & 15;
    int r0 = blockIdx.y*64, c0 = blockIdx.x*64;
    int lr = tid >> 2;
    int lc = (tid & 3) * 4;
    float acc[4][4] = {};
    for (int k0 = 0; k0 < Dm; k0 += 16) {
        float4 va = *(const float4*)(A + (size_t)(r0+lr)*Dm + k0 + lc);
        float4 vb = *(const float4*)(A + (size_t)(c0+lr)*Dm + k0 + lc);
        As[lc+0][lr] = va.x; As[lc+1][lr] = va.y; As[lc+2][lr] = va.z; As[lc+3][lr] = va.w;
        Bs[lc+0][lr] = vb.x; Bs[lc+1][lr] = vb.y; Bs[lc+2][lr] = vb.z; Bs[lc+3][lr] = vb.w;
        __syncthreads();
        #pragma unroll
        for (int k = 0; k < 16; k++) {
            float4 a4 = *(const float4*)&As[k][tr*4];
            float4 b4 = *(const float4*)&Bs[k][tc*4];
            float a[4] = {a4.x, a4.y, a4.z, a4.w};
            float bv[4] = {b4.x, b4.y, b4.z, b4.w};
            #pragma unroll
            for (int i = 0; i < 4; i++)
                #pragma unroll
                for (int j = 0; j < 4; j++) acc[i][j] += a[i]*bv[j];
        }
        __syncthreads();
    }
    #pragma unroll
    for (int i = 0; i < 4; i++) {
        int r = r0 + tr*4 + i;
        float sqr = d_SQ[b*Nn + r];
        #pragma unroll
        for (int j = 0; j < 4; j++) {
            int c = c0 + tc*4 + j;
            float v = sqr + d_SQ[b*Nn + c] - 2.f*acc[i][j];
            if (r == c) v = CUDART_INF_F;
            d_D2[((size_t)b*Nn + r)*Nn + c] = v;
        }
    }
}

// ------------------------- exact top-10 kNN -> adjacency bits ----------------
__global__ void k_topk()
{
    int warp = (blockIdx.x*blockDim.x + threadIdx.x) >> 5;
    int lane = threadIdx.x & 31;
    if (warp >= Bsz*Nn) return;
    int b = warp >> 10, i = warp & 1023;
    const float* row = d_D2 + (size_t)warp*Nn;
    float vals[32];
    #pragma unroll
    for (int t = 0; t < 32; t++) vals[t] = row[t*32 + lane];
    unsigned used = 0u;
    unsigned* adjb = d_ADJ + (size_t)b*N1*AW;
    for (int r = 0; r < KNN; r++) {
        float bv = CUDART_INF_F; int bj = 1 << 30;
        #pragma unroll
        for (int t = 0; t < 32; t++) {
            if (!((used >> t) & 1u)) {
                float v = vals[t]; int j = t*32 + lane;
                if (v < bv || (v == bv && j < bj)) { bv = v; bj = j; }
            }
        }
        #pragma unroll
        for (int o = 16; o; o >>= 1) {
            float ov = __shfl_xor_sync(0xffffffffu, bv, o);
            int   oj = __shfl_xor_sync(0xffffffffu, bj, o);
            if (ov < bv || (ov == bv && oj < bj)) { bv = ov; bj = oj; }
        }
        if (lane == (bj & 31)) used |= 1u << (bj >> 5);
        if (lane == 0) {
            atomicOr(&adjb[i*AW + (bj >> 5)], 1u << (bj & 31));
            atomicOr(&adjb[bj*AW + (i >> 5)], 1u << (i & 31));
        }
    }
}

// ------------------------- generic SGEMM: C = A[M,K] * W[N,K]^T --------------
__global__ void k_gemm(const float* __restrict__ A, const float* __restrict__ Bm,
                       const float* __restrict__ bias, const float* __restrict__ res,
                       float* __restrict__ C, int M, int Nc, int K, int flags)
{
    __shared__ float As[16][68];
    __shared__ float Bs[16][68];
    int tid = threadIdx.x;
    int tr = tid >> 4, tc = tid & 15;
    int r0 = blockIdx.y*64, c0 = blockIdx.x*64;
    int lr = tid >> 2;
    int lc = (tid & 3) * 4;
    float acc[4][4] = {};
    for (int k0 = 0; k0 < K; k0 += 16) {
        int gr = r0 + lr;
        float4 va = (gr < M) ? *(const float4*)(A + (size_t)gr*K + k0 + lc)
                             : make_float4(0.f,0.f,0.f,0.f);
        float4 vb = *(const float4*)(Bm + (size_t)(c0+lr)*K + k0 + lc);
        As[lc+0][lr] = va.x; As[lc+1][lr] = va.y; As[lc+2][lr] = va.z; As[lc+3][lr] = va.w;
        Bs[lc+0][lr] = vb.x; Bs[lc+1][lr] = vb.y; Bs[lc+2][lr] = vb.z; Bs[lc+3][lr] = vb.w;
        __syncthreads();
        #pragma unroll
        for (int k = 0; k < 16; k++) {
            float4 a4 = *(const float4*)&As[k][tr*4];
            float4 b4 = *(const float4*)&Bs[k][tc*4];
            float a[4] = {a4.x, a4.y, a4.z, a4.w};
            float bv[4] = {b4.x, b4.y, b4.z, b4.w};
            #pragma unroll
            for (int i = 0; i < 4; i++)
                #pragma unroll
                for (int j = 0; j < 4; j++) acc[i][j] += a[i]*bv[j];
        }
        __syncthreads();
    }
    int c = c0 + tc*4;
    float4 bz = make_float4(0.f,0.f,0.f,0.f);
    if (flags & 1) bz = *(const float4*)(bias + c);
    #pragma unroll
    for (int i = 0; i < 4; i++) {
        int r = r0 + tr*4 + i;
        if (r >= M) continue;
        float4 v = make_float4(acc[i][0]+bz.x, acc[i][1]+bz.y, acc[i][2]+bz.z, acc[i][3]+bz.w);
        if (flags & 2) {
            float4 rv = *(const float4*)(res + (size_t)r*Nc + c);
            v.x += rv.x; v.y += rv.y; v.z += rv.z; v.w += rv.w;
        }
        if (flags & 4) {
            v.x = fmaxf(v.x, 0.f); v.y = fmaxf(v.y, 0.f);
            v.z = fmaxf(v.z, 0.f); v.w = fmaxf(v.w, 0.f);
        }
        *(float4*)(C + (size_t)r*Nc + c) = v;
    }
}

// ------------------------- fused QKV GEMM -> head-major outputs --------------
__global__ void k_qkv(const float* __restrict__ A, const float* __restrict__ wq,
                      const float* __restrict__ wk, const float* __restrict__ wv)
{
    __shared__ float As[16][68];
    __shared__ float Bs[16][68];
    int sel = blockIdx.x >> 1;
    const float* Bm = (sel == 0) ? wq : (sel == 1) ? wk : wv;
    float* C = (sel == 0) ? d_Q : (sel == 1) ? d_Kb : d_Vb;
    const int M = Bsz*N1;
    int tid = threadIdx.x;
    int tr = tid >> 4, tc = tid & 15;
    int r0 = blockIdx.y*64, c0 = (blockIdx.x & 1)*64;
    int lr = tid >> 2;
    int lc = (tid & 3) * 4;
    float acc[4][4] = {};
    for (int k0 = 0; k0 < Dm; k0 += 16) {
        int gr = r0 + lr;
        float4 va = (gr < M) ? *(const float4*)(A + (size_t)gr*Dm + k0 + lc)
                             : make_float4(0.f,0.f,0.f,0.f);
        float4 vb = *(const float4*)(Bm + (size_t)(c0+lr)*Dm + k0 + lc);
        As[lc+0][lr] = va.x; As[lc+1][lr] = va.y; As[lc+2][lr] = va.z; As[lc+3][lr] = va.w;
        Bs[lc+0][lr] = vb.x; Bs[lc+1][lr] = vb.y; Bs[lc+2][lr] = vb.z; Bs[lc+3][lr] = vb.w;
        __syncthreads();
        #pragma unroll
        for (int k = 0; k < 16; k++) {
            float4 a4 = *(const float4*)&As[k][tr*4];
            float4 b4 = *(const float4*)&Bs[k][tc*4];
            float a[4] = {a4.x, a4.y, a4.z, a4.w};
            float bv[4] = {b4.x, b4.y, b4.z, b4.w};
            #pragma unroll
            for (int i = 0; i < 4; i++)
                #pragma unroll
                for (int j = 0; j < 4; j++) acc[i][j] += a[i]*bv[j];
        }
        __syncthreads();
    }
    int c = c0 + tc*4;
    int h  = c >> 4;
    int dk = c & 15;
    #pragma unroll
    for (int i = 0; i < 4; i++) {
        int r = r0 + tr*4 + i;
        if (r >= M) continue;
        int bb = (r >= N1) ? 1 : 0;
        int n  = r - bb*N1;
        *(float4*)(C + ((size_t)(bb*Hh + h)*N1 + n)*Dk + dk) =
            make_float4(acc[i][0], acc[i][1], acc[i][2], acc[i][3]);
    }
}

// ------------------------- qe = Q . emb per (head,bucket), head-major --------
__global__ void k_qe(const float* __restrict__ emb)
{
    __shared__ float qs[Dm];
    int row = blockIdx.x;              // b*N1 + n
    int b = (row >= N1) ? 1 : 0;
    int n = row - b*N1;
    int tid = threadIdx.x;
    if (tid < Dm) {
        int hh = tid >> 4, dk = tid & 15;
        qs[tid] = d_Q[((size_t)(b*Hh + hh)*N1 + n)*Dk + dk];
    }
    __syncthreads();
    int h = tid >> 5, kb = tid & 31;
    const float* e = emb + kb*Dm + h*Dk;
    const float* q = qs + h*Dk;
    float s = 0.f;
    #pragma unroll
    for (int dd = 0; dd < Dk; dd++) s += q[dd]*e[dd];
    d_QE[((size_t)(b*Hh + h)*N1 + n)*NBk + kb] = s;
}

// ------------------------- sparse attention, split-K + fused dense -----------
__device__ __forceinline__ void attn_word20(unsigned word, int base,
    const float4 q4[4], float cqx, float cqy,
    const float (*Ks)[20], const float (*Vs)[20],
    const float* ckx, const float* cky, const float* qerow,
    float& lrun, float acc[16])
{
    while (word) {
        int mm = base + (__ffs((int)word) - 1);
        word &= word - 1u;
        const float4* kp = (const float4*)Ks[mm];
        float4 k0 = kp[0], k1 = kp[1], k2 = kp[2], k3 = kp[3];
        float s = q4[0].x*k0.x + q4[0].y*k0.y + q4[0].z*k0.z + q4[0].w*k0.w
                + q4[1].x*k1.x + q4[1].y*k1.y + q4[1].z*k1.z + q4[1].w*k1.w
                + q4[2].x*k2.x + q4[2].y*k2.y + q4[2].z*k2.z + q4[2].w*k2.w
                + q4[3].x*k3.x + q4[3].y*k3.y + q4[3].z*k3.z + q4[3].w*k3.w;
        float dx = cqx - ckx[mm], dy = cqy - cky[mm];
        float dist = sqrtf(dx*dx + dy*dy);
        int bk = (int)(dist * 32.f); if (bk > 31) bk = 31;
        float p = __expf(s*SCALEf + qerow[bk]);
        lrun += p;
        const float4* vp = (const float4*)Vs[mm];
        float4 v0 = vp[0], v1 = vp[1], v2 = vp[2], v3 = vp[3];
        acc[ 0] += p*v0.x; acc[ 1] += p*v0.y; acc[ 2] += p*v0.z; acc[ 3] += p*v0.w;
        acc[ 4] += p*v1.x; acc[ 5] += p*v1.y; acc[ 6] += p*v1.z; acc[ 7] += p*v1.w;
        acc[ 8] += p*v2.x; acc[ 9] += p*v2.y; acc[10] += p*v2.z; acc[11] += p*v2.w;
        acc[12] += p*v3.x; acc[13] += p*v3.y; acc[14] += p*v3.z; acc[15] += p*v3.w;
    }
}

// grid (25, Hh, Bsz), 128 threads. x<24: sparse (qtile=x/3, kseg=x%3).
// x==24: dense rows {0, Nn} (64 threads each).
__global__ void k_attn(const float* __restrict__ coords)
{
    __shared__ float Ks[128][20];
    __shared__ float Vs[128][20];
    __shared__ float ckx[128], cky[128];
    __shared__ float qes[128][33];
    __shared__ float pw[4][17];
    int b = blockIdx.z, h = blockIdx.y;
    int x = blockIdx.x;
    int tid = threadIdx.x;
    const size_t hb = (size_t)(b*Hh + h)*N1;

    if (x == 24) {   // ---- dense rows ----
        int sub = tid >> 6, st = tid & 63;
        int lane = tid & 31, w = tid >> 5;
        int n = sub ? Nn : 0;
        float q[16];
        const float4* qp = (const float4*)(d_Q + (hb + n)*Dk);
        #pragma unroll
        for (int i = 0; i < 4; i++) {
            float4 v = qp[i];
            q[i*4+0]=v.x; q[i*4+1]=v.y; q[i*4+2]=v.z; q[i*4+3]=v.w;
        }
        float cqx = 0.f, cqy = 0.f;
        if (n < Nn) { cqx = coords[(b*Nn+n)*2]; cqy = coords[(b*Nn+n)*2+1]; }
        const float* qerow = d_QE + (hb + n)*NBk;
        float l = 0.f, acc[16];
        #pragma unroll
        for (int d = 0; d < 16; d++) acc[d] = 0.f;
        const float* Kt = d_Kb + hb*Dk;
        const float* Vt = d_Vb + hb*Dk;
        for (int mk = st; mk < N1; mk += 64) {
            const float4* kp = (const float4*)(Kt + (size_t)mk*Dk);
            float s = 0.f;
            #pragma unroll
            for (int i = 0; i < 4; i++) {
                float4 kv = kp[i];
                s += q[i*4+0]*kv.x + q[i*4+1]*kv.y + q[i*4+2]*kv.z + q[i*4+3]*kv.w;
            }
            float cmx = 0.f, cmy = 0.f;
            if (mk < Nn) { cmx = coords[(b*Nn+mk)*2]; cmy = coords[(b*Nn+mk)*2+1]; }
            float dx = cqx - cmx, dy = cqy - cmy;
            float dist = sqrtf(dx*dx + dy*dy);
            int bk = (int)(dist * 32.f); if (bk > 31) bk = 31;
            float p = __expf(s*SCALEf + qerow[bk]);
            l += p;
            const float4* vp = (const float4*)(Vt + (size_t)mk*Dk);
            #pragma unroll
            for (int i = 0; i < 4; i++) {
                float4 vv = vp[i];
                acc[i*4+0] += p*vv.x; acc[i*4+1] += p*vv.y;
                acc[i*4+2] += p*vv.z; acc[i*4+3] += p*vv.w;
            }
        }
        #pragma unroll
        for (int o = 16; o; o >>= 1) {
            l += __shfl_xor_sync(0xffffffffu, l, o);
            #pragma unroll
            for (int d = 0; d < 16; d++) acc[d] += __shfl_xor_sync(0xffffffffu, acc[d], o);
        }
        if (lane == 0) {
            #pragma unroll
            for (int d = 0; d < 16; d++) pw[w][d] = acc[d];
            pw[w][16] = l;
        }
        __syncthreads();
        if (tid == 0 || tid == 64) {
            int w0 = sub*2;
            float L = pw[w0][16] + pw[w0+1][16];
            float inv = 1.f / L;
            float* o = d_CTX + ((size_t)(b*N1 + n))*Dm + h*Dk;
            #pragma unroll
            for (int d = 0; d < 16; d++) o[d] = (pw[w0][d] + pw[w0+1][d]) * inv;
        }
        return;
    }

    // ---- sparse split-K ----
    int qt = x / 3, kseg = x % 3;
    int n = qt*128 + tid;              // 0..1023
    bool qv = (n != 0);                // n<1024 always; row 0 is dense
    float4 q4[4];
    float cqx = 0.f, cqy = 0.f, lrun = 0.f;
    float acc[16];
    #pragma unroll
    for (int d = 0; d < 16; d++) acc[d] = 0.f;
    const unsigned* rowadj = d_ADJ + (size_t)(b*N1 + n)*AW;
    {
        const float4* qp = (const float4*)(d_Q + (hb + n)*Dk);
        #pragma unroll
        for (int i = 0; i < 4; i++) q4[i] = qp[i];
        cqx = coords[(b*Nn+n)*2]; cqy = coords[(b*Nn+n)*2+1];
        const float4* qep = (const float4*)(d_QE + (hb + n)*NBk);
        #pragma unroll
        for (int i = 0; i < 8; i++) {
            float4 v = qep[i];
            qes[tid][i*4+0]=v.x; qes[tid][i*4+1]=v.y;
            qes[tid][i*4+2]=v.z; qes[tid][i*4+3]=v.w;
        }
    }
    for (int kt = kseg*3; kt < kseg*3 + 3; kt++) {
        int m0 = kt*128;
        int tlen = N1 - m0; if (tlen > 128) tlen = 128;
        const float4* Kt = (const float4*)(d_Kb + (hb + m0)*Dk);
        const float4* Vt = (const float4*)(d_Vb + (hb + m0)*Dk);
        __syncthreads();
        #pragma unroll
        for (int i = 0; i < 4; i++) {
            int f = tid + i*128;
            int row = f >> 2, j = (f & 3)*4;
            if (row < tlen) {
                *(float4*)&Ks[row][j] = Kt[f];
                *(float4*)&Vs[row][j] = Vt[f];
            }
        }
        if (tid < tlen) {
            int m = m0 + tid;
            if (m < Nn) { ckx[tid] = coords[(b*Nn+m)*2]; cky[tid] = coords[(b*Nn+m)*2+1]; }
            else        { ckx[tid] = 0.f; cky[tid] = 0.f; }
        }
        __syncthreads();
        if (!qv) continue;
        int wb = m0 >> 5;
        unsigned w0 = rowadj[wb];
        unsigned w1 = (wb+1 < AW) ? rowadj[wb+1] : 0u;
        unsigned w2 = (wb+2 < AW) ? rowadj[wb+2] : 0u;
        unsigned w3 = (wb+3 < AW) ? rowadj[wb+3] : 0u;
        attn_word20(w0,  0, q4, cqx, cqy, Ks, Vs, ckx, cky, qes[tid], lrun, acc);
        attn_word20(w1, 32, q4, cqx, cqy, Ks, Vs, ckx, cky, qes[tid], lrun, acc);
        attn_word20(w2, 64, q4, cqx, cqy, Ks, Vs, ckx, cky, qes[tid], lrun, acc);
        attn_word20(w3, 96, q4, cqx, cqy, Ks, Vs, ckx, cky, qes[tid], lrun, acc);
    }
    if (qv) {
        size_t base = ((size_t)kseg*Bsz*N1 + (size_t)b*N1 + n)*Hh + h;
        float* pa = d_PA + base*17;
        #pragma unroll
        for (int d = 0; d < 16; d++) pa[d] = acc[d];
        pa[16] = lrun;
    }
}

// ------------------------- combine split-K partials --------------------------
__global__ void k_comb()
{
    int u = blockIdx.x*blockDim.x + threadIdx.x;   // (b*N1+n)*Hh + h
    if (u >= Bsz*N1*Hh) return;
    int h = u & 7;
    int r = u >> 3;
    int n = (r >= N1) ? r - N1 : r;
    if (n == 0 || n == Nn) return;                  // dense rows written directly
    const int ST = Bsz*N1*Hh*17;
    int base = u*17;
    float l = d_PA[base+16] + d_PA[ST+base+16] + d_PA[2*ST+base+16];
    float inv = 1.f / l;
    float* o = d_CTX + (size_t)r*Dm + h*Dk;
    #pragma unroll
    for (int d = 0; d < 16; d++)
        o[d] = (d_PA[base+d] + d_PA[ST+base+d] + d_PA[2*ST+base+d]) * inv;
}

// ------------------------- instance norm: stats (partials) -------------------
__global__ void k_istat(const float* __restrict__ src)
{
    __shared__ float s1[2][Dm], s2[2][Dm];
    int b = blockIdx.x, z = blockIdx.y;
    int d = threadIdx.x & 127, g = threadIdx.x >> 7;
    int nend = z*64 + 64; if (nend > N1) nend = N1;
    const float* p = src + (size_t)b*N1*Dm + d;
    float a = 0.f, qq = 0.f;
    for (int n = z*64 + g; n < nend; n += 2) {
        float x = p[(size_t)n*Dm];
        a += x; qq += x*x;
    }
    s1[g][d] = a; s2[g][d] = qq;
    __syncthreads();
    if (g == 0) {
        d_PS1[(b*NCH + z)*Dm + d] = s1[0][d] + s1[1][d];
        d_PS2[(b*NCH + z)*Dm + d] = s2[0][d] + s2[1][d];
    }
}

// ------------------------- instance norm: apply ------------------------------
__global__ void k_iapply(const float* __restrict__ src, float* __restrict__ dst,
                         const float* __restrict__ w, const float* __restrict__ bb, int fuse)
{
    int b  = blockIdx.x;
    int dl = threadIdx.x & 31;
    int g  = threadIdx.x >> 5;
    int d  = blockIdx.y*32 + dl;
    int z  = blockIdx.z;
    float S1 = 0.f, S2 = 0.f;
    #pragma unroll
    for (int t = 0; t < NCH; t++) {
        S1 += d_PS1[(b*NCH + t)*Dm + d];
        S2 += d_PS2[(b*NCH + t)*Dm + d];
    }
    float mu  = S1 * (1.f/N1);
    float var = S2 * (1.f/N1) - mu*mu;
    float sc  = rsqrtf(var + EPSf) * w[d];
    float sh  = bb[d];
    const float* p = src + (size_t)b*N1*Dm + d;
    float* o = dst + (size_t)b*N1*Dm + d;
    float mo = 0.f;
    if (fuse) mo = ((S1 - p[(size_t)Nn*Dm])*(1.f/Nn) - mu)*sc + sh;
    int n0 = z*128, n1 = (z == 7) ? N1 : (z+1)*128;
    for (int n = n0 + g; n < n1; n += 32) {
        float val = (p[(size_t)n*Dm] - mu)*sc + sh;
        if (fuse && n == Nn) val += mo;
        o[(size_t)n*Dm] = val;
    }
    if (fuse && z == 7 && g == 0) d_POOL[b*Dm + d] += mo;
}

// ------------------------- final prep: X = h + p_multi; write p_multi --------
__global__ void k_final(float* __restrict__ out)
{
    int gid = blockIdx.x*blockDim.x + threadIdx.x;
    if (gid < Bsz*Dm) out[Bsz*Nn*Dm + gid] = d_POOL[gid] * (1.f/3.f);
    if (gid >= Bsz*Nn*Dm) return;
    int d = gid & 127;
    int n = (gid >> 7) & 1023;
    int b = gid >> 17;
    d_X[gid] = d_HG[((size_t)b*N1 + n)*Dm + d] + d_POOL[b*Dm + d]*(1.f/3.f);
}

// ------------------------- host driver ---------------------------------------
extern "C" void kernel_launch(void* const* d_in, const int* in_sizes, int n_in,
                              void* d_out, int out_size)
{
    const float* coords = (const float*)d_in[0];
    const float* in_W   = (const float*)d_in[1];
    const float* in_b   = (const float*)d_in[2];
    const float* gnode  = (const float*)d_in[3];
    const float* Wq     = (const float*)d_in[4];
    const float* Wk     = (const float*)d_in[5];
    const float* Wv     = (const float*)d_in[6];
    const float* Wo     = (const float*)d_in[7];
    const float* emb    = (const float*)d_in[8];
    const float* W1     = (const float*)d_in[9];
    const float* b1     = (const float*)d_in[10];
    const float* W2     = (const float*)d_in[11];
    const float* b2     = (const float*)d_in[12];
    const float* n1w    = (const float*)d_in[13];
    const float* n1b    = (const float*)d_in[14];
    const float* n2w    = (const float*)d_in[15];
    const float* n2b    = (const float*)d_in[16];
    const float* outW   = (const float*)d_in[17];
    const float* outb   = (const float*)d_in[18];
    float* out = (float*)d_out;

    float *HG, *CTX, *Y, *T1, *T2, *X;
    cudaGetSymbolAddress((void**)&HG,  d_HG);
    cudaGetSymbolAddress((void**)&CTX, d_CTX);
    cudaGetSymbolAddress((void**)&Y,   d_Y);
    cudaGetSymbolAddress((void**)&T1,  d_T1);
    cudaGetSymbolAddress((void**)&T2,  d_T2);
    cudaGetSymbolAddress((void**)&X,   d_X);

    const int Mall = Bsz*N1;  // 2050

    k_input<<<(Bsz*N1*Dm + 255)/256, 256>>>(coords, in_W, in_b, gnode);
    k_colmean<<<Bsz, 1024>>>();                            // layer-0 g update

    for (int l = 0; l < 3; l++) {
        k_prol<<<Bsz*N1, 64>>>();
        { dim3 g(Nn/64, Nn/64, Bsz); k_d2<<<g, 256>>>(); }
        k_topk<<<(Bsz*Nn)/8, 256>>>();

        { dim3 gqkv(6, (Mall + 63)/64);
          k_qkv<<<gqkv, 256>>>(HG, Wq + (size_t)l*Dm*Dm, Wk + (size_t)l*Dm*Dm, Wv + (size_t)l*Dm*Dm); }
        k_qe<<<Mall, 256>>>(emb + (size_t)l*NBk*Dm);
        { dim3 ga(25, Hh, Bsz); k_attn<<<ga, 128>>>(coords); }
        k_comb<<<(Bsz*N1*Hh + 127)/128, 128>>>();

        dim3 gq(Dm/64, (Mall + 63)/64);
        k_gemm<<<gq, 256>>>(CTX, Wo + (size_t)l*Dm*Dm, nullptr, HG, Y, Mall, Dm, Dm, 2);
        { dim3 gs(Bsz, NCH); k_istat<<<gs, 256>>>(Y); }
        { dim3 gi(Bsz, 4, 8); k_iapply<<<gi, 1024>>>(Y, Y, n1w + l*Dm, n1b + l*Dm, 0); }

        dim3 g1(Dff/64, (Mall + 63)/64);
        k_gemm<<<g1, 256>>>(Y,  W1 + (size_t)l*Dff*Dm, b1 + l*Dff, nullptr, T1, Mall, Dff, Dm, 1|4);
        k_gemm<<<gq, 256>>>(T1, W2 + (size_t)l*Dm*Dff, b2 + l*Dm,  Y,      T2, Mall, Dm, Dff, 1|2);
        { dim3 gs(Bsz, NCH); k_istat<<<gs, 256>>>(T2); }
        { dim3 gi(Bsz, 4, 8); k_iapply<<<gi, 1024>>>(T2, HG, n2w + l*Dm, n2b + l*Dm, 1); }
    }

    k_final<<<(Bsz*Nn*Dm + 255)/256, 256>>>(out);
    { dim3 ge(Dm/64, (Bsz*Nn + 63)/64);
      k_gemm<<<ge, 256>>>(X, outW, outb, nullptr, out, Bsz*Nn, Dm, Dm, 1); }
}

// round 7
// speedup vs baseline: 4.2880x; 1.0822x over previous
#include <cuda_runtime.h>
#include <math_constants.h>
#include <math.h>

#define Bsz 2
#define Nn 1024
#define N1 1025
#define Dm 128
#define Hh 8
#define Dk 16
#define Dff 512
#define NBk 32
#define KNN 10
#define AW 33          // 33 x 32-bit words cover 1025 mask bits per row
#define EPSf 1e-5f
#define SCALEf 0.25f   // 1/sqrt(16)
#define NCH 17         // inorm stat chunks

// ------------------------- persistent device scratch -------------------------
__device__ float    d_HG [Bsz*N1*Dm];     // state: rows 0..1023 = h, row 1024 = g
__device__ float    d_POOL[Bsz*Dm];
__device__ float    d_SQ [Bsz*Nn];
__device__ float    d_D2 [(size_t)Bsz*Nn*Nn];
__device__ unsigned d_ADJ[Bsz*N1*AW];
__device__ float    d_Q  [Bsz*Hh*N1*Dk];  // head-major: [b][h][n][dk]
__device__ float    d_Kb [Bsz*Hh*N1*Dk];
__device__ float    d_Vb [Bsz*Hh*N1*Dk];
__device__ float    d_CTX[Bsz*N1*Dm];
__device__ float    d_QE [Bsz*Hh*N1*NBk]; // head-major: [b][h][n][bucket]
__device__ float    d_Y  [Bsz*N1*Dm];
__device__ float    d_T1 [Bsz*N1*Dff];
__device__ float    d_T2 [Bsz*N1*Dm];
__device__ float    d_PS1[Bsz*NCH*Dm];
__device__ float    d_PS2[Bsz*NCH*Dm];
__device__ float    d_PA [3*Bsz*N1*Hh*17];  // split-K partials: acc[16]+lrun

// ------------------------- input embedding + state init ----------------------
__global__ void k_input(const float* __restrict__ coords, const float* __restrict__ inW,
                        const float* __restrict__ inb, const float* __restrict__ gnode)
{
    int gid = blockIdx.x*blockDim.x + threadIdx.x;
    if (gid < Bsz*Dm) d_POOL[gid] = 0.f;
    if (gid >= Bsz*N1*Dm) return;
    int d = gid % Dm;
    int n = (gid / Dm) % N1;
    int b = gid / (Dm*N1);
    float v;
    if (n < Nn) {
        float x = coords[(b*Nn+n)*2+0];
        float y = coords[(b*Nn+n)*2+1];
        v = x*inW[d*2+0] + y*inW[d*2+1] + inb[d];
    } else {
        v = gnode[d];
    }
    d_HG[gid] = v;
}

// ------------------------- layer-0 g update: g += mean(h) --------------------
__global__ void k_colmean()
{
    __shared__ float red[8][Dm];
    int b = blockIdx.x;
    int d = threadIdx.x & 127;
    int g = threadIdx.x >> 7;
    const float* base = d_HG + (size_t)b*N1*Dm;
    float s = 0.f;
    for (int n = g; n < Nn; n += 8) s += base[n*Dm + d];
    red[g][d] = s;
    __syncthreads();
    if (g == 0) {
        float t = 0.f;
        #pragma unroll
        for (int i = 0; i < 8; i++) t += red[i][d];
        d_HG[(size_t)b*N1*Dm + Nn*Dm + d] += t * (1.f/Nn);
    }
}

// ------------------------- prologue: adjacency base + sq norms ---------------
// 256 threads = 4 rows x 64
__global__ void k_prol()
{
    int row = blockIdx.x*4 + (threadIdx.x >> 6);   // b*N1 + i
    int t   = threadIdx.x & 63;
    if (row >= Bsz*N1) return;
    int i = row % N1;
    int b = row / N1;
    if (t < AW) {
        int w = t;
        unsigned bits = 0u;
        #pragma unroll 4
        for (int q = 0; q < 32; q++) {
            int m = w*32 + q;
            if (m > Nn) break;
            bool on;
            if (i == Nn || m == Nn || i == m || i == 0 || m == 0) on = true;
            else {
                int di = i - m; if (di < 0) di = -di;
                on = ((i >> 7) == (m >> 7)) && (di <= 11);   // hier adjacency
            }
            if (on) bits |= 1u << q;
        }
        d_ADJ[row*AW + w] = bits;
    }
    if (t >= 32 && i < Nn) {           // lanes 32..63: squared norm
        int lane = t - 32;
        const float* p = d_HG + (size_t)row*Dm;
        float s = 0.f;
        #pragma unroll
        for (int q = 0; q < 4; q++) { float v = p[lane + q*32]; s += v*v; }
        #pragma unroll
        for (int o = 16; o; o >>= 1) s += __shfl_xor_sync(0xffffffffu, s, o);
        if (!lane) d_SQ[b*Nn + i] = s;
    }
}

// ------------------------- D2 matrix: symmetric triangle, double-buffered ----
__global__ void k_d2()
{
    __shared__ float As[2][16][68];
    __shared__ float Bs[2][16][68];
    int b = blockIdx.y;
    // decode upper-triangle block (bi <= bj) from linear index (136 blocks)
    int x = blockIdx.x, bi = 0;
    while (x >= 16 - bi) { x -= 16 - bi; bi++; }
    int bj = bi + x;
    const float* A = d_HG + (size_t)b*N1*Dm;
    int tid = threadIdx.x;
    int tr = tid >> 4, tc = tid & 15;
    int r0 = bi*64, c0 = bj*64;
    int lr = tid >> 2;
    int lc = (tid & 3) * 4;
    float4 va = *(const float4*)(A + (size_t)(r0+lr)*Dm + lc);
    float4 vb = *(const float4*)(A + (size_t)(c0+lr)*Dm + lc);
    As[0][lc+0][lr]=va.x; As[0][lc+1][lr]=va.y; As[0][lc+2][lr]=va.z; As[0][lc+3][lr]=va.w;
    Bs[0][lc+0][lr]=vb.x; Bs[0][lc+1][lr]=vb.y; Bs[0][lc+2][lr]=vb.z; Bs[0][lc+3][lr]=vb.w;
    __syncthreads();
    float acc[4][4] = {};
    #pragma unroll
    for (int s = 0; s < 8; s++) {
        int cur = s & 1;
        if (s < 7) {
            va = *(const float4*)(A + (size_t)(r0+lr)*Dm + (s+1)*16 + lc);
            vb = *(const float4*)(A + (size_t)(c0+lr)*Dm + (s+1)*16 + lc);
        }
        #pragma unroll
        for (int k = 0; k < 16; k++) {
            float4 a4 = *(const float4*)&As[cur][k][tr*4];
            float4 b4 = *(const float4*)&Bs[cur][k][tc*4];
            float a[4] = {a4.x, a4.y, a4.z, a4.w};
            float bv[4] = {b4.x, b4.y, b4.z, b4.w};
            #pragma unroll
            for (int i = 0; i < 4; i++)
                #pragma unroll
                for (int j = 0; j < 4; j++) acc[i][j] += a[i]*bv[j];
        }
        if (s < 7) {
            int nxt = cur ^ 1;
            As[nxt][lc+0][lr]=va.x; As[nxt][lc+1][lr]=va.y; As[nxt][lc+2][lr]=va.z; As[nxt][lc+3][lr]=va.w;
            Bs[nxt][lc+0][lr]=vb.x; Bs[nxt][lc+1][lr]=vb.y; Bs[nxt][lc+2][lr]=vb.z; Bs[nxt][lc+3][lr]=vb.w;
            __syncthreads();
        }
    }
    float vals[4][4];
    #pragma unroll
    for (int i = 0; i < 4; i++) {
        int r = r0 + tr*4 + i;
        float sqr = d_SQ[b*Nn + r];
        float* orow = d_D2 + ((size_t)b*Nn + r)*Nn + c0 + tc*4;
        float o[4];
        #pragma unroll
        for (int j = 0; j < 4; j++) {
            int c = c0 + tc*4 + j;
            float v = sqr + d_SQ[b*Nn + c] - 2.f*acc[i][j];
            o[j] = (r == c) ? CUDART_INF_F : v;
            vals[i][j] = o[j];
        }
        *(float4*)orow = make_float4(o[0], o[1], o[2], o[3]);
    }
    if (bi != bj) {   // mirror write
        #pragma unroll
        for (int j = 0; j < 4; j++) {
            int c = c0 + tc*4 + j;
            float* orow = d_D2 + ((size_t)b*Nn + c)*Nn + r0 + tr*4;
            *(float4*)orow = make_float4(vals[0][j], vals[1][j], vals[2][j], vals[3][j]);
        }
    }
}

// ------------------------- exact top-10 kNN -> adjacency bits ----------------
__global__ void k_topk()
{
    int warp = (blockIdx.x*blockDim.x + threadIdx.x) >> 5;
    int lane = threadIdx.x & 31;
    if (warp >= Bsz*Nn) return;
    int b = warp >> 10, i = warp & 1023;
    const float* row = d_D2 + (size_t)warp*Nn;
    float vals[32];
    #pragma unroll
    for (int t = 0; t < 32; t++) vals[t] = row[t*32 + lane];
    unsigned used = 0u;
    unsigned* adjb = d_ADJ + (size_t)b*N1*AW;
    for (int r = 0; r < KNN; r++) {
        float bv = CUDART_INF_F; int bj = 1 << 30;
        #pragma unroll
        for (int t = 0; t < 32; t++) {
            if (!((used >> t) & 1u)) {
                float v = vals[t]; int j = t*32 + lane;
                if (v < bv || (v == bv && j < bj)) { bv = v; bj = j; }
            }
        }
        #pragma unroll
        for (int o = 16; o; o >>= 1) {
            float ov = __shfl_xor_sync(0xffffffffu, bv, o);
            int   oj = __shfl_xor_sync(0xffffffffu, bj, o);
            if (ov < bv || (ov == bv && oj < bj)) { bv = ov; bj = oj; }
        }
        if (lane == (bj & 31)) used |= 1u << (bj >> 5);
        if (lane == 0) {
            atomicOr(&adjb[i*AW + (bj >> 5)], 1u << (bj & 31));
            atomicOr(&adjb[bj*AW + (i >> 5)], 1u << (i & 31));
        }
    }
}

// ------------------------- generic SGEMM (double-buffered) -------------------
// C = A[M,K] * W[N,K]^T; flags: 1=+bias, 2=+res, 4=relu
__global__ void k_gemm(const float* __restrict__ A, const float* __restrict__ Bm,
                       const float* __restrict__ bias, const float* __restrict__ res,
                       float* __restrict__ C, int M, int Nc, int K, int flags)
{
    __shared__ float As[2][16][68];
    __shared__ float Bs[2][16][68];
    int tid = threadIdx.x;
    int tr = tid >> 4, tc = tid & 15;
    int r0 = blockIdx.y*64, c0 = blockIdx.x*64;
    int lr = tid >> 2;
    int lc = (tid & 3) * 4;
    int gr = r0 + lr, gc = c0 + lr;
    const float4 z4 = make_float4(0.f,0.f,0.f,0.f);
    float4 va = (gr < M) ? *(const float4*)(A + (size_t)gr*K + lc) : z4;
    float4 vb = *(const float4*)(Bm + (size_t)gc*K + lc);
    As[0][lc+0][lr]=va.x; As[0][lc+1][lr]=va.y; As[0][lc+2][lr]=va.z; As[0][lc+3][lr]=va.w;
    Bs[0][lc+0][lr]=vb.x; Bs[0][lc+1][lr]=vb.y; Bs[0][lc+2][lr]=vb.z; Bs[0][lc+3][lr]=vb.w;
    __syncthreads();
    float acc[4][4] = {};
    int S = K >> 4;
    for (int s = 0; s < S; s++) {
        int cur = s & 1;
        if (s + 1 < S) {
            va = (gr < M) ? *(const float4*)(A + (size_t)gr*K + (s+1)*16 + lc) : z4;
            vb = *(const float4*)(Bm + (size_t)gc*K + (s+1)*16 + lc);
        }
        #pragma unroll
        for (int k = 0; k < 16; k++) {
            float4 a4 = *(const float4*)&As[cur][k][tr*4];
            float4 b4 = *(const float4*)&Bs[cur][k][tc*4];
            float a[4] = {a4.x, a4.y, a4.z, a4.w};
            float bv[4] = {b4.x, b4.y, b4.z, b4.w};
            #pragma unroll
            for (int i = 0; i < 4; i++)
                #pragma unroll
                for (int j = 0; j < 4; j++) acc[i][j] += a[i]*bv[j];
        }
        if (s + 1 < S) {
            int nxt = cur ^ 1;
            As[nxt][lc+0][lr]=va.x; As[nxt][lc+1][lr]=va.y; As[nxt][lc+2][lr]=va.z; As[nxt][lc+3][lr]=va.w;
            Bs[nxt][lc+0][lr]=vb.x; Bs[nxt][lc+1][lr]=vb.y; Bs[nxt][lc+2][lr]=vb.z; Bs[nxt][lc+3][lr]=vb.w;
            __syncthreads();
        }
    }
    int c = c0 + tc*4;
    float4 bz = z4;
    if (flags & 1) bz = *(const float4*)(bias + c);
    #pragma unroll
    for (int i = 0; i < 4; i++) {
        int r = r0 + tr*4 + i;
        if (r >= M) continue;
        float4 v = make_float4(acc[i][0]+bz.x, acc[i][1]+bz.y, acc[i][2]+bz.z, acc[i][3]+bz.w);
        if (flags & 2) {
            float4 rv = *(const float4*)(res + (size_t)r*Nc + c);
            v.x += rv.x; v.y += rv.y; v.z += rv.z; v.w += rv.w;
        }
        if (flags & 4) {
            v.x = fmaxf(v.x, 0.f); v.y = fmaxf(v.y, 0.f);
            v.z = fmaxf(v.z, 0.f); v.w = fmaxf(v.w, 0.f);
        }
        *(float4*)(C + (size_t)r*Nc + c) = v;
    }
}

// ------------------------- fused QKV GEMM (double-buffered, head-major out) --
__global__ void k_qkv(const float* __restrict__ A, const float* __restrict__ wq,
                      const float* __restrict__ wk, const float* __restrict__ wv)
{
    __shared__ float As[2][16][68];
    __shared__ float Bs[2][16][68];
    int sel = blockIdx.x >> 1;
    const float* Bm = (sel == 0) ? wq : (sel == 1) ? wk : wv;
    float* C = (sel == 0) ? d_Q : (sel == 1) ? d_Kb : d_Vb;
    const int M = Bsz*N1;
    int tid = threadIdx.x;
    int tr = tid >> 4, tc = tid & 15;
    int r0 = blockIdx.y*64, c0 = (blockIdx.x & 1)*64;
    int lr = tid >> 2;
    int lc = (tid & 3) * 4;
    int gr = r0 + lr, gc = c0 + lr;
    const float4 z4 = make_float4(0.f,0.f,0.f,0.f);
    float4 va = (gr < M) ? *(const float4*)(A + (size_t)gr*Dm + lc) : z4;
    float4 vb = *(const float4*)(Bm + (size_t)gc*Dm + lc);
    As[0][lc+0][lr]=va.x; As[0][lc+1][lr]=va.y; As[0][lc+2][lr]=va.z; As[0][lc+3][lr]=va.w;
    Bs[0][lc+0][lr]=vb.x; Bs[0][lc+1][lr]=vb.y; Bs[0][lc+2][lr]=vb.z; Bs[0][lc+3][lr]=vb.w;
    __syncthreads();
    float acc[4][4] = {};
    #pragma unroll
    for (int s = 0; s < 8; s++) {
        int cur = s & 1;
        if (s < 7) {
            va = (gr < M) ? *(const float4*)(A + (size_t)gr*Dm + (s+1)*16 + lc) : z4;
            vb = *(const float4*)(Bm + (size_t)gc*Dm + (s+1)*16 + lc);
        }
        #pragma unroll
        for (int k = 0; k < 16; k++) {
            float4 a4 = *(const float4*)&As[cur][k][tr*4];
            float4 b4 = *(const float4*)&Bs[cur][k][tc*4];
            float a[4] = {a4.x, a4.y, a4.z, a4.w};
            float bv[4] = {b4.x, b4.y, b4.z, b4.w};
            #pragma unroll
            for (int i = 0; i < 4; i++)
                #pragma unroll
                for (int j = 0; j < 4; j++) acc[i][j] += a[i]*bv[j];
        }
        if (s < 7) {
            int nxt = cur ^ 1;
            As[nxt][lc+0][lr]=va.x; As[nxt][lc+1][lr]=va.y; As[nxt][lc+2][lr]=va.z; As[nxt][lc+3][lr]=va.w;
            Bs[nxt][lc+0][lr]=vb.x; Bs[nxt][lc+1][lr]=vb.y; Bs[nxt][lc+2][lr]=vb.z; Bs[nxt][lc+3][lr]=vb.w;
            __syncthreads();
        }
    }
    int c = c0 + tc*4;
    int h  = c >> 4;
    int dk = c & 15;
    #pragma unroll
    for (int i = 0; i < 4; i++) {
        int r = r0 + tr*4 + i;
        if (r >= M) continue;
        int bb = (r >= N1) ? 1 : 0;
        int n  = r - bb*N1;
        *(float4*)(C + ((size_t)(bb*Hh + h)*N1 + n)*Dk + dk) =
            make_float4(acc[i][0], acc[i][1], acc[i][2], acc[i][3]);
    }
}

// ------------------------- qe = Q . emb per (head,bucket), head-major --------
__global__ void k_qe(const float* __restrict__ emb)
{
    __shared__ float qs[Dm];
    int row = blockIdx.x;              // b*N1 + n
    int b = (row >= N1) ? 1 : 0;
    int n = row - b*N1;
    int tid = threadIdx.x;
    if (tid < Dm) {
        int hh = tid >> 4, dk = tid & 15;
        qs[tid] = d_Q[((size_t)(b*Hh + hh)*N1 + n)*Dk + dk];
    }
    __syncthreads();
    int h = tid >> 5, kb = tid & 31;
    const float* e = emb + kb*Dm + h*Dk;
    const float* q = qs + h*Dk;
    float s = 0.f;
    #pragma unroll
    for (int dd = 0; dd < Dk; dd++) s += q[dd]*e[dd];
    d_QE[((size_t)(b*Hh + h)*N1 + n)*NBk + kb] = s;
}

// ------------------------- sparse attention, split-K + fused dense -----------
__device__ __forceinline__ void attn_word20(unsigned word, int base,
    const float4 q4[4], float cqx, float cqy,
    const float (*Ks)[20], const float (*Vs)[20],
    const float* ckx, const float* cky, const float* qerow,
    float& lrun, float acc[16])
{
    while (word) {
        int mm = base + (__ffs((int)word) - 1);
        word &= word - 1u;
        const float4* kp = (const float4*)Ks[mm];
        float4 k0 = kp[0], k1 = kp[1], k2 = kp[2], k3 = kp[3];
        float s = q4[0].x*k0.x + q4[0].y*k0.y + q4[0].z*k0.z + q4[0].w*k0.w
                + q4[1].x*k1.x + q4[1].y*k1.y + q4[1].z*k1.z + q4[1].w*k1.w
                + q4[2].x*k2.x + q4[2].y*k2.y + q4[2].z*k2.z + q4[2].w*k2.w
                + q4[3].x*k3.x + q4[3].y*k3.y + q4[3].z*k3.z + q4[3].w*k3.w;
        float dx = cqx - ckx[mm], dy = cqy - cky[mm];
        float dist = sqrtf(dx*dx + dy*dy);
        int bk = (int)(dist * 32.f); if (bk > 31) bk = 31;
        float p = __expf(s*SCALEf + qerow[bk]);
        lrun += p;
        const float4* vp = (const float4*)Vs[mm];
        float4 v0 = vp[0], v1 = vp[1], v2 = vp[2], v3 = vp[3];
        acc[ 0] += p*v0.x; acc[ 1] += p*v0.y; acc[ 2] += p*v0.z; acc[ 3] += p*v0.w;
        acc[ 4] += p*v1.x; acc[ 5] += p*v1.y; acc[ 6] += p*v1.z; acc[ 7] += p*v1.w;
        acc[ 8] += p*v2.x; acc[ 9] += p*v2.y; acc[10] += p*v2.z; acc[11] += p*v2.w;
        acc[12] += p*v3.x; acc[13] += p*v3.y; acc[14] += p*v3.z; acc[15] += p*v3.w;
    }
}

// grid (25, Hh, Bsz), 128 threads. x<24: sparse (qtile=x/3, kseg=x%3).
// x==24: dense rows {0, Nn} (64 threads each).
__global__ void k_attn(const float* __restrict__ coords)
{
    __shared__ float Ks[128][20];
    __shared__ float Vs[128][20];
    __shared__ float ckx[128], cky[128];
    __shared__ float qes[128][33];
    __shared__ float pw[4][17];
    int b = blockIdx.z, h = blockIdx.y;
    int x = blockIdx.x;
    int tid = threadIdx.x;
    const size_t hb = (size_t)(b*Hh + h)*N1;

    if (x == 24) {   // ---- dense rows ----
        int sub = tid >> 6, st = tid & 63;
        int lane = tid & 31, w = tid >> 5;
        int n = sub ? Nn : 0;
        float q[16];
        const float4* qp = (const float4*)(d_Q + (hb + n)*Dk);
        #pragma unroll
        for (int i = 0; i < 4; i++) {
            float4 v = qp[i];
            q[i*4+0]=v.x; q[i*4+1]=v.y; q[i*4+2]=v.z; q[i*4+3]=v.w;
        }
        float cqx = 0.f, cqy = 0.f;
        if (n < Nn) { cqx = coords[(b*Nn+n)*2]; cqy = coords[(b*Nn+n)*2+1]; }
        const float* qerow = d_QE + (hb + n)*NBk;
        float l = 0.f, acc[16];
        #pragma unroll
        for (int d = 0; d < 16; d++) acc[d] = 0.f;
        const float* Kt = d_Kb + hb*Dk;
        const float* Vt = d_Vb + hb*Dk;
        for (int mk = st; mk < N1; mk += 64) {
            const float4* kp = (const float4*)(Kt + (size_t)mk*Dk);
            float s = 0.f;
            #pragma unroll
            for (int i = 0; i < 4; i++) {
                float4 kv = kp[i];
                s += q[i*4+0]*kv.x + q[i*4+1]*kv.y + q[i*4+2]*kv.z + q[i*4+3]*kv.w;
            }
            float cmx = 0.f, cmy = 0.f;
            if (mk < Nn) { cmx = coords[(b*Nn+mk)*2]; cmy = coords[(b*Nn+mk)*2+1]; }
            float dx = cqx - cmx, dy = cqy - cmy;
            float dist = sqrtf(dx*dx + dy*dy);
            int bk = (int)(dist * 32.f); if (bk > 31) bk = 31;
            float p = __expf(s*SCALEf + qerow[bk]);
            l += p;
            const float4* vp = (const float4*)(Vt + (size_t)mk*Dk);
            #pragma unroll
            for (int i = 0; i < 4; i++) {
                float4 vv = vp[i];
                acc[i*4+0] += p*vv.x; acc[i*4+1] += p*vv.y;
                acc[i*4+2] += p*vv.z; acc[i*4+3] += p*vv.w;
            }
        }
        #pragma unroll
        for (int o = 16; o; o >>= 1) {
            l += __shfl_xor_sync(0xffffffffu, l, o);
            #pragma unroll
            for (int d = 0; d < 16; d++) acc[d] += __shfl_xor_sync(0xffffffffu, acc[d], o);
        }
        if (lane == 0) {
            #pragma unroll
            for (int d = 0; d < 16; d++) pw[w][d] = acc[d];
            pw[w][16] = l;
        }
        __syncthreads();
        if (tid == 0 || tid == 64) {
            int w0 = sub*2;
            float L = pw[w0][16] + pw[w0+1][16];
            float inv = 1.f / L;
            float* o = d_CTX + ((size_t)(b*N1 + n))*Dm + h*Dk;
            #pragma unroll
            for (int d = 0; d < 16; d++) o[d] = (pw[w0][d] + pw[w0+1][d]) * inv;
        }
        return;
    }

    // ---- sparse split-K ----
    int qt = x / 3, kseg = x % 3;
    int n = qt*128 + tid;              // 0..1023
    bool qv = (n != 0);                // row 0 is dense
    float4 q4[4];
    float cqx = 0.f, cqy = 0.f, lrun = 0.f;
    float acc[16];
    #pragma unroll
    for (int d = 0; d < 16; d++) acc[d] = 0.f;
    const unsigned* rowadj = d_ADJ + (size_t)(b*N1 + n)*AW;
    {
        const float4* qp = (const float4*)(d_Q + (hb + n)*Dk);
        #pragma unroll
        for (int i = 0; i < 4; i++) q4[i] = qp[i];
        cqx = coords[(b*Nn+n)*2]; cqy = coords[(b*Nn+n)*2+1];
        const float4* qep = (const float4*)(d_QE + (hb + n)*NBk);
        #pragma unroll
        for (int i = 0; i < 8; i++) {
            float4 v = qep[i];
            qes[tid][i*4+0]=v.x; qes[tid][i*4+1]=v.y;
            qes[tid][i*4+2]=v.z; qes[tid][i*4+3]=v.w;
        }
    }
    for (int kt = kseg*3; kt < kseg*3 + 3; kt++) {
        int m0 = kt*128;
        int tlen = N1 - m0; if (tlen > 128) tlen = 128;
        const float4* Kt = (const float4*)(d_Kb + (hb + m0)*Dk);
        const float4* Vt = (const float4*)(d_Vb + (hb + m0)*Dk);
        __syncthreads();
        #pragma unroll
        for (int i = 0; i < 4; i++) {
            int f = tid + i*128;
            int row = f >> 2, j = (f & 3)*4;
            if (row < tlen) {
                *(float4*)&Ks[row][j] = Kt[f];
                *(float4*)&Vs[row][j] = Vt[f];
            }
        }
        if (tid < tlen) {
            int m = m0 + tid;
            if (m < Nn) { ckx[tid] = coords[(b*Nn+m)*2]; cky[tid] = coords[(b*Nn+m)*2+1]; }
            else        { ckx[tid] = 0.f; cky[tid] = 0.f; }
        }
        __syncthreads();
        if (!qv) continue;
        int wb = m0 >> 5;
        unsigned w0 = rowadj[wb];
        unsigned w1 = (wb+1 < AW) ? rowadj[wb+1] : 0u;
        unsigned w2 = (wb+2 < AW) ? rowadj[wb+2] : 0u;
        unsigned w3 = (wb+3 < AW) ? rowadj[wb+3] : 0u;
        attn_word20(w0,  0, q4, cqx, cqy, Ks, Vs, ckx, cky, qes[tid], lrun, acc);
        attn_word20(w1, 32, q4, cqx, cqy, Ks, Vs, ckx, cky, qes[tid], lrun, acc);
        attn_word20(w2, 64, q4, cqx, cqy, Ks, Vs, ckx, cky, qes[tid], lrun, acc);
        attn_word20(w3, 96, q4, cqx, cqy, Ks, Vs, ckx, cky, qes[tid], lrun, acc);
    }
    if (qv) {
        size_t base = ((size_t)kseg*Bsz*N1 + (size_t)b*N1 + n)*Hh + h;
        float* pa = d_PA + base*17;
        #pragma unroll
        for (int d = 0; d < 16; d++) pa[d] = acc[d];
        pa[16] = lrun;
    }
}

// ------------------------- combine split-K partials --------------------------
__global__ void k_comb()
{
    int u = blockIdx.x*blockDim.x + threadIdx.x;   // (b*N1+n)*Hh + h
    if (u >= Bsz*N1*Hh) return;
    int h = u & 7;
    int r = u >> 3;
    int n = (r >= N1) ? r - N1 : r;
    if (n == 0 || n == Nn) return;                  // dense rows written directly
    const int ST = Bsz*N1*Hh*17;
    int base = u*17;
    float l = d_PA[base+16] + d_PA[ST+base+16] + d_PA[2*ST+base+16];
    float inv = 1.f / l;
    float* o = d_CTX + (size_t)r*Dm + h*Dk;
    #pragma unroll
    for (int d = 0; d < 16; d++)
        o[d] = (d_PA[base+d] + d_PA[ST+base+d] + d_PA[2*ST+base+d]) * inv;
}

// ------------------------- instance norm: stats (partials) -------------------
__global__ void k_istat(const float* __restrict__ src)
{
    __shared__ float s1[2][Dm], s2[2][Dm];
    int b = blockIdx.x, z = blockIdx.y;
    int d = threadIdx.x & 127, g = threadIdx.x >> 7;
    int nend = z*64 + 64; if (nend > N1) nend = N1;
    const float* p = src + (size_t)b*N1*Dm + d;
    float a = 0.f, qq = 0.f;
    for (int n = z*64 + g; n < nend; n += 2) {
        float x = p[(size_t)n*Dm];
        a += x; qq += x*x;
    }
    s1[g][d] = a; s2[g][d] = qq;
    __syncthreads();
    if (g == 0) {
        d_PS1[(b*NCH + z)*Dm + d] = s1[0][d] + s1[1][d];
        d_PS2[(b*NCH + z)*Dm + d] = s2[0][d] + s2[1][d];
    }
}

// ------------------------- instance norm: apply ------------------------------
__global__ void k_iapply(const float* __restrict__ src, float* __restrict__ dst,
                         const float* __restrict__ w, const float* __restrict__ bb, int fuse)
{
    int b  = blockIdx.x;
    int dl = threadIdx.x & 31;
    int g  = threadIdx.x >> 5;
    int d  = blockIdx.y*32 + dl;
    int z  = blockIdx.z;
    float S1 = 0.f, S2 = 0.f;
    #pragma unroll
    for (int t = 0; t < NCH; t++) {
        S1 += d_PS1[(b*NCH + t)*Dm + d];
        S2 += d_PS2[(b*NCH + t)*Dm + d];
    }
    float mu  = S1 * (1.f/N1);
    float var = S2 * (1.f/N1) - mu*mu;
    float sc  = rsqrtf(var + EPSf) * w[d];
    float sh  = bb[d];
    const float* p = src + (size_t)b*N1*Dm + d;
    float* o = dst + (size_t)b*N1*Dm + d;
    float mo = 0.f;
    if (fuse) mo = ((S1 - p[(size_t)Nn*Dm])*(1.f/Nn) - mu)*sc + sh;
    int n0 = z*128, n1 = (z == 7) ? N1 : (z+1)*128;
    for (int n = n0 + g; n < n1; n += 32) {
        float val = (p[(size_t)n*Dm] - mu)*sc + sh;
        if (fuse && n == Nn) val += mo;
        o[(size_t)n*Dm] = val;
    }
    if (fuse && z == 7 && g == 0) d_POOL[b*Dm + d] += mo;
}

// ------------------------- final GEMM: out = (h + pool/3) @ outW^T + outb ----
// A built on the fly from d_HG + d_POOL. M = Bsz*Nn = 2048 exactly.
__global__ void k_fgemm(const float* __restrict__ Bm, const float* __restrict__ bias,
                        float* __restrict__ out)
{
    __shared__ float As[2][16][68];
    __shared__ float Bs[2][16][68];
    int tid = threadIdx.x;
    int tr = tid >> 4, tc = tid & 15;
    int r0 = blockIdx.y*64, c0 = blockIdx.x*64;
    int lr = tid >> 2;
    int lc = (tid & 3) * 4;
    int gr = r0 + lr;
    int bb = gr >> 10, nn = gr & 1023;
    const float* Arow = d_HG + ((size_t)bb*N1 + nn)*Dm;
    const float* Prow = d_POOL + bb*Dm;
    int gc = c0 + lr;
    if (blockIdx.x == 0 && blockIdx.y == 0 && tid < Bsz*Dm)
        out[Bsz*Nn*Dm + tid] = d_POOL[tid] * (1.f/3.f);
    float4 va, vb;
    {
        float4 hv = *(const float4*)(Arow + lc);
        float4 pv = *(const float4*)(Prow + lc);
        va = make_float4(hv.x + pv.x*(1.f/3.f), hv.y + pv.y*(1.f/3.f),
                         hv.z + pv.z*(1.f/3.f), hv.w + pv.w*(1.f/3.f));
        vb = *(const float4*)(Bm + (size_t)gc*Dm + lc);
    }
    As[0][lc+0][lr]=va.x; As[0][lc+1][lr]=va.y; As[0][lc+2][lr]=va.z; As[0][lc+3][lr]=va.w;
    Bs[0][lc+0][lr]=vb.x; Bs[0][lc+1][lr]=vb.y; Bs[0][lc+2][lr]=vb.z; Bs[0][lc+3][lr]=vb.w;
    __syncthreads();
    float acc[4][4] = {};
    #pragma unroll
    for (int s = 0; s < 8; s++) {
        int cur = s & 1;
        if (s < 7) {
            float4 hv = *(const float4*)(Arow + (s+1)*16 + lc);
            float4 pv = *(const float4*)(Prow + (s+1)*16 + lc);
            va = make_float4(hv.x + pv.x*(1.f/3.f), hv.y + pv.y*(1.f/3.f),
                             hv.z + pv.z*(1.f/3.f), hv.w + pv.w*(1.f/3.f));
            vb = *(const float4*)(Bm + (size_t)gc*Dm + (s+1)*16 + lc);
        }
        #pragma unroll
        for (int k = 0; k < 16; k++) {
            float4 a4 = *(const float4*)&As[cur][k][tr*4];
            float4 b4 = *(const float4*)&Bs[cur][k][tc*4];
            float a[4] = {a4.x, a4.y, a4.z, a4.w};
            float bv[4] = {b4.x, b4.y, b4.z, b4.w};
            #pragma unroll
            for (int i = 0; i < 4; i++)
                #pragma unroll
                for (int j = 0; j < 4; j++) acc[i][j] += a[i]*bv[j];
        }
        if (s < 7) {
            int nxt = cur ^ 1;
            As[nxt][lc+0][lr]=va.x; As[nxt][lc+1][lr]=va.y; As[nxt][lc+2][lr]=va.z; As[nxt][lc+3][lr]=va.w;
            Bs[nxt][lc+0][lr]=vb.x; Bs[nxt][lc+1][lr]=vb.y; Bs[nxt][lc+2][lr]=vb.z; Bs[nxt][lc+3][lr]=vb.w;
            __syncthreads();
        }
    }
    int c = c0 + tc*4;
    float4 bz = *(const float4*)(bias + c);
    #pragma unroll
    for (int i = 0; i < 4; i++) {
        int r = r0 + tr*4 + i;
        *(float4*)(out + (size_t)r*Dm + c) =
            make_float4(acc[i][0]+bz.x, acc[i][1]+bz.y, acc[i][2]+bz.z, acc[i][3]+bz.w);
    }
}

// ------------------------- host driver ---------------------------------------
extern "C" void kernel_launch(void* const* d_in, const int* in_sizes, int n_in,
                              void* d_out, int out_size)
{
    const float* coords = (const float*)d_in[0];
    const float* in_W   = (const float*)d_in[1];
    const float* in_b   = (const float*)d_in[2];
    const float* gnode  = (const float*)d_in[3];
    const float* Wq     = (const float*)d_in[4];
    const float* Wk     = (const float*)d_in[5];
    const float* Wv     = (const float*)d_in[6];
    const float* Wo     = (const float*)d_in[7];
    const float* emb    = (const float*)d_in[8];
    const float* W1     = (const float*)d_in[9];
    const float* b1     = (const float*)d_in[10];
    const float* W2     = (const float*)d_in[11];
    const float* b2     = (const float*)d_in[12];
    const float* n1w    = (const float*)d_in[13];
    const float* n1b    = (const float*)d_in[14];
    const float* n2w    = (const float*)d_in[15];
    const float* n2b    = (const float*)d_in[16];
    const float* outW   = (const float*)d_in[17];
    const float* outb   = (const float*)d_in[18];
    float* out = (float*)d_out;

    float *HG, *CTX, *Y, *T1, *T2;
    cudaGetSymbolAddress((void**)&HG,  d_HG);
    cudaGetSymbolAddress((void**)&CTX, d_CTX);
    cudaGetSymbolAddress((void**)&Y,   d_Y);
    cudaGetSymbolAddress((void**)&T1,  d_T1);
    cudaGetSymbolAddress((void**)&T2,  d_T2);

    const int Mall = Bsz*N1;  // 2050

    k_input<<<(Bsz*N1*Dm + 255)/256, 256>>>(coords, in_W, in_b, gnode);
    k_colmean<<<Bsz, 1024>>>();                            // layer-0 g update

    for (int l = 0; l < 3; l++) {
        k_prol<<<(Bsz*N1 + 3)/4, 256>>>();
        { dim3 g(136, Bsz); k_d2<<<g, 256>>>(); }
        k_topk<<<(Bsz*Nn)/8, 256>>>();

        { dim3 gqkv(6, (Mall + 63)/64);
          k_qkv<<<gqkv, 256>>>(HG, Wq + (size_t)l*Dm*Dm, Wk + (size_t)l*Dm*Dm, Wv + (size_t)l*Dm*Dm); }
        k_qe<<<Mall, 256>>>(emb + (size_t)l*NBk*Dm);
        { dim3 ga(25, Hh, Bsz); k_attn<<<ga, 128>>>(coords); }
        k_comb<<<(Bsz*N1*Hh + 127)/128, 128>>>();

        dim3 gq(Dm/64, (Mall + 63)/64);
        k_gemm<<<gq, 256>>>(CTX, Wo + (size_t)l*Dm*Dm, nullptr, HG, Y, Mall, Dm, Dm, 2);
        { dim3 gs(Bsz, NCH); k_istat<<<gs, 256>>>(Y); }
        { dim3 gi(Bsz, 4, 8); k_iapply<<<gi, 1024>>>(Y, Y, n1w + l*Dm, n1b + l*Dm, 0); }

        dim3 g1(Dff/64, (Mall + 63)/64);
        k_gemm<<<g1, 256>>>(Y,  W1 + (size_t)l*Dff*Dm, b1 + l*Dff, nullptr, T1, Mall, Dff, Dm, 1|4);
        k_gemm<<<gq, 256>>>(T1, W2 + (size_t)l*Dm*Dff, b2 + l*Dm,  Y,      T2, Mall, Dm, Dff, 1|2);
        { dim3 gs(Bsz, NCH); k_istat<<<gs, 256>>>(T2); }
        { dim3 gi(Bsz, 4, 8); k_iapply<<<gi, 1024>>>(T2, HG, n2w + l*Dm, n2b + l*Dm, 1); }
    }

    { dim3 ge(Dm/64, (Bsz*Nn)/64); k_fgemm<<<ge, 256>>>(outW, outb, out); }
}

// round 8
// speedup vs baseline: 4.8266x; 1.1256x over previous
#include <cuda_runtime.h>
#include <math_constants.h>
#include <math.h>

#define Bsz 2
#define Nn 1024
#define N1 1025
#define Dm 128
#define Hh 8
#define Dk 16
#define Dff 512
#define NBk 32
#define KNN 10
#define AW 33          // 33 x 32-bit words cover 1025 mask bits per row
#define EPSf 1e-5f
#define SCALEf 0.25f   // 1/sqrt(16)
#define NCH 17         // inorm stat chunks

// ------------------------- persistent device scratch -------------------------
__device__ float    d_HG [Bsz*N1*Dm];     // state: rows 0..1023 = h, row 1024 = g
__device__ float    d_POOL[Bsz*Dm];
__device__ float    d_D2 [(size_t)Bsz*Nn*Nn];
__device__ unsigned d_ADJ[Bsz*N1*AW];
__device__ float    d_Q  [Bsz*Hh*N1*Dk];  // head-major: [b][h][n][dk]
__device__ float    d_Kb [Bsz*Hh*N1*Dk];
__device__ float    d_Vb [Bsz*Hh*N1*Dk];
__device__ float    d_CTX[Bsz*N1*Dm];
__device__ float    d_QE [Bsz*Hh*N1*NBk]; // head-major: [b][h][n][bucket]
__device__ float    d_Y  [Bsz*N1*Dm];
__device__ float    d_T1 [Bsz*N1*Dff];
__device__ float    d_T2 [Bsz*N1*Dm];
__device__ float    d_PS1[Bsz*NCH*Dm];
__device__ float    d_PS2[Bsz*NCH*Dm];
__device__ float    d_PA [3*Bsz*N1*Hh*17];  // split-K partials: acc[16]+lrun

// ------------------------- input embedding + state init ----------------------
__global__ void k_input(const float* __restrict__ coords, const float* __restrict__ inW,
                        const float* __restrict__ inb, const float* __restrict__ gnode)
{
    int gid = blockIdx.x*blockDim.x + threadIdx.x;
    if (gid < Bsz*Dm) d_POOL[gid] = 0.f;
    if (gid >= Bsz*N1*Dm) return;
    int d = gid % Dm;
    int n = (gid / Dm) % N1;
    int b = gid / (Dm*N1);
    float v;
    if (n < Nn) {
        float x = coords[(b*Nn+n)*2+0];
        float y = coords[(b*Nn+n)*2+1];
        v = x*inW[d*2+0] + y*inW[d*2+1] + inb[d];
    } else {
        v = gnode[d];
    }
    d_HG[gid] = v;
}

// ------------------------- layer-0 g update: g += mean(h) --------------------
__global__ void k_colmean()
{
    __shared__ float red[8][Dm];
    int b = blockIdx.x;
    int d = threadIdx.x & 127;
    int g = threadIdx.x >> 7;
    const float* base = d_HG + (size_t)b*N1*Dm;
    float s = 0.f;
    for (int n = g; n < Nn; n += 8) s += base[n*Dm + d];
    red[g][d] = s;
    __syncthreads();
    if (g == 0) {
        float t = 0.f;
        #pragma unroll
        for (int i = 0; i < 8; i++) t += red[i][d];
        d_HG[(size_t)b*N1*Dm + Nn*Dm + d] += t * (1.f/Nn);
    }
}

// ===================== PAR1: D2 (self-norms) + QKV + ADJ-init =================
// grid: [0,272) d2 tiles, [272,470) qkv, [470,983) adjacency rows. 256 threads.
__global__ void k_par1(const float* __restrict__ wq, const float* __restrict__ wk,
                       const float* __restrict__ wv)
{
    __shared__ __align__(16) float As[2][16][68];
    __shared__ __align__(16) float Bs[2][16][68];
    __shared__ float rsq[64], csq[64];
    int bx = blockIdx.x;
    int tid = threadIdx.x;

    if (bx < 272) {        // ---------- D2 symmetric tile ----------
        int b = bx / 136;
        int x = bx % 136, bi = 0;
        while (x >= 16 - bi) { x -= 16 - bi; bi++; }
        int bj = bi + x;
        const float* A = d_HG + (size_t)b*N1*Dm;
        int tr = tid >> 4, tc = tid & 15;
        int r0 = bi*64, c0 = bj*64;
        int lr = tid >> 2, lc = (tid & 3)*4;
        float rn = 0.f, cn = 0.f;
        float4 va = *(const float4*)(A + (size_t)(r0+lr)*Dm + lc);
        float4 vb = *(const float4*)(A + (size_t)(c0+lr)*Dm + lc);
        rn += va.x*va.x + va.y*va.y + va.z*va.z + va.w*va.w;
        cn += vb.x*vb.x + vb.y*vb.y + vb.z*vb.z + vb.w*vb.w;
        As[0][lc+0][lr]=va.x; As[0][lc+1][lr]=va.y; As[0][lc+2][lr]=va.z; As[0][lc+3][lr]=va.w;
        Bs[0][lc+0][lr]=vb.x; Bs[0][lc+1][lr]=vb.y; Bs[0][lc+2][lr]=vb.z; Bs[0][lc+3][lr]=vb.w;
        __syncthreads();
        float acc[4][4] = {};
        #pragma unroll
        for (int s = 0; s < 8; s++) {
            int cur = s & 1;
            if (s < 7) {
                va = *(const float4*)(A + (size_t)(r0+lr)*Dm + (s+1)*16 + lc);
                vb = *(const float4*)(A + (size_t)(c0+lr)*Dm + (s+1)*16 + lc);
                rn += va.x*va.x + va.y*va.y + va.z*va.z + va.w*va.w;
                cn += vb.x*vb.x + vb.y*vb.y + vb.z*vb.z + vb.w*vb.w;
            }
            #pragma unroll
            for (int k = 0; k < 16; k++) {
                float4 a4 = *(const float4*)&As[cur][k][tr*4];
                float4 b4 = *(const float4*)&Bs[cur][k][tc*4];
                float a[4] = {a4.x, a4.y, a4.z, a4.w};
                float bv[4] = {b4.x, b4.y, b4.z, b4.w};
                #pragma unroll
                for (int i = 0; i < 4; i++)
                    #pragma unroll
                    for (int j = 0; j < 4; j++) acc[i][j] += a[i]*bv[j];
            }
            if (s < 7) {
                int nxt = cur ^ 1;
                As[nxt][lc+0][lr]=va.x; As[nxt][lc+1][lr]=va.y; As[nxt][lc+2][lr]=va.z; As[nxt][lc+3][lr]=va.w;
                Bs[nxt][lc+0][lr]=vb.x; Bs[nxt][lc+1][lr]=vb.y; Bs[nxt][lc+2][lr]=vb.z; Bs[nxt][lc+3][lr]=vb.w;
                __syncthreads();
            }
        }
        rn += __shfl_xor_sync(0xffffffffu, rn, 1);
        rn += __shfl_xor_sync(0xffffffffu, rn, 2);
        cn += __shfl_xor_sync(0xffffffffu, cn, 1);
        cn += __shfl_xor_sync(0xffffffffu, cn, 2);
        if ((tid & 3) == 0) { rsq[lr] = rn; csq[lr] = cn; }
        __syncthreads();
        float vals[4][4];
        #pragma unroll
        for (int i = 0; i < 4; i++) {
            int r = r0 + tr*4 + i;
            float sqr = rsq[tr*4 + i];
            float* orow = d_D2 + ((size_t)b*Nn + r)*Nn + c0 + tc*4;
            float o[4];
            #pragma unroll
            for (int j = 0; j < 4; j++) {
                int c = c0 + tc*4 + j;
                float v = sqr + csq[tc*4 + j] - 2.f*acc[i][j];
                o[j] = (r == c) ? CUDART_INF_F : v;
                vals[i][j] = o[j];
            }
            *(float4*)orow = make_float4(o[0], o[1], o[2], o[3]);
        }
        if (bi != bj) {
            #pragma unroll
            for (int j = 0; j < 4; j++) {
                int c = c0 + tc*4 + j;
                float* orow = d_D2 + ((size_t)b*Nn + c)*Nn + r0 + tr*4;
                *(float4*)orow = make_float4(vals[0][j], vals[1][j], vals[2][j], vals[3][j]);
            }
        }
        return;
    }

    if (bx < 470) {        // ---------- QKV GEMM ----------
        int idx = bx - 272;
        int sel = idx / 66, rem = idx % 66;
        const float* Bm = (sel == 0) ? wq : (sel == 1) ? wk : wv;
        float* C = (sel == 0) ? d_Q : (sel == 1) ? d_Kb : d_Vb;
        const int M = Bsz*N1;
        int tr = tid >> 4, tc = tid & 15;
        int r0 = (rem >> 1)*64, c0 = (rem & 1)*64;
        int lr = tid >> 2, lc = (tid & 3)*4;
        int gr = r0 + lr, gc = c0 + lr;
        const float4 z4 = make_float4(0.f,0.f,0.f,0.f);
        float4 va = (gr < M) ? *(const float4*)(d_HG + (size_t)gr*Dm + lc) : z4;
        float4 vb = *(const float4*)(Bm + (size_t)gc*Dm + lc);
        As[0][lc+0][lr]=va.x; As[0][lc+1][lr]=va.y; As[0][lc+2][lr]=va.z; As[0][lc+3][lr]=va.w;
        Bs[0][lc+0][lr]=vb.x; Bs[0][lc+1][lr]=vb.y; Bs[0][lc+2][lr]=vb.z; Bs[0][lc+3][lr]=vb.w;
        __syncthreads();
        float acc[4][4] = {};
        #pragma unroll
        for (int s = 0; s < 8; s++) {
            int cur = s & 1;
            if (s < 7) {
                va = (gr < M) ? *(const float4*)(d_HG + (size_t)gr*Dm + (s+1)*16 + lc) : z4;
                vb = *(const float4*)(Bm + (size_t)gc*Dm + (s+1)*16 + lc);
            }
            #pragma unroll
            for (int k = 0; k < 16; k++) {
                float4 a4 = *(const float4*)&As[cur][k][tr*4];
                float4 b4 = *(const float4*)&Bs[cur][k][tc*4];
                float a[4] = {a4.x, a4.y, a4.z, a4.w};
                float bv[4] = {b4.x, b4.y, b4.z, b4.w};
                #pragma unroll
                for (int i = 0; i < 4; i++)
                    #pragma unroll
                    for (int j = 0; j < 4; j++) acc[i][j] += a[i]*bv[j];
            }
            if (s < 7) {
                int nxt = cur ^ 1;
                As[nxt][lc+0][lr]=va.x; As[nxt][lc+1][lr]=va.y; As[nxt][lc+2][lr]=va.z; As[nxt][lc+3][lr]=va.w;
                Bs[nxt][lc+0][lr]=vb.x; Bs[nxt][lc+1][lr]=vb.y; Bs[nxt][lc+2][lr]=vb.z; Bs[nxt][lc+3][lr]=vb.w;
                __syncthreads();
            }
        }
        int c = c0 + tc*4;
        int h  = c >> 4;
        int dk = c & 15;
        #pragma unroll
        for (int i = 0; i < 4; i++) {
            int r = r0 + tr*4 + i;
            if (r >= M) continue;
            int bb = (r >= N1) ? 1 : 0;
            int n  = r - bb*N1;
            *(float4*)(C + ((size_t)(bb*Hh + h)*N1 + n)*Dk + dk) =
                make_float4(acc[i][0], acc[i][1], acc[i][2], acc[i][3]);
        }
        return;
    }

    // ---------- adjacency base pattern ----------
    {
        int row = (bx - 470)*4 + (tid >> 6);
        int t = tid & 63;
        if (row >= Bsz*N1 || t >= AW) return;
        int i = row % N1;
        int w = t;
        unsigned bits = 0u;
        #pragma unroll 4
        for (int q = 0; q < 32; q++) {
            int m = w*32 + q;
            if (m > Nn) break;
            bool on;
            if (i == Nn || m == Nn || i == m || i == 0 || m == 0) on = true;
            else {
                int di = i - m; if (di < 0) di = -di;
                on = ((i >> 7) == (m >> 7)) && (di <= 11);   // hier adjacency
            }
            if (on) bits |= 1u << q;
        }
        d_ADJ[row*AW + w] = bits;
    }
}

// ===================== PAR2: topk + qe =======================================
// grid: [0,256) topk (8 warps/block), [256,2306) qe rows. 256 threads.
__global__ void k_par2(const float* __restrict__ emb)
{
    int bx = blockIdx.x;
    int tid = threadIdx.x;
    if (bx < 256) {        // ---------- exact top-10 kNN ----------
        int warp = bx*8 + (tid >> 5);
        int lane = tid & 31;
        int b = warp >> 10, i = warp & 1023;
        const float* row = d_D2 + (size_t)warp*Nn;
        float vals[32];
        #pragma unroll
        for (int t = 0; t < 32; t++) vals[t] = row[t*32 + lane];
        unsigned used = 0u;
        unsigned* adjb = d_ADJ + (size_t)b*N1*AW;
        for (int r = 0; r < KNN; r++) {
            float bv = CUDART_INF_F; int bj = 1 << 30;
            #pragma unroll
            for (int t = 0; t < 32; t++) {
                if (!((used >> t) & 1u)) {
                    float v = vals[t]; int j = t*32 + lane;
                    if (v < bv || (v == bv && j < bj)) { bv = v; bj = j; }
                }
            }
            #pragma unroll
            for (int o = 16; o; o >>= 1) {
                float ov = __shfl_xor_sync(0xffffffffu, bv, o);
                int   oj = __shfl_xor_sync(0xffffffffu, bj, o);
                if (ov < bv || (ov == bv && oj < bj)) { bv = ov; bj = oj; }
            }
            if (lane == (bj & 31)) used |= 1u << (bj >> 5);
            if (lane == 0) {
                atomicOr(&adjb[i*AW + (bj >> 5)], 1u << (bj & 31));
                atomicOr(&adjb[bj*AW + (i >> 5)], 1u << (i & 31));
            }
        }
        return;
    }
    // ---------- qe = Q . emb per (head,bucket) ----------
    __shared__ float qs[Dm];
    int row = bx - 256;                // b*N1 + n
    int b = (row >= N1) ? 1 : 0;
    int n = row - b*N1;
    if (tid < Dm) {
        int hh = tid >> 4, dk = tid & 15;
        qs[tid] = d_Q[((size_t)(b*Hh + hh)*N1 + n)*Dk + dk];
    }
    __syncthreads();
    int h = tid >> 5, kb = tid & 31;
    const float* e = emb + kb*Dm + h*Dk;
    const float* q = qs + h*Dk;
    float s = 0.f;
    #pragma unroll
    for (int dd = 0; dd < Dk; dd++) s += q[dd]*e[dd];
    d_QE[((size_t)(b*Hh + h)*N1 + n)*NBk + kb] = s;
}

// ------------------------- generic SGEMM 64x64 (double-buffered) -------------
__global__ void k_gemm(const float* __restrict__ A, const float* __restrict__ Bm,
                       const float* __restrict__ bias, const float* __restrict__ res,
                       float* __restrict__ C, int M, int Nc, int K, int flags)
{
    __shared__ __align__(16) float As[2][16][68];
    __shared__ __align__(16) float Bs[2][16][68];
    int tid = threadIdx.x;
    int tr = tid >> 4, tc = tid & 15;
    int r0 = blockIdx.y*64, c0 = blockIdx.x*64;
    int lr = tid >> 2;
    int lc = (tid & 3) * 4;
    int gr = r0 + lr, gc = c0 + lr;
    const float4 z4 = make_float4(0.f,0.f,0.f,0.f);
    float4 va = (gr < M) ? *(const float4*)(A + (size_t)gr*K + lc) : z4;
    float4 vb = *(const float4*)(Bm + (size_t)gc*K + lc);
    As[0][lc+0][lr]=va.x; As[0][lc+1][lr]=va.y; As[0][lc+2][lr]=va.z; As[0][lc+3][lr]=va.w;
    Bs[0][lc+0][lr]=vb.x; Bs[0][lc+1][lr]=vb.y; Bs[0][lc+2][lr]=vb.z; Bs[0][lc+3][lr]=vb.w;
    __syncthreads();
    float acc[4][4] = {};
    int S = K >> 4;
    for (int s = 0; s < S; s++) {
        int cur = s & 1;
        if (s + 1 < S) {
            va = (gr < M) ? *(const float4*)(A + (size_t)gr*K + (s+1)*16 + lc) : z4;
            vb = *(const float4*)(Bm + (size_t)gc*K + (s+1)*16 + lc);
        }
        #pragma unroll
        for (int k = 0; k < 16; k++) {
            float4 a4 = *(const float4*)&As[cur][k][tr*4];
            float4 b4 = *(const float4*)&Bs[cur][k][tc*4];
            float a[4] = {a4.x, a4.y, a4.z, a4.w};
            float bv[4] = {b4.x, b4.y, b4.z, b4.w};
            #pragma unroll
            for (int i = 0; i < 4; i++)
                #pragma unroll
                for (int j = 0; j < 4; j++) acc[i][j] += a[i]*bv[j];
        }
        if (s + 1 < S) {
            int nxt = cur ^ 1;
            As[nxt][lc+0][lr]=va.x; As[nxt][lc+1][lr]=va.y; As[nxt][lc+2][lr]=va.z; As[nxt][lc+3][lr]=va.w;
            Bs[nxt][lc+0][lr]=vb.x; Bs[nxt][lc+1][lr]=vb.y; Bs[nxt][lc+2][lr]=vb.z; Bs[nxt][lc+3][lr]=vb.w;
            __syncthreads();
        }
    }
    int c = c0 + tc*4;
    float4 bz = z4;
    if (flags & 1) bz = *(const float4*)(bias + c);
    #pragma unroll
    for (int i = 0; i < 4; i++) {
        int r = r0 + tr*4 + i;
        if (r >= M) continue;
        float4 v = make_float4(acc[i][0]+bz.x, acc[i][1]+bz.y, acc[i][2]+bz.z, acc[i][3]+bz.w);
        if (flags & 2) {
            float4 rv = *(const float4*)(res + (size_t)r*Nc + c);
            v.x += rv.x; v.y += rv.y; v.z += rv.z; v.w += rv.w;
        }
        if (flags & 4) {
            v.x = fmaxf(v.x, 0.f); v.y = fmaxf(v.y, 0.f);
            v.z = fmaxf(v.z, 0.f); v.w = fmaxf(v.w, 0.f);
        }
        *(float4*)(C + (size_t)r*Nc + c) = v;
    }
}

// ------------------------- SGEMM 32x64 tile (better chip fill) ---------------
__global__ void k_gemmS(const float* __restrict__ A, const float* __restrict__ Bm,
                        const float* __restrict__ bias, const float* __restrict__ res,
                        float* __restrict__ C, int M, int Nc, int K, int flags)
{
    __shared__ __align__(16) float As[2][16][36];
    __shared__ __align__(16) float Bs[2][16][68];
    int tid = threadIdx.x;
    int tr = tid >> 4, tc = tid & 15;
    int r0 = blockIdx.y*32, c0 = blockIdx.x*64;
    int lr = tid >> 2;
    int lc = (tid & 3) * 4;
    bool aload = tid < 128;
    int ar = tid >> 2;                 // 0..31 for tid<128
    int gr = r0 + ar, gc = c0 + lr;
    const float4 z4 = make_float4(0.f,0.f,0.f,0.f);
    float4 va = (aload && gr < M) ? *(const float4*)(A + (size_t)gr*K + lc) : z4;
    float4 vb = *(const float4*)(Bm + (size_t)gc*K + lc);
    if (aload) {
        As[0][lc+0][ar]=va.x; As[0][lc+1][ar]=va.y; As[0][lc+2][ar]=va.z; As[0][lc+3][ar]=va.w;
    }
    Bs[0][lc+0][lr]=vb.x; Bs[0][lc+1][lr]=vb.y; Bs[0][lc+2][lr]=vb.z; Bs[0][lc+3][lr]=vb.w;
    __syncthreads();
    float acc[2][4] = {};
    int S = K >> 4;
    for (int s = 0; s < S; s++) {
        int cur = s & 1;
        if (s + 1 < S) {
            va = (aload && gr < M) ? *(const float4*)(A + (size_t)gr*K + (s+1)*16 + lc) : z4;
            vb = *(const float4*)(Bm + (size_t)gc*K + (s+1)*16 + lc);
        }
        #pragma unroll
        for (int k = 0; k < 16; k++) {
            float2 a2 = *(const float2*)&As[cur][k][tr*2];
            float4 b4 = *(const float4*)&Bs[cur][k][tc*4];
            acc[0][0] += a2.x*b4.x; acc[0][1] += a2.x*b4.y;
            acc[0][2] += a2.x*b4.z; acc[0][3] += a2.x*b4.w;
            acc[1][0] += a2.y*b4.x; acc[1][1] += a2.y*b4.y;
            acc[1][2] += a2.y*b4.z; acc[1][3] += a2.y*b4.w;
        }
        if (s + 1 < S) {
            int nxt = cur ^ 1;
            if (aload) {
                As[nxt][lc+0][ar]=va.x; As[nxt][lc+1][ar]=va.y; As[nxt][lc+2][ar]=va.z; As[nxt][lc+3][ar]=va.w;
            }
            Bs[nxt][lc+0][lr]=vb.x; Bs[nxt][lc+1][lr]=vb.y; Bs[nxt][lc+2][lr]=vb.z; Bs[nxt][lc+3][lr]=vb.w;
            __syncthreads();
        }
    }
    int c = c0 + tc*4;
    float4 bz = z4;
    if (flags & 1) bz = *(const float4*)(bias + c);
    #pragma unroll
    for (int i = 0; i < 2; i++) {
        int r = r0 + tr*2 + i;
        if (r >= M) continue;
        float4 v = make_float4(acc[i][0]+bz.x, acc[i][1]+bz.y, acc[i][2]+bz.z, acc[i][3]+bz.w);
        if (flags & 2) {
            float4 rv = *(const float4*)(res + (size_t)r*Nc + c);
            v.x += rv.x; v.y += rv.y; v.z += rv.z; v.w += rv.w;
        }
        if (flags & 4) {
            v.x = fmaxf(v.x, 0.f); v.y = fmaxf(v.y, 0.f);
            v.z = fmaxf(v.z, 0.f); v.w = fmaxf(v.w, 0.f);
        }
        *(float4*)(C + (size_t)r*Nc + c) = v;
    }
}

// ------------------------- sparse attention, split-K + fused dense -----------
__device__ __forceinline__ void attn_word20(unsigned word, int base,
    const float4 q4[4], float cqx, float cqy,
    const float (*Ks)[20], const float (*Vs)[20],
    const float* ckx, const float* cky, const float* qerow,
    float& lrun, float acc[16])
{
    while (word) {
        int mm = base + (__ffs((int)word) - 1);
        word &= word - 1u;
        const float4* kp = (const float4*)Ks[mm];
        float4 k0 = kp[0], k1 = kp[1], k2 = kp[2], k3 = kp[3];
        float s = q4[0].x*k0.x + q4[0].y*k0.y + q4[0].z*k0.z + q4[0].w*k0.w
                + q4[1].x*k1.x + q4[1].y*k1.y + q4[1].z*k1.z + q4[1].w*k1.w
                + q4[2].x*k2.x + q4[2].y*k2.y + q4[2].z*k2.z + q4[2].w*k2.w
                + q4[3].x*k3.x + q4[3].y*k3.y + q4[3].z*k3.z + q4[3].w*k3.w;
        float dx = cqx - ckx[mm], dy = cqy - cky[mm];
        float dist = sqrtf(dx*dx + dy*dy);
        int bk = (int)(dist * 32.f); if (bk > 31) bk = 31;
        float p = __expf(s*SCALEf + qerow[bk]);
        lrun += p;
        const float4* vp = (const float4*)Vs[mm];
        float4 v0 = vp[0], v1 = vp[1], v2 = vp[2], v3 = vp[3];
        acc[ 0] += p*v0.x; acc[ 1] += p*v0.y; acc[ 2] += p*v0.z; acc[ 3] += p*v0.w;
        acc[ 4] += p*v1.x; acc[ 5] += p*v1.y; acc[ 6] += p*v1.z; acc[ 7] += p*v1.w;
        acc[ 8] += p*v2.x; acc[ 9] += p*v2.y; acc[10] += p*v2.z; acc[11] += p*v2.w;
        acc[12] += p*v3.x; acc[13] += p*v3.y; acc[14] += p*v3.z; acc[15] += p*v3.w;
    }
}

// grid (25, Hh, Bsz), 128 threads. x<24: sparse (qtile=x/3, kseg=x%3).
// x==24: dense rows {0, Nn} (64 threads each).
__global__ void k_attn(const float* __restrict__ coords)
{
    __shared__ float Ks[128][20];
    __shared__ float Vs[128][20];
    __shared__ float ckx[128], cky[128];
    __shared__ float qes[128][33];
    __shared__ float pw[4][17];
    int b = blockIdx.z, h = blockIdx.y;
    int x = blockIdx.x;
    int tid = threadIdx.x;
    const size_t hb = (size_t)(b*Hh + h)*N1;

    if (x == 24) {   // ---- dense rows ----
        int sub = tid >> 6, st = tid & 63;
        int lane = tid & 31, w = tid >> 5;
        int n = sub ? Nn : 0;
        float q[16];
        const float4* qp = (const float4*)(d_Q + (hb + n)*Dk);
        #pragma unroll
        for (int i = 0; i < 4; i++) {
            float4 v = qp[i];
            q[i*4+0]=v.x; q[i*4+1]=v.y; q[i*4+2]=v.z; q[i*4+3]=v.w;
        }
        float cqx = 0.f, cqy = 0.f;
        if (n < Nn) { cqx = coords[(b*Nn+n)*2]; cqy = coords[(b*Nn+n)*2+1]; }
        const float* qerow = d_QE + (hb + n)*NBk;
        float l = 0.f, acc[16];
        #pragma unroll
        for (int d = 0; d < 16; d++) acc[d] = 0.f;
        const float* Kt = d_Kb + hb*Dk;
        const float* Vt = d_Vb + hb*Dk;
        for (int mk = st; mk < N1; mk += 64) {
            const float4* kp = (const float4*)(Kt + (size_t)mk*Dk);
            float s = 0.f;
            #pragma unroll
            for (int i = 0; i < 4; i++) {
                float4 kv = kp[i];
                s += q[i*4+0]*kv.x + q[i*4+1]*kv.y + q[i*4+2]*kv.z + q[i*4+3]*kv.w;
            }
            float cmx = 0.f, cmy = 0.f;
            if (mk < Nn) { cmx = coords[(b*Nn+mk)*2]; cmy = coords[(b*Nn+mk)*2+1]; }
            float dx = cqx - cmx, dy = cqy - cmy;
            float dist = sqrtf(dx*dx + dy*dy);
            int bk = (int)(dist * 32.f); if (bk > 31) bk = 31;
            float p = __expf(s*SCALEf + qerow[bk]);
            l += p;
            const float4* vp = (const float4*)(Vt + (size_t)mk*Dk);
            #pragma unroll
            for (int i = 0; i < 4; i++) {
                float4 vv = vp[i];
                acc[i*4+0] += p*vv.x; acc[i*4+1] += p*vv.y;
                acc[i*4+2] += p*vv.z; acc[i*4+3] += p*vv.w;
            }
        }
        #pragma unroll
        for (int o = 16; o; o >>= 1) {
            l += __shfl_xor_sync(0xffffffffu, l, o);
            #pragma unroll
            for (int d = 0; d < 16; d++) acc[d] += __shfl_xor_sync(0xffffffffu, acc[d], o);
        }
        if (lane == 0) {
            #pragma unroll
            for (int d = 0; d < 16; d++) pw[w][d] = acc[d];
            pw[w][16] = l;
        }
        __syncthreads();
        if (tid == 0 || tid == 64) {
            int w0 = sub*2;
            float L = pw[w0][16] + pw[w0+1][16];
            float inv = 1.f / L;
            float* o = d_CTX + ((size_t)(b*N1 + n))*Dm + h*Dk;
            #pragma unroll
            for (int d = 0; d < 16; d++) o[d] = (pw[w0][d] + pw[w0+1][d]) * inv;
        }
        return;
    }

    // ---- sparse split-K ----
    int qt = x / 3, kseg = x % 3;
    int n = qt*128 + tid;              // 0..1023
    bool qv = (n != 0);                // row 0 is dense
    float4 q4[4];
    float cqx = 0.f, cqy = 0.f, lrun = 0.f;
    float acc[16];
    #pragma unroll
    for (int d = 0; d < 16; d++) acc[d] = 0.f;
    const unsigned* rowadj = d_ADJ + (size_t)(b*N1 + n)*AW;
    {
        const float4* qp = (const float4*)(d_Q + (hb + n)*Dk);
        #pragma unroll
        for (int i = 0; i < 4; i++) q4[i] = qp[i];
        cqx = coords[(b*Nn+n)*2]; cqy = coords[(b*Nn+n)*2+1];
        const float4* qep = (const float4*)(d_QE + (hb + n)*NBk);
        #pragma unroll
        for (int i = 0; i < 8; i++) {
            float4 v = qep[i];
            qes[tid][i*4+0]=v.x; qes[tid][i*4+1]=v.y;
            qes[tid][i*4+2]=v.z; qes[tid][i*4+3]=v.w;
        }
    }
    for (int kt = kseg*3; kt < kseg*3 + 3; kt++) {
        int m0 = kt*128;
        int tlen = N1 - m0; if (tlen > 128) tlen = 128;
        const float4* Kt = (const float4*)(d_Kb + (hb + m0)*Dk);
        const float4* Vt = (const float4*)(d_Vb + (hb + m0)*Dk);
        __syncthreads();
        #pragma unroll
        for (int i = 0; i < 4; i++) {
            int f = tid + i*128;
            int row = f >> 2, j = (f & 3)*4;
            if (row < tlen) {
                *(float4*)&Ks[row][j] = Kt[f];
                *(float4*)&Vs[row][j] = Vt[f];
            }
        }
        if (tid < tlen) {
            int m = m0 + tid;
            if (m < Nn) { ckx[tid] = coords[(b*Nn+m)*2]; cky[tid] = coords[(b*Nn+m)*2+1]; }
            else        { ckx[tid] = 0.f; cky[tid] = 0.f; }
        }
        __syncthreads();
        if (!qv) continue;
        int wb = m0 >> 5;
        unsigned w0 = rowadj[wb];
        unsigned w1 = (wb+1 < AW) ? rowadj[wb+1] : 0u;
        unsigned w2 = (wb+2 < AW) ? rowadj[wb+2] : 0u;
        unsigned w3 = (wb+3 < AW) ? rowadj[wb+3] : 0u;
        attn_word20(w0,  0, q4, cqx, cqy, Ks, Vs, ckx, cky, qes[tid], lrun, acc);
        attn_word20(w1, 32, q4, cqx, cqy, Ks, Vs, ckx, cky, qes[tid], lrun, acc);
        attn_word20(w2, 64, q4, cqx, cqy, Ks, Vs, ckx, cky, qes[tid], lrun, acc);
        attn_word20(w3, 96, q4, cqx, cqy, Ks, Vs, ckx, cky, qes[tid], lrun, acc);
    }
    if (qv) {
        size_t base = ((size_t)kseg*Bsz*N1 + (size_t)b*N1 + n)*Hh + h;
        float* pa = d_PA + base*17;
        #pragma unroll
        for (int d = 0; d < 16; d++) pa[d] = acc[d];
        pa[16] = lrun;
    }
}

// ------------------------- combine split-K partials --------------------------
__global__ void k_comb()
{
    int u = blockIdx.x*blockDim.x + threadIdx.x;   // (b*N1+n)*Hh + h
    if (u >= Bsz*N1*Hh) return;
    int h = u & 7;
    int r = u >> 3;
    int n = (r >= N1) ? r - N1 : r;
    if (n == 0 || n == Nn) return;                  // dense rows written directly
    const int ST = Bsz*N1*Hh*17;
    int base = u*17;
    float l = d_PA[base+16] + d_PA[ST+base+16] + d_PA[2*ST+base+16];
    float inv = 1.f / l;
    float* o = d_CTX + (size_t)r*Dm + h*Dk;
    #pragma unroll
    for (int d = 0; d < 16; d++)
        o[d] = (d_PA[base+d] + d_PA[ST+base+d] + d_PA[2*ST+base+d]) * inv;
}

// ------------------------- instance norm: stats (partials) -------------------
__global__ void k_istat(const float* __restrict__ src)
{
    __shared__ float s1[2][Dm], s2[2][Dm];
    int b = blockIdx.x, z = blockIdx.y;
    int d = threadIdx.x & 127, g = threadIdx.x >> 7;
    int nend = z*64 + 64; if (nend > N1) nend = N1;
    const float* p = src + (size_t)b*N1*Dm + d;
    float a = 0.f, qq = 0.f;
    for (int n = z*64 + g; n < nend; n += 2) {
        float x = p[(size_t)n*Dm];
        a += x; qq += x*x;
    }
    s1[g][d] = a; s2[g][d] = qq;
    __syncthreads();
    if (g == 0) {
        d_PS1[(b*NCH + z)*Dm + d] = s1[0][d] + s1[1][d];
        d_PS2[(b*NCH + z)*Dm + d] = s2[0][d] + s2[1][d];
    }
}

// ------------------------- instance norm: apply ------------------------------
__global__ void k_iapply(const float* __restrict__ src, float* __restrict__ dst,
                         const float* __restrict__ w, const float* __restrict__ bb, int fuse)
{
    int b  = blockIdx.x;
    int dl = threadIdx.x & 31;
    int g  = threadIdx.x >> 5;
    int d  = blockIdx.y*32 + dl;
    int z  = blockIdx.z;
    float S1 = 0.f, S2 = 0.f;
    #pragma unroll
    for (int t = 0; t < NCH; t++) {
        S1 += d_PS1[(b*NCH + t)*Dm + d];
        S2 += d_PS2[(b*NCH + t)*Dm + d];
    }
    float mu  = S1 * (1.f/N1);
    float var = S2 * (1.f/N1) - mu*mu;
    float sc  = rsqrtf(var + EPSf) * w[d];
    float sh  = bb[d];
    const float* p = src + (size_t)b*N1*Dm + d;
    float* o = dst + (size_t)b*N1*Dm + d;
    float mo = 0.f;
    if (fuse) mo = ((S1 - p[(size_t)Nn*Dm])*(1.f/Nn) - mu)*sc + sh;
    int n0 = z*128, n1 = (z == 7) ? N1 : (z+1)*128;
    for (int n = n0 + g; n < n1; n += 32) {
        float val = (p[(size_t)n*Dm] - mu)*sc + sh;
        if (fuse && n == Nn) val += mo;
        o[(size_t)n*Dm] = val;
    }
    if (fuse && z == 7 && g == 0) d_POOL[b*Dm + d] += mo;
}

// ------------------------- final GEMM: out = (h + pool/3) @ outW^T + outb ----
__global__ void k_fgemm(const float* __restrict__ Bm, const float* __restrict__ bias,
                        float* __restrict__ out)
{
    __shared__ __align__(16) float As[2][16][68];
    __shared__ __align__(16) float Bs[2][16][68];
    int tid = threadIdx.x;
    int tr = tid >> 4, tc = tid & 15;
    int r0 = blockIdx.y*64, c0 = blockIdx.x*64;
    int lr = tid >> 2;
    int lc = (tid & 3) * 4;
    int gr = r0 + lr;
    int bb = gr >> 10, nn = gr & 1023;
    const float* Arow = d_HG + ((size_t)bb*N1 + nn)*Dm;
    const float* Prow = d_POOL + bb*Dm;
    int gc = c0 + lr;
    if (blockIdx.x == 0 && blockIdx.y == 0 && tid < Bsz*Dm)
        out[Bsz*Nn*Dm + tid] = d_POOL[tid] * (1.f/3.f);
    float4 va, vb;
    {
        float4 hv = *(const float4*)(Arow + lc);
        float4 pv = *(const float4*)(Prow + lc);
        va = make_float4(hv.x + pv.x*(1.f/3.f), hv.y + pv.y*(1.f/3.f),
                         hv.z + pv.z*(1.f/3.f), hv.w + pv.w*(1.f/3.f));
        vb = *(const float4*)(Bm + (size_t)gc*Dm + lc);
    }
    As[0][lc+0][lr]=va.x; As[0][lc+1][lr]=va.y; As[0][lc+2][lr]=va.z; As[0][lc+3][lr]=va.w;
    Bs[0][lc+0][lr]=vb.x; Bs[0][lc+1][lr]=vb.y; Bs[0][lc+2][lr]=vb.z; Bs[0][lc+3][lr]=vb.w;
    __syncthreads();
    float acc[4][4] = {};
    #pragma unroll
    for (int s = 0; s < 8; s++) {
        int cur = s & 1;
        if (s < 7) {
            float4 hv = *(const float4*)(Arow + (s+1)*16 + lc);
            float4 pv = *(const float4*)(Prow + (s+1)*16 + lc);
            va = make_float4(hv.x + pv.x*(1.f/3.f), hv.y + pv.y*(1.f/3.f),
                             hv.z + pv.z*(1.f/3.f), hv.w + pv.w*(1.f/3.f));
            vb = *(const float4*)(Bm + (size_t)gc*Dm + (s+1)*16 + lc);
        }
        #pragma unroll
        for (int k = 0; k < 16; k++) {
            float4 a4 = *(const float4*)&As[cur][k][tr*4];
            float4 b4 = *(const float4*)&Bs[cur][k][tc*4];
            float a[4] = {a4.x, a4.y, a4.z, a4.w};
            float bv[4] = {b4.x, b4.y, b4.z, b4.w};
            #pragma unroll
            for (int i = 0; i < 4; i++)
                #pragma unroll
                for (int j = 0; j < 4; j++) acc[i][j] += a[i]*bv[j];
        }
        if (s < 7) {
            int nxt = cur ^ 1;
            As[nxt][lc+0][lr]=va.x; As[nxt][lc+1][lr]=va.y; As[nxt][lc+2][lr]=va.z; As[nxt][lc+3][lr]=va.w;
            Bs[nxt][lc+0][lr]=vb.x; Bs[nxt][lc+1][lr]=vb.y; Bs[nxt][lc+2][lr]=vb.z; Bs[nxt][lc+3][lr]=vb.w;
            __syncthreads();
        }
    }
    int c = c0 + tc*4;
    float4 bz = *(const float4*)(bias + c);
    #pragma unroll
    for (int i = 0; i < 4; i++) {
        int r = r0 + tr*4 + i;
        *(float4*)(out + (size_t)r*Dm + c) =
            make_float4(acc[i][0]+bz.x, acc[i][1]+bz.y, acc[i][2]+bz.z, acc[i][3]+bz.w);
    }
}

// ------------------------- host driver ---------------------------------------
extern "C" void kernel_launch(void* const* d_in, const int* in_sizes, int n_in,
                              void* d_out, int out_size)
{
    const float* coords = (const float*)d_in[0];
    const float* in_W   = (const float*)d_in[1];
    const float* in_b   = (const float*)d_in[2];
    const float* gnode  = (const float*)d_in[3];
    const float* Wq     = (const float*)d_in[4];
    const float* Wk     = (const float*)d_in[5];
    const float* Wv     = (const float*)d_in[6];
    const float* Wo     = (const float*)d_in[7];
    const float* emb    = (const float*)d_in[8];
    const float* W1     = (const float*)d_in[9];
    const float* b1     = (const float*)d_in[10];
    const float* W2     = (const float*)d_in[11];
    const float* b2     = (const float*)d_in[12];
    const float* n1w    = (const float*)d_in[13];
    const float* n1b    = (const float*)d_in[14];
    const float* n2w    = (const float*)d_in[15];
    const float* n2b    = (const float*)d_in[16];
    const float* outW   = (const float*)d_in[17];
    const float* outb   = (const float*)d_in[18];
    float* out = (float*)d_out;

    float *HG, *CTX, *Y, *T1, *T2;
    cudaGetSymbolAddress((void**)&HG,  d_HG);
    cudaGetSymbolAddress((void**)&CTX, d_CTX);
    cudaGetSymbolAddress((void**)&Y,   d_Y);
    cudaGetSymbolAddress((void**)&T1,  d_T1);
    cudaGetSymbolAddress((void**)&T2,  d_T2);

    const int Mall = Bsz*N1;  // 2050

    k_input<<<(Bsz*N1*Dm + 255)/256, 256>>>(coords, in_W, in_b, gnode);
    k_colmean<<<Bsz, 1024>>>();                            // layer-0 g update

    for (int l = 0; l < 3; l++) {
        k_par1<<<983, 256>>>(Wq + (size_t)l*Dm*Dm, Wk + (size_t)l*Dm*Dm, Wv + (size_t)l*Dm*Dm);
        k_par2<<<2306, 256>>>(emb + (size_t)l*NBk*Dm);
        { dim3 ga(25, Hh, Bsz); k_attn<<<ga, 128>>>(coords); }
        k_comb<<<(Bsz*N1*Hh + 127)/128, 128>>>();

        { dim3 gq(Dm/64, (Mall + 31)/32);
          k_gemmS<<<gq, 256>>>(CTX, Wo + (size_t)l*Dm*Dm, nullptr, HG, Y, Mall, Dm, Dm, 2); }
        { dim3 gs(Bsz, NCH); k_istat<<<gs, 256>>>(Y); }
        { dim3 gi(Bsz, 4, 8); k_iapply<<<gi, 1024>>>(Y, Y, n1w + l*Dm, n1b + l*Dm, 0); }

        { dim3 g1(Dff/64, (Mall + 63)/64);
          k_gemm<<<g1, 256>>>(Y,  W1 + (size_t)l*Dff*Dm, b1 + l*Dff, nullptr, T1, Mall, Dff, Dm, 1|4); }
        { dim3 g2(Dm/64, (Mall + 31)/32);
          k_gemmS<<<g2, 256>>>(T1, W2 + (size_t)l*Dm*Dff, b2 + l*Dm, Y, T2, Mall, Dm, Dff, 1|2); }
        { dim3 gs(Bsz, NCH); k_istat<<<gs, 256>>>(T2); }
        { dim3 gi(Bsz, 4, 8); k_iapply<<<gi, 1024>>>(T2, HG, n2w + l*Dm, n2b + l*Dm, 1); }
    }

    { dim3 ge(Dm/64, (Bsz*Nn)/64); k_fgemm<<<ge, 256>>>(outW, outb, out); }
}

// round 9
// speedup vs baseline: 5.6951x; 1.1799x over previous
#include <cuda_runtime.h>
#include <math_constants.h>
#include <math.h>

#define Bsz 2
#define Nn 1024
#define N1 1025
#define Dm 128
#define Hh 8
#define Dk 16
#define Dff 512
#define NBk 32
#define KNN 10
#define AW 33          // 33 x 32-bit words cover 1025 mask bits per row
#define EPSf 1e-5f
#define SCALEf 0.25f   // 1/sqrt(16)
#define NCH 17         // inorm stat chunks

// ------------------------- persistent device scratch -------------------------
__device__ float    d_HG [Bsz*N1*Dm];     // state: rows 0..1023 = h, row 1024 = g
__device__ float    d_POOL[Bsz*Dm];
__device__ float    d_D2 [(size_t)Bsz*Nn*Nn];
__device__ unsigned d_ADJ[Bsz*N1*AW];
__device__ float    d_Q  [Bsz*Hh*N1*Dk];  // head-major: [b][h][n][dk]
__device__ float    d_Kb [Bsz*Hh*N1*Dk];
__device__ float    d_Vb [Bsz*Hh*N1*Dk];
__device__ float    d_CTX[Bsz*N1*Dm];
__device__ float    d_QE [Bsz*Hh*N1*NBk]; // head-major: [b][h][n][bucket]
__device__ float    d_Y  [Bsz*N1*Dm];
__device__ float    d_T1 [Bsz*N1*Dff];
__device__ float    d_T2 [Bsz*N1*Dm];
__device__ float    d_PS1[Bsz*NCH*Dm];
__device__ float    d_PS2[Bsz*NCH*Dm];
__device__ float    d_PA [3*Bsz*N1*Hh*17];  // split-K partials: acc[16]+lrun

// ------------------------- input embedding + state init ----------------------
__global__ void k_input(const float* __restrict__ coords, const float* __restrict__ inW,
                        const float* __restrict__ inb, const float* __restrict__ gnode)
{
    int gid = blockIdx.x*blockDim.x + threadIdx.x;
    if (gid < Bsz*Dm) d_POOL[gid] = 0.f;
    if (gid >= Bsz*N1*Dm) return;
    int d = gid % Dm;
    int n = (gid / Dm) % N1;
    int b = gid / (Dm*N1);
    float v;
    if (n < Nn) {
        float x = coords[(b*Nn+n)*2+0];
        float y = coords[(b*Nn+n)*2+1];
        v = x*inW[d*2+0] + y*inW[d*2+1] + inb[d];
    } else {
        v = gnode[d];
    }
    d_HG[gid] = v;
}

// ------------------------- layer-0 g update: g += mean(h) --------------------
__global__ void k_colmean()
{
    __shared__ float red[8][Dm];
    int b = blockIdx.x;
    int d = threadIdx.x & 127;
    int g = threadIdx.x >> 7;
    const float* base = d_HG + (size_t)b*N1*Dm;
    float s = 0.f;
    for (int n = g; n < Nn; n += 8) s += base[n*Dm + d];
    red[g][d] = s;
    __syncthreads();
    if (g == 0) {
        float t = 0.f;
        #pragma unroll
        for (int i = 0; i < 8; i++) t += red[i][d];
        d_HG[(size_t)b*N1*Dm + Nn*Dm + d] += t * (1.f/Nn);
    }
}

// ===================== PAR1: D2 (self-norms) + QKV + ADJ-init =================
// grid: [0,272) d2 tiles, [272,470) qkv, [470,983) adjacency rows. 256 threads.
__global__ void k_par1(const float* __restrict__ wq, const float* __restrict__ wk,
                       const float* __restrict__ wv)
{
    __shared__ __align__(16) float As[2][16][68];
    __shared__ __align__(16) float Bs[2][16][68];
    __shared__ float rsq[64], csq[64];
    int bx = blockIdx.x;
    int tid = threadIdx.x;

    if (bx < 272) {        // ---------- D2 symmetric tile ----------
        int b = bx / 136;
        int x = bx % 136, bi = 0;
        while (x >= 16 - bi) { x -= 16 - bi; bi++; }
        int bj = bi + x;
        const float* A = d_HG + (size_t)b*N1*Dm;
        int tr = tid >> 4, tc = tid & 15;
        int r0 = bi*64, c0 = bj*64;
        int lr = tid >> 2, lc = (tid & 3)*4;
        float rn = 0.f, cn = 0.f;
        float4 va = *(const float4*)(A + (size_t)(r0+lr)*Dm + lc);
        float4 vb = *(const float4*)(A + (size_t)(c0+lr)*Dm + lc);
        rn += va.x*va.x + va.y*va.y + va.z*va.z + va.w*va.w;
        cn += vb.x*vb.x + vb.y*vb.y + vb.z*vb.z + vb.w*vb.w;
        As[0][lc+0][lr]=va.x; As[0][lc+1][lr]=va.y; As[0][lc+2][lr]=va.z; As[0][lc+3][lr]=va.w;
        Bs[0][lc+0][lr]=vb.x; Bs[0][lc+1][lr]=vb.y; Bs[0][lc+2][lr]=vb.z; Bs[0][lc+3][lr]=vb.w;
        __syncthreads();
        float acc[4][4] = {};
        #pragma unroll
        for (int s = 0; s < 8; s++) {
            int cur = s & 1;
            if (s < 7) {
                va = *(const float4*)(A + (size_t)(r0+lr)*Dm + (s+1)*16 + lc);
                vb = *(const float4*)(A + (size_t)(c0+lr)*Dm + (s+1)*16 + lc);
                rn += va.x*va.x + va.y*va.y + va.z*va.z + va.w*va.w;
                cn += vb.x*vb.x + vb.y*vb.y + vb.z*vb.z + vb.w*vb.w;
            }
            #pragma unroll
            for (int k = 0; k < 16; k++) {
                float4 a4 = *(const float4*)&As[cur][k][tr*4];
                float4 b4 = *(const float4*)&Bs[cur][k][tc*4];
                float a[4] = {a4.x, a4.y, a4.z, a4.w};
                float bv[4] = {b4.x, b4.y, b4.z, b4.w};
                #pragma unroll
                for (int i = 0; i < 4; i++)
                    #pragma unroll
                    for (int j = 0; j < 4; j++) acc[i][j] += a[i]*bv[j];
            }
            if (s < 7) {
                int nxt = cur ^ 1;
                As[nxt][lc+0][lr]=va.x; As[nxt][lc+1][lr]=va.y; As[nxt][lc+2][lr]=va.z; As[nxt][lc+3][lr]=va.w;
                Bs[nxt][lc+0][lr]=vb.x; Bs[nxt][lc+1][lr]=vb.y; Bs[nxt][lc+2][lr]=vb.z; Bs[nxt][lc+3][lr]=vb.w;
                __syncthreads();
            }
        }
        rn += __shfl_xor_sync(0xffffffffu, rn, 1);
        rn += __shfl_xor_sync(0xffffffffu, rn, 2);
        cn += __shfl_xor_sync(0xffffffffu, cn, 1);
        cn += __shfl_xor_sync(0xffffffffu, cn, 2);
        if ((tid & 3) == 0) { rsq[lr] = rn; csq[lr] = cn; }
        __syncthreads();
        float vals[4][4];
        #pragma unroll
        for (int i = 0; i < 4; i++) {
            int r = r0 + tr*4 + i;
            float sqr = rsq[tr*4 + i];
            float* orow = d_D2 + ((size_t)b*Nn + r)*Nn + c0 + tc*4;
            float o[4];
            #pragma unroll
            for (int j = 0; j < 4; j++) {
                int c = c0 + tc*4 + j;
                float v = sqr + csq[tc*4 + j] - 2.f*acc[i][j];
                o[j] = (r == c) ? CUDART_INF_F : v;
                vals[i][j] = o[j];
            }
            *(float4*)orow = make_float4(o[0], o[1], o[2], o[3]);
        }
        if (bi != bj) {
            #pragma unroll
            for (int j = 0; j < 4; j++) {
                int c = c0 + tc*4 + j;
                float* orow = d_D2 + ((size_t)b*Nn + c)*Nn + r0 + tr*4;
                *(float4*)orow = make_float4(vals[0][j], vals[1][j], vals[2][j], vals[3][j]);
            }
        }
        return;
    }

    if (bx < 470) {        // ---------- QKV GEMM ----------
        int idx = bx - 272;
        int sel = idx / 66, rem = idx % 66;
        const float* Bm = (sel == 0) ? wq : (sel == 1) ? wk : wv;
        float* C = (sel == 0) ? d_Q : (sel == 1) ? d_Kb : d_Vb;
        const int M = Bsz*N1;
        int tr = tid >> 4, tc = tid & 15;
        int r0 = (rem >> 1)*64, c0 = (rem & 1)*64;
        int lr = tid >> 2, lc = (tid & 3)*4;
        int gr = r0 + lr, gc = c0 + lr;
        const float4 z4 = make_float4(0.f,0.f,0.f,0.f);
        float4 va = (gr < M) ? *(const float4*)(d_HG + (size_t)gr*Dm + lc) : z4;
        float4 vb = *(const float4*)(Bm + (size_t)gc*Dm + lc);
        As[0][lc+0][lr]=va.x; As[0][lc+1][lr]=va.y; As[0][lc+2][lr]=va.z; As[0][lc+3][lr]=va.w;
        Bs[0][lc+0][lr]=vb.x; Bs[0][lc+1][lr]=vb.y; Bs[0][lc+2][lr]=vb.z; Bs[0][lc+3][lr]=vb.w;
        __syncthreads();
        float acc[4][4] = {};
        #pragma unroll
        for (int s = 0; s < 8; s++) {
            int cur = s & 1;
            if (s < 7) {
                va = (gr < M) ? *(const float4*)(d_HG + (size_t)gr*Dm + (s+1)*16 + lc) : z4;
                vb = *(const float4*)(Bm + (size_t)gc*Dm + (s+1)*16 + lc);
            }
            #pragma unroll
            for (int k = 0; k < 16; k++) {
                float4 a4 = *(const float4*)&As[cur][k][tr*4];
                float4 b4 = *(const float4*)&Bs[cur][k][tc*4];
                float a[4] = {a4.x, a4.y, a4.z, a4.w};
                float bv[4] = {b4.x, b4.y, b4.z, b4.w};
                #pragma unroll
                for (int i = 0; i < 4; i++)
                    #pragma unroll
                    for (int j = 0; j < 4; j++) acc[i][j] += a[i]*bv[j];
            }
            if (s < 7) {
                int nxt = cur ^ 1;
                As[nxt][lc+0][lr]=va.x; As[nxt][lc+1][lr]=va.y; As[nxt][lc+2][lr]=va.z; As[nxt][lc+3][lr]=va.w;
                Bs[nxt][lc+0][lr]=vb.x; Bs[nxt][lc+1][lr]=vb.y; Bs[nxt][lc+2][lr]=vb.z; Bs[nxt][lc+3][lr]=vb.w;
                __syncthreads();
            }
        }
        int c = c0 + tc*4;
        int h  = c >> 4;
        int dk = c & 15;
        #pragma unroll
        for (int i = 0; i < 4; i++) {
            int r = r0 + tr*4 + i;
            if (r >= M) continue;
            int bb = (r >= N1) ? 1 : 0;
            int n  = r - bb*N1;
            *(float4*)(C + ((size_t)(bb*Hh + h)*N1 + n)*Dk + dk) =
                make_float4(acc[i][0], acc[i][1], acc[i][2], acc[i][3]);
        }
        return;
    }

    // ---------- adjacency base pattern ----------
    {
        int row = (bx - 470)*4 + (tid >> 6);
        int t = tid & 63;
        if (row >= Bsz*N1 || t >= AW) return;
        int i = row % N1;
        int w = t;
        unsigned bits = 0u;
        #pragma unroll 4
        for (int q = 0; q < 32; q++) {
            int m = w*32 + q;
            if (m > Nn) break;
            bool on;
            if (i == Nn || m == Nn || i == m || i == 0 || m == 0) on = true;
            else {
                int di = i - m; if (di < 0) di = -di;
                on = ((i >> 7) == (m >> 7)) && (di <= 11);   // hier adjacency
            }
            if (on) bits |= 1u << q;
        }
        d_ADJ[row*AW + w] = bits;
    }
}

// ===================== PAR2: topk (u32 keys) + qe (8 rows/block) ==============
// grid: [0,256) topk (8 warps/block), [256,513) qe (8 rows/block). 256 threads.
__global__ void k_par2(const float* __restrict__ emb)
{
    int bx = blockIdx.x;
    int tid = threadIdx.x;
    if (bx < 256) {        // ---------- exact top-10 kNN ----------
        int warp = bx*8 + (tid >> 5);
        int lane = tid & 31;
        int b = warp >> 10, i = warp & 1023;
        const float* row = d_D2 + (size_t)warp*Nn;
        unsigned uv[32];
        #pragma unroll
        for (int t = 0; t < 32; t++) {
            unsigned u = __float_as_uint(row[t*32 + lane]);
            uv[t] = (u & 0x80000000u) ? ~u : (u | 0x80000000u);
        }
        unsigned* adjb = d_ADJ + (size_t)b*N1*AW;
        for (int r = 0; r < KNN; r++) {
            // 4-way ILP min chains over this lane's 32 keys
            unsigned m0 = uv[0], m1 = uv[1], m2 = uv[2], m3 = uv[3];
            #pragma unroll
            for (int t = 4; t < 32; t += 4) {
                m0 = min(m0, uv[t+0]); m1 = min(m1, uv[t+1]);
                m2 = min(m2, uv[t+2]); m3 = min(m3, uv[t+3]);
            }
            unsigned mm = min(min(m0, m1), min(m2, m3));
            #pragma unroll
            for (int o = 16; o; o >>= 1)
                mm = min(mm, __shfl_xor_sync(0xffffffffu, mm, o));
            // recover lowest global index j with key == mm
            int lj = 0x7FFFFFFF;
            #pragma unroll
            for (int t = 0; t < 32; t++)
                if (uv[t] == mm) { lj = t*32 + lane; break; }   // lowest t first
            #pragma unroll
            for (int o = 16; o; o >>= 1)
                lj = min(lj, __shfl_xor_sync(0xffffffffu, lj, o));
            if (lane == (lj & 31)) uv[lj >> 5] = 0xFFFFFFFFu;
            if (lane == 0) {
                atomicOr(&adjb[i*AW + (lj >> 5)], 1u << (lj & 31));
                atomicOr(&adjb[lj*AW + (i >> 5)], 1u << (i & 31));
            }
        }
        return;
    }
    // ---------- qe: 8 rows per block ----------
    __shared__ float qs[8][Dm];
    int r0 = (bx - 256)*8;             // first global row (b*N1+n)
    // stage 8 q-rows into smem (head-major gather)
    if (tid < 128) {
        int hh = tid >> 4, dk = tid & 15;
        #pragma unroll
        for (int r = 0; r < 8; r++) {
            int row = r0 + r;
            if (row >= Bsz*N1) break;
            int b = (row >= N1) ? 1 : 0;
            int n = row - b*N1;
            qs[r][tid] = d_Q[((size_t)(b*Hh + hh)*N1 + n)*Dk + dk];
        }
    }
    __syncthreads();
    int h = tid >> 5, kb = tid & 31;
    float e[16];
    const float* ep = emb + kb*Dm + h*Dk;
    #pragma unroll
    for (int d = 0; d < 16; d++) e[d] = ep[d];
    #pragma unroll
    for (int r = 0; r < 8; r++) {
        int row = r0 + r;
        if (row >= Bsz*N1) break;
        int b = (row >= N1) ? 1 : 0;
        int n = row - b*N1;
        const float* q = qs[r] + h*Dk;
        float s = 0.f;
        #pragma unroll
        for (int d = 0; d < 16; d++) s += q[d]*e[d];
        d_QE[((size_t)(b*Hh + h)*N1 + n)*NBk + kb] = s;
    }
}

// ------------------------- generic SGEMM 64x64 (double-buffered) -------------
__global__ void k_gemm(const float* __restrict__ A, const float* __restrict__ Bm,
                       const float* __restrict__ bias, const float* __restrict__ res,
                       float* __restrict__ C, int M, int Nc, int K, int flags)
{
    __shared__ __align__(16) float As[2][16][68];
    __shared__ __align__(16) float Bs[2][16][68];
    int tid = threadIdx.x;
    int tr = tid >> 4, tc = tid & 15;
    int r0 = blockIdx.y*64, c0 = blockIdx.x*64;
    int lr = tid >> 2;
    int lc = (tid & 3) * 4;
    int gr = r0 + lr, gc = c0 + lr;
    const float4 z4 = make_float4(0.f,0.f,0.f,0.f);
    float4 va = (gr < M) ? *(const float4*)(A + (size_t)gr*K + lc) : z4;
    float4 vb = *(const float4*)(Bm + (size_t)gc*K + lc);
    As[0][lc+0][lr]=va.x; As[0][lc+1][lr]=va.y; As[0][lc+2][lr]=va.z; As[0][lc+3][lr]=va.w;
    Bs[0][lc+0][lr]=vb.x; Bs[0][lc+1][lr]=vb.y; Bs[0][lc+2][lr]=vb.z; Bs[0][lc+3][lr]=vb.w;
    __syncthreads();
    float acc[4][4] = {};
    int S = K >> 4;
    for (int s = 0; s < S; s++) {
        int cur = s & 1;
        if (s + 1 < S) {
            va = (gr < M) ? *(const float4*)(A + (size_t)gr*K + (s+1)*16 + lc) : z4;
            vb = *(const float4*)(Bm + (size_t)gc*K + (s+1)*16 + lc);
        }
        #pragma unroll
        for (int k = 0; k < 16; k++) {
            float4 a4 = *(const float4*)&As[cur][k][tr*4];
            float4 b4 = *(const float4*)&Bs[cur][k][tc*4];
            float a[4] = {a4.x, a4.y, a4.z, a4.w};
            float bv[4] = {b4.x, b4.y, b4.z, b4.w};
            #pragma unroll
            for (int i = 0; i < 4; i++)
                #pragma unroll
                for (int j = 0; j < 4; j++) acc[i][j] += a[i]*bv[j];
        }
        if (s + 1 < S) {
            int nxt = cur ^ 1;
            As[nxt][lc+0][lr]=va.x; As[nxt][lc+1][lr]=va.y; As[nxt][lc+2][lr]=va.z; As[nxt][lc+3][lr]=va.w;
            Bs[nxt][lc+0][lr]=vb.x; Bs[nxt][lc+1][lr]=vb.y; Bs[nxt][lc+2][lr]=vb.z; Bs[nxt][lc+3][lr]=vb.w;
            __syncthreads();
        }
    }
    int c = c0 + tc*4;
    float4 bz = z4;
    if (flags & 1) bz = *(const float4*)(bias + c);
    #pragma unroll
    for (int i = 0; i < 4; i++) {
        int r = r0 + tr*4 + i;
        if (r >= M) continue;
        float4 v = make_float4(acc[i][0]+bz.x, acc[i][1]+bz.y, acc[i][2]+bz.z, acc[i][3]+bz.w);
        if (flags & 2) {
            float4 rv = *(const float4*)(res + (size_t)r*Nc + c);
            v.x += rv.x; v.y += rv.y; v.z += rv.z; v.w += rv.w;
        }
        if (flags & 4) {
            v.x = fmaxf(v.x, 0.f); v.y = fmaxf(v.y, 0.f);
            v.z = fmaxf(v.z, 0.f); v.w = fmaxf(v.w, 0.f);
        }
        *(float4*)(C + (size_t)r*Nc + c) = v;
    }
}

// ------------------------- SGEMM 32x64 tile (better chip fill) ---------------
__global__ void k_gemmS(const float* __restrict__ A, const float* __restrict__ Bm,
                        const float* __restrict__ bias, const float* __restrict__ res,
                        float* __restrict__ C, int M, int Nc, int K, int flags)
{
    __shared__ __align__(16) float As[2][16][36];
    __shared__ __align__(16) float Bs[2][16][68];
    int tid = threadIdx.x;
    int tr = tid >> 4, tc = tid & 15;
    int r0 = blockIdx.y*32, c0 = blockIdx.x*64;
    int lr = tid >> 2;
    int lc = (tid & 3) * 4;
    bool aload = tid < 128;
    int ar = tid >> 2;                 // 0..31 for tid<128
    int gr = r0 + ar, gc = c0 + lr;
    const float4 z4 = make_float4(0.f,0.f,0.f,0.f);
    float4 va = (aload && gr < M) ? *(const float4*)(A + (size_t)gr*K + lc) : z4;
    float4 vb = *(const float4*)(Bm + (size_t)gc*K + lc);
    if (aload) {
        As[0][lc+0][ar]=va.x; As[0][lc+1][ar]=va.y; As[0][lc+2][ar]=va.z; As[0][lc+3][ar]=va.w;
    }
    Bs[0][lc+0][lr]=vb.x; Bs[0][lc+1][lr]=vb.y; Bs[0][lc+2][lr]=vb.z; Bs[0][lc+3][lr]=vb.w;
    __syncthreads();
    float acc[2][4] = {};
    int S = K >> 4;
    for (int s = 0; s < S; s++) {
        int cur = s & 1;
        if (s + 1 < S) {
            va = (aload && gr < M) ? *(const float4*)(A + (size_t)gr*K + (s+1)*16 + lc) : z4;
            vb = *(const float4*)(Bm + (size_t)gc*K + (s+1)*16 + lc);
        }
        #pragma unroll
        for (int k = 0; k < 16; k++) {
            float2 a2 = *(const float2*)&As[cur][k][tr*2];
            float4 b4 = *(const float4*)&Bs[cur][k][tc*4];
            acc[0][0] += a2.x*b4.x; acc[0][1] += a2.x*b4.y;
            acc[0][2] += a2.x*b4.z; acc[0][3] += a2.x*b4.w;
            acc[1][0] += a2.y*b4.x; acc[1][1] += a2.y*b4.y;
            acc[1][2] += a2.y*b4.z; acc[1][3] += a2.y*b4.w;
        }
        if (s + 1 < S) {
            int nxt = cur ^ 1;
            if (aload) {
                As[nxt][lc+0][ar]=va.x; As[nxt][lc+1][ar]=va.y; As[nxt][lc+2][ar]=va.z; As[nxt][lc+3][ar]=va.w;
            }
            Bs[nxt][lc+0][lr]=vb.x; Bs[nxt][lc+1][lr]=vb.y; Bs[nxt][lc+2][lr]=vb.z; Bs[nxt][lc+3][lr]=vb.w;
            __syncthreads();
        }
    }
    int c = c0 + tc*4;
    float4 bz = z4;
    if (flags & 1) bz = *(const float4*)(bias + c);
    #pragma unroll
    for (int i = 0; i < 2; i++) {
        int r = r0 + tr*2 + i;
        if (r >= M) continue;
        float4 v = make_float4(acc[i][0]+bz.x, acc[i][1]+bz.y, acc[i][2]+bz.z, acc[i][3]+bz.w);
        if (flags & 2) {
            float4 rv = *(const float4*)(res + (size_t)r*Nc + c);
            v.x += rv.x; v.y += rv.y; v.z += rv.z; v.w += rv.w;
        }
        if (flags & 4) {
            v.x = fmaxf(v.x, 0.f); v.y = fmaxf(v.y, 0.f);
            v.z = fmaxf(v.z, 0.f); v.w = fmaxf(v.w, 0.f);
        }
        *(float4*)(C + (size_t)r*Nc + c) = v;
    }
}

// ------------------------- sparse attention, split-K + fused dense -----------
__device__ __forceinline__ void attn_word20(unsigned word, int base,
    const float4 q4[4], float cqx, float cqy,
    const float (*Ks)[20], const float (*Vs)[20],
    const float* ckx, const float* cky, const float* qerow,
    float& lrun, float acc[16])
{
    while (word) {
        int mm = base + (__ffs((int)word) - 1);
        word &= word - 1u;
        const float4* kp = (const float4*)Ks[mm];
        float4 k0 = kp[0], k1 = kp[1], k2 = kp[2], k3 = kp[3];
        float s = q4[0].x*k0.x + q4[0].y*k0.y + q4[0].z*k0.z + q4[0].w*k0.w
                + q4[1].x*k1.x + q4[1].y*k1.y + q4[1].z*k1.z + q4[1].w*k1.w
                + q4[2].x*k2.x + q4[2].y*k2.y + q4[2].z*k2.z + q4[2].w*k2.w
                + q4[3].x*k3.x + q4[3].y*k3.y + q4[3].z*k3.z + q4[3].w*k3.w;
        float dx = cqx - ckx[mm], dy = cqy - cky[mm];
        float dist = sqrtf(dx*dx + dy*dy);
        int bk = (int)(dist * 32.f); if (bk > 31) bk = 31;
        float p = __expf(s*SCALEf + qerow[bk]);
        lrun += p;
        const float4* vp = (const float4*)Vs[mm];
        float4 v0 = vp[0], v1 = vp[1], v2 = vp[2], v3 = vp[3];
        acc[ 0] += p*v0.x; acc[ 1] += p*v0.y; acc[ 2] += p*v0.z; acc[ 3] += p*v0.w;
        acc[ 4] += p*v1.x; acc[ 5] += p*v1.y; acc[ 6] += p*v1.z; acc[ 7] += p*v1.w;
        acc[ 8] += p*v2.x; acc[ 9] += p*v2.y; acc[10] += p*v2.z; acc[11] += p*v2.w;
        acc[12] += p*v3.x; acc[13] += p*v3.y; acc[14] += p*v3.z; acc[15] += p*v3.w;
    }
}

// grid (25, Hh, Bsz), 128 threads. x<24: sparse (qtile=x/3, kseg=x%3).
// x==24: dense rows {0, Nn} (64 threads each).
__global__ void k_attn(const float* __restrict__ coords)
{
    __shared__ float Ks[128][20];
    __shared__ float Vs[128][20];
    __shared__ float ckx[128], cky[128];
    __shared__ float qes[128][33];
    __shared__ float pw[4][17];
    int b = blockIdx.z, h = blockIdx.y;
    int x = blockIdx.x;
    int tid = threadIdx.x;
    const size_t hb = (size_t)(b*Hh + h)*N1;

    if (x == 24) {   // ---- dense rows ----
        int sub = tid >> 6, st = tid & 63;
        int lane = tid & 31, w = tid >> 5;
        int n = sub ? Nn : 0;
        float q[16];
        const float4* qp = (const float4*)(d_Q + (hb + n)*Dk);
        #pragma unroll
        for (int i = 0; i < 4; i++) {
            float4 v = qp[i];
            q[i*4+0]=v.x; q[i*4+1]=v.y; q[i*4+2]=v.z; q[i*4+3]=v.w;
        }
        float cqx = 0.f, cqy = 0.f;
        if (n < Nn) { cqx = coords[(b*Nn+n)*2]; cqy = coords[(b*Nn+n)*2+1]; }
        const float* qerow = d_QE + (hb + n)*NBk;
        float l = 0.f, acc[16];
        #pragma unroll
        for (int d = 0; d < 16; d++) acc[d] = 0.f;
        const float* Kt = d_Kb + hb*Dk;
        const float* Vt = d_Vb + hb*Dk;
        for (int mk = st; mk < N1; mk += 64) {
            const float4* kp = (const float4*)(Kt + (size_t)mk*Dk);
            float s = 0.f;
            #pragma unroll
            for (int i = 0; i < 4; i++) {
                float4 kv = kp[i];
                s += q[i*4+0]*kv.x + q[i*4+1]*kv.y + q[i*4+2]*kv.z + q[i*4+3]*kv.w;
            }
            float cmx = 0.f, cmy = 0.f;
            if (mk < Nn) { cmx = coords[(b*Nn+mk)*2]; cmy = coords[(b*Nn+mk)*2+1]; }
            float dx = cqx - cmx, dy = cqy - cmy;
            float dist = sqrtf(dx*dx + dy*dy);
            int bk = (int)(dist * 32.f); if (bk > 31) bk = 31;
            float p = __expf(s*SCALEf + qerow[bk]);
            l += p;
            const float4* vp = (const float4*)(Vt + (size_t)mk*Dk);
            #pragma unroll
            for (int i = 0; i < 4; i++) {
                float4 vv = vp[i];
                acc[i*4+0] += p*vv.x; acc[i*4+1] += p*vv.y;
                acc[i*4+2] += p*vv.z; acc[i*4+3] += p*vv.w;
            }
        }
        #pragma unroll
        for (int o = 16; o; o >>= 1) {
            l += __shfl_xor_sync(0xffffffffu, l, o);
            #pragma unroll
            for (int d = 0; d < 16; d++) acc[d] += __shfl_xor_sync(0xffffffffu, acc[d], o);
        }
        if (lane == 0) {
            #pragma unroll
            for (int d = 0; d < 16; d++) pw[w][d] = acc[d];
            pw[w][16] = l;
        }
        __syncthreads();
        if (tid == 0 || tid == 64) {
            int w0 = sub*2;
            float L = pw[w0][16] + pw[w0+1][16];
            float inv = 1.f / L;
            float* o = d_CTX + ((size_t)(b*N1 + n))*Dm + h*Dk;
            #pragma unroll
            for (int d = 0; d < 16; d++) o[d] = (pw[w0][d] + pw[w0+1][d]) * inv;
        }
        return;
    }

    // ---- sparse split-K ----
    int qt = x / 3, kseg = x % 3;
    int n = qt*128 + tid;              // 0..1023
    bool qv = (n != 0);                // row 0 is dense
    float4 q4[4];
    float cqx = 0.f, cqy = 0.f, lrun = 0.f;
    float acc[16];
    #pragma unroll
    for (int d = 0; d < 16; d++) acc[d] = 0.f;
    const unsigned* rowadj = d_ADJ + (size_t)(b*N1 + n)*AW;
    {
        const float4* qp = (const float4*)(d_Q + (hb + n)*Dk);
        #pragma unroll
        for (int i = 0; i < 4; i++) q4[i] = qp[i];
        cqx = coords[(b*Nn+n)*2]; cqy = coords[(b*Nn+n)*2+1];
        const float4* qep = (const float4*)(d_QE + (hb + n)*NBk);
        #pragma unroll
        for (int i = 0; i < 8; i++) {
            float4 v = qep[i];
            qes[tid][i*4+0]=v.x; qes[tid][i*4+1]=v.y;
            qes[tid][i*4+2]=v.z; qes[tid][i*4+3]=v.w;
        }
    }
    for (int kt = kseg*3; kt < kseg*3 + 3; kt++) {
        int m0 = kt*128;
        int tlen = N1 - m0; if (tlen > 128) tlen = 128;
        const float4* Kt = (const float4*)(d_Kb + (hb + m0)*Dk);
        const float4* Vt = (const float4*)(d_Vb + (hb + m0)*Dk);
        __syncthreads();
        #pragma unroll
        for (int i = 0; i < 4; i++) {
            int f = tid + i*128;
            int row = f >> 2, j = (f & 3)*4;
            if (row < tlen) {
                *(float4*)&Ks[row][j] = Kt[f];
                *(float4*)&Vs[row][j] = Vt[f];
            }
        }
        if (tid < tlen) {
            int m = m0 + tid;
            if (m < Nn) { ckx[tid] = coords[(b*Nn+m)*2]; cky[tid] = coords[(b*Nn+m)*2+1]; }
            else        { ckx[tid] = 0.f; cky[tid] = 0.f; }
        }
        __syncthreads();
        if (!qv) continue;
        int wb = m0 >> 5;
        unsigned w0 = rowadj[wb];
        unsigned w1 = (wb+1 < AW) ? rowadj[wb+1] : 0u;
        unsigned w2 = (wb+2 < AW) ? rowadj[wb+2] : 0u;
        unsigned w3 = (wb+3 < AW) ? rowadj[wb+3] : 0u;
        attn_word20(w0,  0, q4, cqx, cqy, Ks, Vs, ckx, cky, qes[tid], lrun, acc);
        attn_word20(w1, 32, q4, cqx, cqy, Ks, Vs, ckx, cky, qes[tid], lrun, acc);
        attn_word20(w2, 64, q4, cqx, cqy, Ks, Vs, ckx, cky, qes[tid], lrun, acc);
        attn_word20(w3, 96, q4, cqx, cqy, Ks, Vs, ckx, cky, qes[tid], lrun, acc);
    }
    if (qv) {
        size_t base = ((size_t)kseg*Bsz*N1 + (size_t)b*N1 + n)*Hh + h;
        float* pa = d_PA + base*17;
        #pragma unroll
        for (int d = 0; d < 16; d++) pa[d] = acc[d];
        pa[16] = lrun;
    }
}

// ------------------------- combine split-K partials --------------------------
__global__ void k_comb()
{
    int u = blockIdx.x*blockDim.x + threadIdx.x;   // (b*N1+n)*Hh + h
    if (u >= Bsz*N1*Hh) return;
    int h = u & 7;
    int r = u >> 3;
    int n = (r >= N1) ? r - N1 : r;
    if (n == 0 || n == Nn) return;                  // dense rows written directly
    const int ST = Bsz*N1*Hh*17;
    int base = u*17;
    float l = d_PA[base+16] + d_PA[ST+base+16] + d_PA[2*ST+base+16];
    float inv = 1.f / l;
    float* o = d_CTX + (size_t)r*Dm + h*Dk;
    #pragma unroll
    for (int d = 0; d < 16; d++)
        o[d] = (d_PA[base+d] + d_PA[ST+base+d] + d_PA[2*ST+base+d]) * inv;
}

// ------------------------- instance norm: stats (partials) -------------------
__global__ void k_istat(const float* __restrict__ src)
{
    __shared__ float s1[2][Dm], s2[2][Dm];
    int b = blockIdx.x, z = blockIdx.y;
    int d = threadIdx.x & 127, g = threadIdx.x >> 7;
    int nend = z*64 + 64; if (nend > N1) nend = N1;
    const float* p = src + (size_t)b*N1*Dm + d;
    float a = 0.f, qq = 0.f;
    for (int n = z*64 + g; n < nend; n += 2) {
        float x = p[(size_t)n*Dm];
        a += x; qq += x*x;
    }
    s1[g][d] = a; s2[g][d] = qq;
    __syncthreads();
    if (g == 0) {
        d_PS1[(b*NCH + z)*Dm + d] = s1[0][d] + s1[1][d];
        d_PS2[(b*NCH + z)*Dm + d] = s2[0][d] + s2[1][d];
    }
}

// ------------------------- instance norm: apply ------------------------------
__global__ void k_iapply(const float* __restrict__ src, float* __restrict__ dst,
                         const float* __restrict__ w, const float* __restrict__ bb, int fuse)
{
    int b  = blockIdx.x;
    int dl = threadIdx.x & 31;
    int g  = threadIdx.x >> 5;
    int d  = blockIdx.y*32 + dl;
    int z  = blockIdx.z;
    float S1 = 0.f, S2 = 0.f;
    #pragma unroll
    for (int t = 0; t < NCH; t++) {
        S1 += d_PS1[(b*NCH + t)*Dm + d];
        S2 += d_PS2[(b*NCH + t)*Dm + d];
    }
    float mu  = S1 * (1.f/N1);
    float var = S2 * (1.f/N1) - mu*mu;
    float sc  = rsqrtf(var + EPSf) * w[d];
    float sh  = bb[d];
    const float* p = src + (size_t)b*N1*Dm + d;
    float* o = dst + (size_t)b*N1*Dm + d;
    float mo = 0.f;
    if (fuse) mo = ((S1 - p[(size_t)Nn*Dm])*(1.f/Nn) - mu)*sc + sh;
    int n0 = z*128, n1 = (z == 7) ? N1 : (z+1)*128;
    for (int n = n0 + g; n < n1; n += 32) {
        float val = (p[(size_t)n*Dm] - mu)*sc + sh;
        if (fuse && n == Nn) val += mo;
        o[(size_t)n*Dm] = val;
    }
    if (fuse && z == 7 && g == 0) d_POOL[b*Dm + d] += mo;
}

// ------------------------- final GEMM: out = (h + pool/3) @ outW^T + outb ----
__global__ void k_fgemm(const float* __restrict__ Bm, const float* __restrict__ bias,
                        float* __restrict__ out)
{
    __shared__ __align__(16) float As[2][16][68];
    __shared__ __align__(16) float Bs[2][16][68];
    int tid = threadIdx.x;
    int tr = tid >> 4, tc = tid & 15;
    int r0 = blockIdx.y*64, c0 = blockIdx.x*64;
    int lr = tid >> 2;
    int lc = (tid & 3) * 4;
    int gr = r0 + lr;
    int bb = gr >> 10, nn = gr & 1023;
    const float* Arow = d_HG + ((size_t)bb*N1 + nn)*Dm;
    const float* Prow = d_POOL + bb*Dm;
    int gc = c0 + lr;
    if (blockIdx.x == 0 && blockIdx.y == 0 && tid < Bsz*Dm)
        out[Bsz*Nn*Dm + tid] = d_POOL[tid] * (1.f/3.f);
    float4 va, vb;
    {
        float4 hv = *(const float4*)(Arow + lc);
        float4 pv = *(const float4*)(Prow + lc);
        va = make_float4(hv.x + pv.x*(1.f/3.f), hv.y + pv.y*(1.f/3.f),
                         hv.z + pv.z*(1.f/3.f), hv.w + pv.w*(1.f/3.f));
        vb = *(const float4*)(Bm + (size_t)gc*Dm + lc);
    }
    As[0][lc+0][lr]=va.x; As[0][lc+1][lr]=va.y; As[0][lc+2][lr]=va.z; As[0][lc+3][lr]=va.w;
    Bs[0][lc+0][lr]=vb.x; Bs[0][lc+1][lr]=vb.y; Bs[0][lc+2][lr]=vb.z; Bs[0][lc+3][lr]=vb.w;
    __syncthreads();
    float acc[4][4] = {};
    #pragma unroll
    for (int s = 0; s < 8; s++) {
        int cur = s & 1;
        if (s < 7) {
            float4 hv = *(const float4*)(Arow + (s+1)*16 + lc);
            float4 pv = *(const float4*)(Prow + (s+1)*16 + lc);
            va = make_float4(hv.x + pv.x*(1.f/3.f), hv.y + pv.y*(1.f/3.f),
                             hv.z + pv.z*(1.f/3.f), hv.w + pv.w*(1.f/3.f));
            vb = *(const float4*)(Bm + (size_t)gc*Dm + (s+1)*16 + lc);
        }
        #pragma unroll
        for (int k = 0; k < 16; k++) {
            float4 a4 = *(const float4*)&As[cur][k][tr*4];
            float4 b4 = *(const float4*)&Bs[cur][k][tc*4];
            float a[4] = {a4.x, a4.y, a4.z, a4.w};
            float bv[4] = {b4.x, b4.y, b4.z, b4.w};
            #pragma unroll
            for (int i = 0; i < 4; i++)
                #pragma unroll
                for (int j = 0; j < 4; j++) acc[i][j] += a[i]*bv[j];
        }
        if (s < 7) {
            int nxt = cur ^ 1;
            As[nxt][lc+0][lr]=va.x; As[nxt][lc+1][lr]=va.y; As[nxt][lc+2][lr]=va.z; As[nxt][lc+3][lr]=va.w;
            Bs[nxt][lc+0][lr]=vb.x; Bs[nxt][lc+1][lr]=vb.y; Bs[nxt][lc+2][lr]=vb.z; Bs[nxt][lc+3][lr]=vb.w;
            __syncthreads();
        }
    }
    int c = c0 + tc*4;
    float4 bz = *(const float4*)(bias + c);
    #pragma unroll
    for (int i = 0; i < 4; i++) {
        int r = r0 + tr*4 + i;
        *(float4*)(out + (size_t)r*Dm + c) =
            make_float4(acc[i][0]+bz.x, acc[i][1]+bz.y, acc[i][2]+bz.z, acc[i][3]+bz.w);
    }
}

// ------------------------- host driver ---------------------------------------
extern "C" void kernel_launch(void* const* d_in, const int* in_sizes, int n_in,
                              void* d_out, int out_size)
{
    const float* coords = (const float*)d_in[0];
    const float* in_W   = (const float*)d_in[1];
    const float* in_b   = (const float*)d_in[2];
    const float* gnode  = (const float*)d_in[3];
    const float* Wq     = (const float*)d_in[4];
    const float* Wk     = (const float*)d_in[5];
    const float* Wv     = (const float*)d_in[6];
    const float* Wo     = (const float*)d_in[7];
    const float* emb    = (const float*)d_in[8];
    const float* W1     = (const float*)d_in[9];
    const float* b1     = (const float*)d_in[10];
    const float* W2     = (const float*)d_in[11];
    const float* b2     = (const float*)d_in[12];
    const float* n1w    = (const float*)d_in[13];
    const float* n1b    = (const float*)d_in[14];
    const float* n2w    = (const float*)d_in[15];
    const float* n2b    = (const float*)d_in[16];
    const float* outW   = (const float*)d_in[17];
    const float* outb   = (const float*)d_in[18];
    float* out = (float*)d_out;

    float *HG, *CTX, *Y, *T1, *T2;
    cudaGetSymbolAddress((void**)&HG,  d_HG);
    cudaGetSymbolAddress((void**)&CTX, d_CTX);
    cudaGetSymbolAddress((void**)&Y,   d_Y);
    cudaGetSymbolAddress((void**)&T1,  d_T1);
    cudaGetSymbolAddress((void**)&T2,  d_T2);

    const int Mall = Bsz*N1;  // 2050

    k_input<<<(Bsz*N1*Dm + 255)/256, 256>>>(coords, in_W, in_b, gnode);
    k_colmean<<<Bsz, 1024>>>();                            // layer-0 g update

    for (int l = 0; l < 3; l++) {
        k_par1<<<983, 256>>>(Wq + (size_t)l*Dm*Dm, Wk + (size_t)l*Dm*Dm, Wv + (size_t)l*Dm*Dm);
        k_par2<<<513, 256>>>(emb + (size_t)l*NBk*Dm);
        { dim3 ga(25, Hh, Bsz); k_attn<<<ga, 128>>>(coords); }
        k_comb<<<(Bsz*N1*Hh + 127)/128, 128>>>();

        { dim3 gq(Dm/64, (Mall + 31)/32);
          k_gemmS<<<gq, 256>>>(CTX, Wo + (size_t)l*Dm*Dm, nullptr, HG, Y, Mall, Dm, Dm, 2); }
        { dim3 gs(Bsz, NCH); k_istat<<<gs, 256>>>(Y); }
        { dim3 gi(Bsz, 4, 8); k_iapply<<<gi, 1024>>>(Y, Y, n1w + l*Dm, n1b + l*Dm, 0); }

        { dim3 g1(Dff/64, (Mall + 63)/64);
          k_gemm<<<g1, 256>>>(Y,  W1 + (size_t)l*Dff*Dm, b1 + l*Dff, nullptr, T1, Mall, Dff, Dm, 1|4); }
        { dim3 g2(Dm/64, (Mall + 31)/32);
          k_gemmS<<<g2, 256>>>(T1, W2 + (size_t)l*Dm*Dff, b2 + l*Dm, Y, T2, Mall, Dm, Dff, 1|2); }
        { dim3 gs(Bsz, NCH); k_istat<<<gs, 256>>>(T2); }
        { dim3 gi(Bsz, 4, 8); k_iapply<<<gi, 1024>>>(T2, HG, n2w + l*Dm, n2b + l*Dm, 1); }
    }

    { dim3 ge(Dm/64, (Bsz*Nn)/64); k_fgemm<<<ge, 256>>>(outW, outb, out); }
}

// round 11
// speedup vs baseline: 6.0189x; 1.0569x over previous
#include <cuda_runtime.h>
#include <math_constants.h>
#include <math.h>

#define Bsz 2
#define Nn 1024
#define N1 1025
#define Dm 128
#define Hh 8
#define Dk 16
#define Dff 512
#define NBk 32
#define KNN 10
#define AW 33          // 33 x 32-bit words cover 1025 mask bits per row
#define EPSf 1e-5f
#define SCALEf 0.25f   // 1/sqrt(16)
#define NCH 17         // inorm stat chunks
#define PASTR 20       // split-K partial stride (floats), 16B-aligned

// ------------------------- persistent device scratch -------------------------
__device__ float    d_HG [Bsz*N1*Dm];     // state: rows 0..1023 = h, row 1024 = g
__device__ float    d_POOL[Bsz*Dm];
__device__ float    d_D2 [(size_t)Bsz*Nn*Nn];
__device__ unsigned d_ADJ[Bsz*N1*AW];
__device__ float    d_Q  [Bsz*Hh*N1*Dk];  // head-major: [b][h][n][dk]
__device__ float    d_Kb [Bsz*Hh*N1*Dk];
__device__ float    d_Vb [Bsz*Hh*N1*Dk];
__device__ float    d_CTX[Bsz*N1*Dm];
__device__ float    d_QE [Bsz*Hh*N1*NBk]; // head-major: [b][h][n][bucket]
__device__ float    d_Y  [Bsz*N1*Dm];
__device__ float    d_T1 [Bsz*N1*Dff];
__device__ float    d_T2 [Bsz*N1*Dm];
__device__ float    d_PS1[Bsz*NCH*Dm];
__device__ float    d_PS2[Bsz*NCH*Dm];
__device__ float    d_PA [3*Bsz*N1*Hh*PASTR];  // split-K partials: acc[16]+lrun

// ------------------------- input embedding + state init ----------------------
__global__ void k_input(const float* __restrict__ coords, const float* __restrict__ inW,
                        const float* __restrict__ inb, const float* __restrict__ gnode)
{
    int gid = blockIdx.x*blockDim.x + threadIdx.x;
    if (gid < Bsz*Dm) d_POOL[gid] = 0.f;
    if (gid >= Bsz*N1*Dm) return;
    int d = gid % Dm;
    int n = (gid / Dm) % N1;
    int b = gid / (Dm*N1);
    float v;
    if (n < Nn) {
        float x = coords[(b*Nn+n)*2+0];
        float y = coords[(b*Nn+n)*2+1];
        v = x*inW[d*2+0] + y*inW[d*2+1] + inb[d];
    } else {
        v = gnode[d];
    }
    d_HG[gid] = v;
}

// ------------------------- layer-0 g update: g += mean(h) --------------------
__global__ void k_colmean()
{
    __shared__ float red[8][Dm];
    int b = blockIdx.x;
    int d = threadIdx.x & 127;
    int g = threadIdx.x >> 7;
    const float* base = d_HG + (size_t)b*N1*Dm;
    float s = 0.f;
    for (int n = g; n < Nn; n += 8) s += base[n*Dm + d];
    red[g][d] = s;
    __syncthreads();
    if (g == 0) {
        float t = 0.f;
        #pragma unroll
        for (int i = 0; i < 8; i++) t += red[i][d];
        d_HG[(size_t)b*N1*Dm + Nn*Dm + d] += t * (1.f/Nn);
    }
}

// ===================== PAR1: D2 (self-norms) + QKV + ADJ-init =================
// grid: [0,272) d2 tiles, [272,470) qkv, [470,983) adjacency rows. 256 threads.
__global__ void k_par1(const float* __restrict__ wq, const float* __restrict__ wk,
                       const float* __restrict__ wv)
{
    __shared__ __align__(16) float As[2][16][68];
    __shared__ __align__(16) float Bs[2][16][68];
    __shared__ float rsq[64], csq[64];
    int bx = blockIdx.x;
    int tid = threadIdx.x;

    if (bx < 272) {        // ---------- D2 symmetric tile ----------
        int b = bx / 136;
        int x = bx % 136, bi = 0;
        while (x >= 16 - bi) { x -= 16 - bi; bi++; }
        int bj = bi + x;
        const float* A = d_HG + (size_t)b*N1*Dm;
        int tr = tid >> 4, tc = tid & 15;
        int r0 = bi*64, c0 = bj*64;
        int lr = tid >> 2, lc = (tid & 3)*4;
        float rn = 0.f, cn = 0.f;
        float4 va = *(const float4*)(A + (size_t)(r0+lr)*Dm + lc);
        float4 vb = *(const float4*)(A + (size_t)(c0+lr)*Dm + lc);
        rn += va.x*va.x + va.y*va.y + va.z*va.z + va.w*va.w;
        cn += vb.x*vb.x + vb.y*vb.y + vb.z*vb.z + vb.w*vb.w;
        As[0][lc+0][lr]=va.x; As[0][lc+1][lr]=va.y; As[0][lc+2][lr]=va.z; As[0][lc+3][lr]=va.w;
        Bs[0][lc+0][lr]=vb.x; Bs[0][lc+1][lr]=vb.y; Bs[0][lc+2][lr]=vb.z; Bs[0][lc+3][lr]=vb.w;
        __syncthreads();
        float acc[4][4] = {};
        #pragma unroll
        for (int s = 0; s < 8; s++) {
            int cur = s & 1;
            if (s < 7) {
                va = *(const float4*)(A + (size_t)(r0+lr)*Dm + (s+1)*16 + lc);
                vb = *(const float4*)(A + (size_t)(c0+lr)*Dm + (s+1)*16 + lc);
                rn += va.x*va.x + va.y*va.y + va.z*va.z + va.w*va.w;
                cn += vb.x*vb.x + vb.y*vb.y + vb.z*vb.z + vb.w*vb.w;
            }
            #pragma unroll
            for (int k = 0; k < 16; k++) {
                float4 a4 = *(const float4*)&As[cur][k][tr*4];
                float4 b4 = *(const float4*)&Bs[cur][k][tc*4];
                float a[4] = {a4.x, a4.y, a4.z, a4.w};
                float bv[4] = {b4.x, b4.y, b4.z, b4.w};
                #pragma unroll
                for (int i = 0; i < 4; i++)
                    #pragma unroll
                    for (int j = 0; j < 4; j++) acc[i][j] += a[i]*bv[j];
            }
            if (s < 7) {
                int nxt = cur ^ 1;
                As[nxt][lc+0][lr]=va.x; As[nxt][lc+1][lr]=va.y; As[nxt][lc+2][lr]=va.z; As[nxt][lc+3][lr]=va.w;
                Bs[nxt][lc+0][lr]=vb.x; Bs[nxt][lc+1][lr]=vb.y; Bs[nxt][lc+2][lr]=vb.z; Bs[nxt][lc+3][lr]=vb.w;
                __syncthreads();
            }
        }
        rn += __shfl_xor_sync(0xffffffffu, rn, 1);
        rn += __shfl_xor_sync(0xffffffffu, rn, 2);
        cn += __shfl_xor_sync(0xffffffffu, cn, 1);
        cn += __shfl_xor_sync(0xffffffffu, cn, 2);
        if ((tid & 3) == 0) { rsq[lr] = rn; csq[lr] = cn; }
        __syncthreads();
        float vals[4][4];
        #pragma unroll
        for (int i = 0; i < 4; i++) {
            int r = r0 + tr*4 + i;
            float sqr = rsq[tr*4 + i];
            float* orow = d_D2 + ((size_t)b*Nn + r)*Nn + c0 + tc*4;
            float o[4];
            #pragma unroll
            for (int j = 0; j < 4; j++) {
                int c = c0 + tc*4 + j;
                float v = sqr + csq[tc*4 + j] - 2.f*acc[i][j];
                o[j] = (r == c) ? CUDART_INF_F : v;
                vals[i][j] = o[j];
            }
            *(float4*)orow = make_float4(o[0], o[1], o[2], o[3]);
        }
        if (bi != bj) {
            #pragma unroll
            for (int j = 0; j < 4; j++) {
                int c = c0 + tc*4 + j;
                float* orow = d_D2 + ((size_t)b*Nn + c)*Nn + r0 + tr*4;
                *(float4*)orow = make_float4(vals[0][j], vals[1][j], vals[2][j], vals[3][j]);
            }
        }
        return;
    }

    if (bx < 470) {        // ---------- QKV GEMM ----------
        int idx = bx - 272;
        int sel = idx / 66, rem = idx % 66;
        const float* Bm = (sel == 0) ? wq : (sel == 1) ? wk : wv;
        float* C = (sel == 0) ? d_Q : (sel == 1) ? d_Kb : d_Vb;
        const int M = Bsz*N1;
        int tr = tid >> 4, tc = tid & 15;
        int r0 = (rem >> 1)*64, c0 = (rem & 1)*64;
        int lr = tid >> 2, lc = (tid & 3)*4;
        int gr = r0 + lr, gc = c0 + lr;
        const float4 z4 = make_float4(0.f,0.f,0.f,0.f);
        float4 va = (gr < M) ? *(const float4*)(d_HG + (size_t)gr*Dm + lc) : z4;
        float4 vb = *(const float4*)(Bm + (size_t)gc*Dm + lc);
        As[0][lc+0][lr]=va.x; As[0][lc+1][lr]=va.y; As[0][lc+2][lr]=va.z; As[0][lc+3][lr]=va.w;
        Bs[0][lc+0][lr]=vb.x; Bs[0][lc+1][lr]=vb.y; Bs[0][lc+2][lr]=vb.z; Bs[0][lc+3][lr]=vb.w;
        __syncthreads();
        float acc[4][4] = {};
        #pragma unroll
        for (int s = 0; s < 8; s++) {
            int cur = s & 1;
            if (s < 7) {
                va = (gr < M) ? *(const float4*)(d_HG + (size_t)gr*Dm + (s+1)*16 + lc) : z4;
                vb = *(const float4*)(Bm + (size_t)gc*Dm + (s+1)*16 + lc);
            }
            #pragma unroll
            for (int k = 0; k < 16; k++) {
                float4 a4 = *(const float4*)&As[cur][k][tr*4];
                float4 b4 = *(const float4*)&Bs[cur][k][tc*4];
                float a[4] = {a4.x, a4.y, a4.z, a4.w};
                float bv[4] = {b4.x, b4.y, b4.z, b4.w};
                #pragma unroll
                for (int i = 0; i < 4; i++)
                    #pragma unroll
                    for (int j = 0; j < 4; j++) acc[i][j] += a[i]*bv[j];
            }
            if (s < 7) {
                int nxt = cur ^ 1;
                As[nxt][lc+0][lr]=va.x; As[nxt][lc+1][lr]=va.y; As[nxt][lc+2][lr]=va.z; As[nxt][lc+3][lr]=va.w;
                Bs[nxt][lc+0][lr]=vb.x; Bs[nxt][lc+1][lr]=vb.y; Bs[nxt][lc+2][lr]=vb.z; Bs[nxt][lc+3][lr]=vb.w;
                __syncthreads();
            }
        }
        int c = c0 + tc*4;
        int h  = c >> 4;
        int dk = c & 15;
        #pragma unroll
        for (int i = 0; i < 4; i++) {
            int r = r0 + tr*4 + i;
            if (r >= M) continue;
            int bb = (r >= N1) ? 1 : 0;
            int n  = r - bb*N1;
            *(float4*)(C + ((size_t)(bb*Hh + h)*N1 + n)*Dk + dk) =
                make_float4(acc[i][0], acc[i][1], acc[i][2], acc[i][3]);
        }
        return;
    }

    // ---------- adjacency base pattern ----------
    {
        int row = (bx - 470)*4 + (tid >> 6);
        int t = tid & 63;
        if (row >= Bsz*N1 || t >= AW) return;
        int i = row % N1;
        int w = t;
        unsigned bits = 0u;
        #pragma unroll 4
        for (int q = 0; q < 32; q++) {
            int m = w*32 + q;
            if (m > Nn) break;
            bool on;
            if (i == Nn || m == Nn || i == m || i == 0 || m == 0) on = true;
            else {
                int di = i - m; if (di < 0) di = -di;
                on = ((i >> 7) == (m >> 7)) && (di <= 11);   // hier adjacency
            }
            if (on) bits |= 1u << q;
        }
        d_ADJ[row*AW + w] = bits;
    }
}

// ===================== PAR2: topk (2 warps/row) + qe (8 rows/block) ===========
// grid: [0,512) topk (4 rows x 2 warps), [512,769) qe (8 rows/block). 256 thr.
__global__ void k_par2(const float* __restrict__ emb)
{
    int bx = blockIdx.x;
    int tid = threadIdx.x;
    if (bx < 512) {        // ---------- exact top-10 kNN, 2 warps/row ----------
        __shared__ unsigned candK[2][4][2];
        __shared__ int      candJ[2][4][2];
        int wid  = tid >> 5;           // 0..7
        int lane = tid & 31;
        int rw   = wid >> 1;           // row within block 0..3
        int w    = wid & 1;            // column half 0/1
        int rowg = bx*4 + rw;          // 0..2047
        int b = rowg >> 10, i = rowg & 1023;
        const float* row = d_D2 + (size_t)rowg*Nn + w*512;
        unsigned uv[16];
        #pragma unroll
        for (int t = 0; t < 16; t++) {
            unsigned u = __float_as_uint(row[t*32 + lane]);
            uv[t] = (u & 0x80000000u) ? ~u : (u | 0x80000000u);
        }
        unsigned* adjb = d_ADJ + (size_t)b*N1*AW;
        for (int r = 0; r < KNN; r++) {
            unsigned m0 = min(uv[0], uv[4]),  m1 = min(uv[1], uv[5]);
            unsigned m2 = min(uv[2], uv[6]),  m3 = min(uv[3], uv[7]);
            m0 = min(m0, min(uv[8],  uv[12]));
            m1 = min(m1, min(uv[9],  uv[13]));
            m2 = min(m2, min(uv[10], uv[14]));
            m3 = min(m3, min(uv[11], uv[15]));
            unsigned mm = min(min(m0, m1), min(m2, m3));
            #pragma unroll
            for (int o = 16; o; o >>= 1)
                mm = min(mm, __shfl_xor_sync(0xffffffffu, mm, o));
            int lj = 0x7FFFFFFF;
            #pragma unroll
            for (int t = 0; t < 16; t++)
                if (uv[t] == mm) { lj = w*512 + t*32 + lane; break; }
            #pragma unroll
            for (int o = 16; o; o >>= 1)
                lj = min(lj, __shfl_xor_sync(0xffffffffu, lj, o));
            int pb = r & 1;
            if (lane == 0) { candK[pb][rw][w] = mm; candJ[pb][rw][w] = lj; }
            __syncthreads();
            unsigned k0 = candK[pb][rw][0], k1 = candK[pb][rw][1];
            int j0 = candJ[pb][rw][0], j1 = candJ[pb][rw][1];
            int bj;
            if (k0 < k1 || (k0 == k1 && j0 < j1)) bj = j0; else bj = j1;
            if (w == (bj >> 9)) {               // owning half clears the slot
                int jl = bj - w*512;
                if (lane == (jl & 31)) uv[jl >> 5] = 0xFFFFFFFFu;
            }
            if (w == 0 && lane == 0) {
                atomicOr(&adjb[i*AW + (bj >> 5)], 1u << (bj & 31));
                atomicOr(&adjb[bj*AW + (i >> 5)], 1u << (i & 31));
            }
        }
        return;
    }
    // ---------- qe: 8 rows per block ----------
    __shared__ float qs[8][Dm];
    int r0 = (bx - 512)*8;             // first global row (b*N1+n)
    if (tid < 128) {
        int hh = tid >> 4, dk = tid & 15;
        #pragma unroll
        for (int r = 0; r < 8; r++) {
            int row = r0 + r;
            if (row >= Bsz*N1) break;
            int b = (row >= N1) ? 1 : 0;
            int n = row - b*N1;
            qs[r][tid] = d_Q[((size_t)(b*Hh + hh)*N1 + n)*Dk + dk];
        }
    }
    __syncthreads();
    int h = tid >> 5, kb = tid & 31;
    float e[16];
    const float* ep = emb + kb*Dm + h*Dk;
    #pragma unroll
    for (int d = 0; d < 16; d++) e[d] = ep[d];
    #pragma unroll
    for (int r = 0; r < 8; r++) {
        int row = r0 + r;
        if (row >= Bsz*N1) break;
        int b = (row >= N1) ? 1 : 0;
        int n = row - b*N1;
        const float* q = qs[r] + h*Dk;
        float s = 0.f;
        #pragma unroll
        for (int d = 0; d < 16; d++) s += q[d]*e[d];
        d_QE[((size_t)(b*Hh + h)*N1 + n)*NBk + kb] = s;
    }
}

// ------------------------- generic SGEMM 64x64 (double-buffered) -------------
__global__ void k_gemm(const float* __restrict__ A, const float* __restrict__ Bm,
                       const float* __restrict__ bias, const float* __restrict__ res,
                       float* __restrict__ C, int M, int Nc, int K, int flags)
{
    __shared__ __align__(16) float As[2][16][68];
    __shared__ __align__(16) float Bs[2][16][68];
    int tid = threadIdx.x;
    int tr = tid >> 4, tc = tid & 15;
    int r0 = blockIdx.y*64, c0 = blockIdx.x*64;
    int lr = tid >> 2;
    int lc = (tid & 3) * 4;
    int gr = r0 + lr, gc = c0 + lr;
    const float4 z4 = make_float4(0.f,0.f,0.f,0.f);
    float4 va = (gr < M) ? *(const float4*)(A + (size_t)gr*K + lc) : z4;
    float4 vb = *(const float4*)(Bm + (size_t)gc*K + lc);
    As[0][lc+0][lr]=va.x; As[0][lc+1][lr]=va.y; As[0][lc+2][lr]=va.z; As[0][lc+3][lr]=va.w;
    Bs[0][lc+0][lr]=vb.x; Bs[0][lc+1][lr]=vb.y; Bs[0][lc+2][lr]=vb.z; Bs[0][lc+3][lr]=vb.w;
    __syncthreads();
    float acc[4][4] = {};
    int S = K >> 4;
    for (int s = 0; s < S; s++) {
        int cur = s & 1;
        if (s + 1 < S) {
            va = (gr < M) ? *(const float4*)(A + (size_t)gr*K + (s+1)*16 + lc) : z4;
            vb = *(const float4*)(Bm + (size_t)gc*K + (s+1)*16 + lc);
        }
        #pragma unroll
        for (int k = 0; k < 16; k++) {
            float4 a4 = *(const float4*)&As[cur][k][tr*4];
            float4 b4 = *(const float4*)&Bs[cur][k][tc*4];
            float a[4] = {a4.x, a4.y, a4.z, a4.w};
            float bv[4] = {b4.x, b4.y, b4.z, b4.w};
            #pragma unroll
            for (int i = 0; i < 4; i++)
                #pragma unroll
                for (int j = 0; j < 4; j++) acc[i][j] += a[i]*bv[j];
        }
        if (s + 1 < S) {
            int nxt = cur ^ 1;
            As[nxt][lc+0][lr]=va.x; As[nxt][lc+1][lr]=va.y; As[nxt][lc+2][lr]=va.z; As[nxt][lc+3][lr]=va.w;
            Bs[nxt][lc+0][lr]=vb.x; Bs[nxt][lc+1][lr]=vb.y; Bs[nxt][lc+2][lr]=vb.z; Bs[nxt][lc+3][lr]=vb.w;
            __syncthreads();
        }
    }
    int c = c0 + tc*4;
    float4 bz = z4;
    if (flags & 1) bz = *(const float4*)(bias + c);
    #pragma unroll
    for (int i = 0; i < 4; i++) {
        int r = r0 + tr*4 + i;
        if (r >= M) continue;
        float4 v = make_float4(acc[i][0]+bz.x, acc[i][1]+bz.y, acc[i][2]+bz.z, acc[i][3]+bz.w);
        if (flags & 2) {
            float4 rv = *(const float4*)(res + (size_t)r*Nc + c);
            v.x += rv.x; v.y += rv.y; v.z += rv.z; v.w += rv.w;
        }
        if (flags & 4) {
            v.x = fmaxf(v.x, 0.f); v.y = fmaxf(v.y, 0.f);
            v.z = fmaxf(v.z, 0.f); v.w = fmaxf(v.w, 0.f);
        }
        *(float4*)(C + (size_t)r*Nc + c) = v;
    }
}

// ------------------------- SGEMM 32x64 tile (better chip fill) ---------------
__global__ void k_gemmS(const float* __restrict__ A, const float* __restrict__ Bm,
                        const float* __restrict__ bias, const float* __restrict__ res,
                        float* __restrict__ C, int M, int Nc, int K, int flags)
{
    __shared__ __align__(16) float As[2][16][36];
    __shared__ __align__(16) float Bs[2][16][68];
    int tid = threadIdx.x;
    int tr = tid >> 4, tc = tid & 15;
    int r0 = blockIdx.y*32, c0 = blockIdx.x*64;
    int lr = tid >> 2;
    int lc = (tid & 3) * 4;
    bool aload = tid < 128;
    int ar = tid >> 2;                 // 0..31 for tid<128
    int gr = r0 + ar, gc = c0 + lr;
    const float4 z4 = make_float4(0.f,0.f,0.f,0.f);
    float4 va = (aload && gr < M) ? *(const float4*)(A + (size_t)gr*K + lc) : z4;
    float4 vb = *(const float4*)(Bm + (size_t)gc*K + lc);
    if (aload) {
        As[0][lc+0][ar]=va.x; As[0][lc+1][ar]=va.y; As[0][lc+2][ar]=va.z; As[0][lc+3][ar]=va.w;
    }
    Bs[0][lc+0][lr]=vb.x; Bs[0][lc+1][lr]=vb.y; Bs[0][lc+2][lr]=vb.z; Bs[0][lc+3][lr]=vb.w;
    __syncthreads();
    float acc[2][4] = {};
    int S = K >> 4;
    for (int s = 0; s < S; s++) {
        int cur = s & 1;
        if (s + 1 < S) {
            va = (aload && gr < M) ? *(const float4*)(A + (size_t)gr*K + (s+1)*16 + lc) : z4;
            vb = *(const float4*)(Bm + (size_t)gc*K + (s+1)*16 + lc);
        }
        #pragma unroll
        for (int k = 0; k < 16; k++) {
            float2 a2 = *(const float2*)&As[cur][k][tr*2];
            float4 b4 = *(const float4*)&Bs[cur][k][tc*4];
            acc[0][0] += a2.x*b4.x; acc[0][1] += a2.x*b4.y;
            acc[0][2] += a2.x*b4.z; acc[0][3] += a2.x*b4.w;
            acc[1][0] += a2.y*b4.x; acc[1][1] += a2.y*b4.y;
            acc[1][2] += a2.y*b4.z; acc[1][3] += a2.y*b4.w;
        }
        if (s + 1 < S) {
            int nxt = cur ^ 1;
            if (aload) {
                As[nxt][lc+0][ar]=va.x; As[nxt][lc+1][ar]=va.y; As[nxt][lc+2][ar]=va.z; As[nxt][lc+3][ar]=va.w;
            }
            Bs[nxt][lc+0][lr]=vb.x; Bs[nxt][lc+1][lr]=vb.y; Bs[nxt][lc+2][lr]=vb.z; Bs[nxt][lc+3][lr]=vb.w;
            __syncthreads();
        }
    }
    int c = c0 + tc*4;
    float4 bz = z4;
    if (flags & 1) bz = *(const float4*)(bias + c);
    #pragma unroll
    for (int i = 0; i < 2; i++) {
        int r = r0 + tr*2 + i;
        if (r >= M) continue;
        float4 v = make_float4(acc[i][0]+bz.x, acc[i][1]+bz.y, acc[i][2]+bz.z, acc[i][3]+bz.w);
        if (flags & 2) {
            float4 rv = *(const float4*)(res + (size_t)r*Nc + c);
            v.x += rv.x; v.y += rv.y; v.z += rv.z; v.w += rv.w;
        }
        if (flags & 4) {
            v.x = fmaxf(v.x, 0.f); v.y = fmaxf(v.y, 0.f);
            v.z = fmaxf(v.z, 0.f); v.w = fmaxf(v.w, 0.f);
        }
        *(float4*)(C + (size_t)r*Nc + c) = v;
    }
}

// ------------ Wo GEMM with fused split-K combine in the A-loader -------------
// Y = combine(PA)/CTX @ Wo^T + HG.  M=2050, Nc=K=128, 32x64 tiles.
__global__ void k_gemmC(const float* __restrict__ Bm, float* __restrict__ C)
{
    __shared__ __align__(16) float As[2][16][36];
    __shared__ __align__(16) float Bs[2][16][68];
    const int M = Bsz*N1;
    const int PST = Bsz*N1*Hh*PASTR;   // floats per kseg
    int tid = threadIdx.x;
    int tr = tid >> 4, tc = tid & 15;
    int r0 = blockIdx.y*32, c0 = blockIdx.x*64;
    int lr = tid >> 2;
    int lc = (tid & 3) * 4;
    bool aload = tid < 128;
    int ar = tid >> 2;
    int gr = r0 + ar, gc = c0 + lr;
    const float4 z4 = make_float4(0.f,0.f,0.f,0.f);
    bool valid = aload && gr < M;
    int bb = (gr >= N1) ? 1 : 0;
    int nn = gr - bb*N1;
    bool dense = (nn == 0) || (nn == Nn);
    size_t pbase = ((size_t)gr*Hh)*PASTR;   // + h*PASTR per step
    // A fetch helper (head h == k-step s)
    auto fetchA = [&](int s) -> float4 {
        if (!valid) return z4;
        if (dense) return *(const float4*)(d_CTX + (size_t)gr*Dm + s*16 + lc);
        size_t pb = pbase + (size_t)s*PASTR;
        float4 p0 = *(const float4*)(d_PA + pb + lc);
        float4 p1 = *(const float4*)(d_PA + PST + pb + lc);
        float4 p2 = *(const float4*)(d_PA + 2*PST + pb + lc);
        float l = d_PA[pb+16] + d_PA[PST+pb+16] + d_PA[2*PST+pb+16];
        float inv = __fdividef(1.f, l);
        return make_float4((p0.x+p1.x+p2.x)*inv, (p0.y+p1.y+p2.y)*inv,
                           (p0.z+p1.z+p2.z)*inv, (p0.w+p1.w+p2.w)*inv);
    };
    float4 va = fetchA(0);
    float4 vb = *(const float4*)(Bm + (size_t)gc*Dm + lc);
    if (aload) {
        As[0][lc+0][ar]=va.x; As[0][lc+1][ar]=va.y; As[0][lc+2][ar]=va.z; As[0][lc+3][ar]=va.w;
    }
    Bs[0][lc+0][lr]=vb.x; Bs[0][lc+1][lr]=vb.y; Bs[0][lc+2][lr]=vb.z; Bs[0][lc+3][lr]=vb.w;
    __syncthreads();
    float acc[2][4] = {};
    #pragma unroll
    for (int s = 0; s < 8; s++) {
        int cur = s & 1;
        if (s < 7) {
            va = fetchA(s+1);
            vb = *(const float4*)(Bm + (size_t)gc*Dm + (s+1)*16 + lc);
        }
        #pragma unroll
        for (int k = 0; k < 16; k++) {
            float2 a2 = *(const float2*)&As[cur][k][tr*2];
            float4 b4 = *(const float4*)&Bs[cur][k][tc*4];
            acc[0][0] += a2.x*b4.x; acc[0][1] += a2.x*b4.y;
            acc[0][2] += a2.x*b4.z; acc[0][3] += a2.x*b4.w;
            acc[1][0] += a2.y*b4.x; acc[1][1] += a2.y*b4.y;
            acc[1][2] += a2.y*b4.z; acc[1][3] += a2.y*b4.w;
        }
        if (s < 7) {
            int nxt = cur ^ 1;
            if (aload) {
                As[nxt][lc+0][ar]=va.x; As[nxt][lc+1][ar]=va.y; As[nxt][lc+2][ar]=va.z; As[nxt][lc+3][ar]=va.w;
            }
            Bs[nxt][lc+0][lr]=vb.x; Bs[nxt][lc+1][lr]=vb.y; Bs[nxt][lc+2][lr]=vb.z; Bs[nxt][lc+3][lr]=vb.w;
            __syncthreads();
        }
    }
    int c = c0 + tc*4;
    #pragma unroll
    for (int i = 0; i < 2; i++) {
        int r = r0 + tr*2 + i;
        if (r >= M) continue;
        float4 rv = *(const float4*)(d_HG + (size_t)r*Dm + c);
        *(float4*)(C + (size_t)r*Dm + c) =
            make_float4(acc[i][0]+rv.x, acc[i][1]+rv.y, acc[i][2]+rv.z, acc[i][3]+rv.w);
    }
}

// ------------------------- sparse attention, split-K + fused dense -----------
__device__ __forceinline__ void attn_word20(unsigned word, int base,
    const float4 q4[4], float cqx, float cqy,
    const float (*Ks)[20], const float (*Vs)[20],
    const float* ckx, const float* cky, const float* qerow,
    float& lrun, float acc[16])
{
    while (word) {
        int mm = base + (__ffs((int)word) - 1);
        word &= word - 1u;
        const float4* kp = (const float4*)Ks[mm];
        float4 k0 = kp[0], k1 = kp[1], k2 = kp[2], k3 = kp[3];
        float s = q4[0].x*k0.x + q4[0].y*k0.y + q4[0].z*k0.z + q4[0].w*k0.w
                + q4[1].x*k1.x + q4[1].y*k1.y + q4[1].z*k1.z + q4[1].w*k1.w
                + q4[2].x*k2.x + q4[2].y*k2.y + q4[2].z*k2.z + q4[2].w*k2.w
                + q4[3].x*k3.x + q4[3].y*k3.y + q4[3].z*k3.z + q4[3].w*k3.w;
        float dx = cqx - ckx[mm], dy = cqy - cky[mm];
        float dist = sqrtf(dx*dx + dy*dy);
        int bk = (int)(dist * 32.f); if (bk > 31) bk = 31;
        float p = __expf(s*SCALEf + qerow[bk]);
        lrun += p;
        const float4* vp = (const float4*)Vs[mm];
        float4 v0 = vp[0], v1 = vp[1], v2 = vp[2], v3 = vp[3];
        acc[ 0] += p*v0.x; acc[ 1] += p*v0.y; acc[ 2] += p*v0.z; acc[ 3] += p*v0.w;
        acc[ 4] += p*v1.x; acc[ 5] += p*v1.y; acc[ 6] += p*v1.z; acc[ 7] += p*v1.w;
        acc[ 8] += p*v2.x; acc[ 9] += p*v2.y; acc[10] += p*v2.z; acc[11] += p*v2.w;
        acc[12] += p*v3.x; acc[13] += p*v3.y; acc[14] += p*v3.z; acc[15] += p*v3.w;
    }
}

// grid (25, Hh, Bsz), 128 threads. x<24: sparse (qtile=x/3, kseg=x%3).
// x==24: dense rows {0, Nn} (64 threads each).
__global__ void k_attn(const float* __restrict__ coords)
{
    __shared__ float Ks[128][20];
    __shared__ float Vs[128][20];
    __shared__ float ckx[128], cky[128];
    __shared__ float qes[128][33];
    __shared__ float pw[4][17];
    int b = blockIdx.z, h = blockIdx.y;
    int x = blockIdx.x;
    int tid = threadIdx.x;
    const size_t hb = (size_t)(b*Hh + h)*N1;

    if (x == 24) {   // ---- dense rows ----
        int sub = tid >> 6, st = tid & 63;
        int lane = tid & 31, w = tid >> 5;
        int n = sub ? Nn : 0;
        float q[16];
        const float4* qp = (const float4*)(d_Q + (hb + n)*Dk);
        #pragma unroll
        for (int i = 0; i < 4; i++) {
            float4 v = qp[i];
            q[i*4+0]=v.x; q[i*4+1]=v.y; q[i*4+2]=v.z; q[i*4+3]=v.w;
        }
        float cqx = 0.f, cqy = 0.f;
        if (n < Nn) { cqx = coords[(b*Nn+n)*2]; cqy = coords[(b*Nn+n)*2+1]; }
        const float* qerow = d_QE + (hb + n)*NBk;
        float l = 0.f, acc[16];
        #pragma unroll
        for (int d = 0; d < 16; d++) acc[d] = 0.f;
        const float* Kt = d_Kb + hb*Dk;
        const float* Vt = d_Vb + hb*Dk;
        for (int mk = st; mk < N1; mk += 64) {
            const float4* kp = (const float4*)(Kt + (size_t)mk*Dk);
            float s = 0.f;
            #pragma unroll
            for (int i = 0; i < 4; i++) {
                float4 kv = kp[i];
                s += q[i*4+0]*kv.x + q[i*4+1]*kv.y + q[i*4+2]*kv.z + q[i*4+3]*kv.w;
            }
            float cmx = 0.f, cmy = 0.f;
            if (mk < Nn) { cmx = coords[(b*Nn+mk)*2]; cmy = coords[(b*Nn+mk)*2+1]; }
            float dx = cqx - cmx, dy = cqy - cmy;
            float dist = sqrtf(dx*dx + dy*dy);
            int bk = (int)(dist * 32.f); if (bk > 31) bk = 31;
            float p = __expf(s*SCALEf + qerow[bk]);
            l += p;
            const float4* vp = (const float4*)(Vt + (size_t)mk*Dk);
            #pragma unroll
            for (int i = 0; i < 4; i++) {
                float4 vv = vp[i];
                acc[i*4+0] += p*vv.x; acc[i*4+1] += p*vv.y;
                acc[i*4+2] += p*vv.z; acc[i*4+3] += p*vv.w;
            }
        }
        #pragma unroll
        for (int o = 16; o; o >>= 1) {
            l += __shfl_xor_sync(0xffffffffu, l, o);
            #pragma unroll
            for (int d = 0; d < 16; d++) acc[d] += __shfl_xor_sync(0xffffffffu, acc[d], o);
        }
        if (lane == 0) {
            #pragma unroll
            for (int d = 0; d < 16; d++) pw[w][d] = acc[d];
            pw[w][16] = l;
        }
        __syncthreads();
        if (tid == 0 || tid == 64) {
            int w0 = sub*2;
            float L = pw[w0][16] + pw[w0+1][16];
            float inv = 1.f / L;
            float* o = d_CTX + ((size_t)(b*N1 + n))*Dm + h*Dk;
            #pragma unroll
            for (int d = 0; d < 16; d++) o[d] = (pw[w0][d] + pw[w0+1][d]) * inv;
        }
        return;
    }

    // ---- sparse split-K ----
    int qt = x / 3, kseg = x % 3;
    int n = qt*128 + tid;              // 0..1023
    bool qv = (n != 0);                // row 0 is dense
    float4 q4[4];
    float cqx = 0.f, cqy = 0.f, lrun = 0.f;
    float acc[16];
    #pragma unroll
    for (int d = 0; d < 16; d++) acc[d] = 0.f;
    const unsigned* rowadj = d_ADJ + (size_t)(b*N1 + n)*AW;
    {
        const float4* qp = (const float4*)(d_Q + (hb + n)*Dk);
        #pragma unroll
        for (int i = 0; i < 4; i++) q4[i] = qp[i];
        cqx = coords[(b*Nn+n)*2]; cqy = coords[(b*Nn+n)*2+1];
        const float4* qep = (const float4*)(d_QE + (hb + n)*NBk);
        #pragma unroll
        for (int i = 0; i < 8; i++) {
            float4 v = qep[i];
            qes[tid][i*4+0]=v.x; qes[tid][i*4+1]=v.y;
            qes[tid][i*4+2]=v.z; qes[tid][i*4+3]=v.w;
        }
    }
    for (int kt = kseg*3; kt < kseg*3 + 3; kt++) {
        int m0 = kt*128;
        int tlen = N1 - m0; if (tlen > 128) tlen = 128;
        const float4* Kt = (const float4*)(d_Kb + (hb + m0)*Dk);
        const float4* Vt = (const float4*)(d_Vb + (hb + m0)*Dk);
        __syncthreads();
        #pragma unroll
        for (int i = 0; i < 4; i++) {
            int f = tid + i*128;
            int row = f >> 2, j = (f & 3)*4;
            if (row < tlen) {
                *(float4*)&Ks[row][j] = Kt[f];
                *(float4*)&Vs[row][j] = Vt[f];
            }
        }
        if (tid < tlen) {
            int m = m0 + tid;
            if (m < Nn) { ckx[tid] = coords[(b*Nn+m)*2]; cky[tid] = coords[(b*Nn+m)*2+1]; }
            else        { ckx[tid] = 0.f; cky[tid] = 0.f; }
        }
        __syncthreads();
        if (!qv) continue;
        int wb = m0 >> 5;
        unsigned w0 = rowadj[wb];
        unsigned w1 = (wb+1 < AW) ? rowadj[wb+1] : 0u;
        unsigned w2 = (wb+2 < AW) ? rowadj[wb+2] : 0u;
        unsigned w3 = (wb+3 < AW) ? rowadj[wb+3] : 0u;
        attn_word20(w0,  0, q4, cqx, cqy, Ks, Vs, ckx, cky, qes[tid], lrun, acc);
        attn_word20(w1, 32, q4, cqx, cqy, Ks, Vs, ckx, cky, qes[tid], lrun, acc);
        attn_word20(w2, 64, q4, cqx, cqy, Ks, Vs, ckx, cky, qes[tid], lrun, acc);
        attn_word20(w3, 96, q4, cqx, cqy, Ks, Vs, ckx, cky, qes[tid], lrun, acc);
    }
    if (qv) {
        size_t base = ((size_t)kseg*Bsz*N1 + (size_t)b*N1 + n)*Hh + h;
        float* pa = d_PA + base*PASTR;
        *(float4*)(pa+ 0) = make_float4(acc[ 0], acc[ 1], acc[ 2], acc[ 3]);
        *(float4*)(pa+ 4) = make_float4(acc[ 4], acc[ 5], acc[ 6], acc[ 7]);
        *(float4*)(pa+ 8) = make_float4(acc[ 8], acc[ 9], acc[10], acc[11]);
        *(float4*)(pa+12) = make_float4(acc[12], acc[13], acc[14], acc[15]);
        pa[16] = lrun;
    }
}

// ------------------------- instance norm: stats (partials) -------------------
__global__ void k_istat(const float* __restrict__ src)
{
    __shared__ float s1[2][Dm], s2[2][Dm];
    int b = blockIdx.x, z = blockIdx.y;
    int d = threadIdx.x & 127, g = threadIdx.x >> 7;
    int nend = z*64 + 64; if (nend > N1) nend = N1;
    const float* p = src + (size_t)b*N1*Dm + d;
    float a = 0.f, qq = 0.f;
    for (int n = z*64 + g; n < nend; n += 2) {
        float x = p[(size_t)n*Dm];
        a += x; qq += x*x;
    }
    s1[g][d] = a; s2[g][d] = qq;
    __syncthreads();
    if (g == 0) {
        d_PS1[(b*NCH + z)*Dm + d] = s1[0][d] + s1[1][d];
        d_PS2[(b*NCH + z)*Dm + d] = s2[0][d] + s2[1][d];
    }
}

// ------------------------- instance norm: apply ------------------------------
__global__ void k_iapply(const float* __restrict__ src, float* __restrict__ dst,
                         const float* __restrict__ w, const float* __restrict__ bb, int fuse)
{
    int b  = blockIdx.x;
    int dl = threadIdx.x & 31;
    int g  = threadIdx.x >> 5;
    int d  = blockIdx.y*32 + dl;
    int z  = blockIdx.z;
    float S1 = 0.f, S2 = 0.f;
    #pragma unroll
    for (int t = 0; t < NCH; t++) {
        S1 += d_PS1[(b*NCH + t)*Dm + d];
        S2 += d_PS2[(b*NCH + t)*Dm + d];
    }
    float mu  = S1 * (1.f/N1);
    float var = S2 * (1.f/N1) - mu*mu;
    float sc  = rsqrtf(var + EPSf) * w[d];
    float sh  = bb[d];
    const float* p = src + (size_t)b*N1*Dm + d;
    float* o = dst + (size_t)b*N1*Dm + d;
    float mo = 0.f;
    if (fuse) mo = ((S1 - p[(size_t)Nn*Dm])*(1.f/Nn) - mu)*sc + sh;
    int n0 = z*128, n1 = (z == 7) ? N1 : (z+1)*128;
    for (int n = n0 + g; n < n1; n += 32) {
        float val = (p[(size_t)n*Dm] - mu)*sc + sh;
        if (fuse && n == Nn) val += mo;
        o[(size_t)n*Dm] = val;
    }
    if (fuse && z == 7 && g == 0) d_POOL[b*Dm + d] += mo;
}

// ------------------------- final GEMM: out = (h + pool/3) @ outW^T + outb ----
__global__ void k_fgemm(const float* __restrict__ Bm, const float* __restrict__ bias,
                        float* __restrict__ out)
{
    __shared__ __align__(16) float As[2][16][68];
    __shared__ __align__(16) float Bs[2][16][68];
    int tid = threadIdx.x;
    int tr = tid >> 4, tc = tid & 15;
    int r0 = blockIdx.y*64, c0 = blockIdx.x*64;
    int lr = tid >> 2;
    int lc = (tid & 3) * 4;
    int gr = r0 + lr;
    int bb = gr >> 10, nn = gr & 1023;
    const float* Arow = d_HG + ((size_t)bb*N1 + nn)*Dm;
    const float* Prow = d_POOL + bb*Dm;
    int gc = c0 + lr;
    if (blockIdx.x == 0 && blockIdx.y == 0 && tid < Bsz*Dm)
        out[Bsz*Nn*Dm + tid] = d_POOL[tid] * (1.f/3.f);
    float4 va, vb;
    {
        float4 hv = *(const float4*)(Arow + lc);
        float4 pv = *(const float4*)(Prow + lc);
        va = make_float4(hv.x + pv.x*(1.f/3.f), hv.y + pv.y*(1.f/3.f),
                         hv.z + pv.z*(1.f/3.f), hv.w + pv.w*(1.f/3.f));
        vb = *(const float4*)(Bm + (size_t)gc*Dm + lc);
    }
    As[0][lc+0][lr]=va.x; As[0][lc+1][lr]=va.y; As[0][lc+2][lr]=va.z; As[0][lc+3][lr]=va.w;
    Bs[0][lc+0][lr]=vb.x; Bs[0][lc+1][lr]=vb.y; Bs[0][lc+2][lr]=vb.z; Bs[0][lc+3][lr]=vb.w;
    __syncthreads();
    float acc[4][4] = {};
    #pragma unroll
    for (int s = 0; s < 8; s++) {
        int cur = s & 1;
        if (s < 7) {
            float4 hv = *(const float4*)(Arow + (s+1)*16 + lc);
            float4 pv = *(const float4*)(Prow + (s+1)*16 + lc);
            va = make_float4(hv.x + pv.x*(1.f/3.f), hv.y + pv.y*(1.f/3.f),
                             hv.z + pv.z*(1.f/3.f), hv.w + pv.w*(1.f/3.f));
            vb = *(const float4*)(Bm + (size_t)gc*Dm + (s+1)*16 + lc);
        }
        #pragma unroll
        for (int k = 0; k < 16; k++) {
            float4 a4 = *(const float4*)&As[cur][k][tr*4];
            float4 b4 = *(const float4*)&Bs[cur][k][tc*4];
            float a[4] = {a4.x, a4.y, a4.z, a4.w};
            float bv[4] = {b4.x, b4.y, b4.z, b4.w};
            #pragma unroll
            for (int i = 0; i < 4; i++)
                #pragma unroll
                for (int j = 0; j < 4; j++) acc[i][j] += a[i]*bv[j];
        }
        if (s < 7) {
            int nxt = cur ^ 1;
            As[nxt][lc+0][lr]=va.x; As[nxt][lc+1][lr]=va.y; As[nxt][lc+2][lr]=va.z; As[nxt][lc+3][lr]=va.w;
            Bs[nxt][lc+0][lr]=vb.x; Bs[nxt][lc+1][lr]=vb.y; Bs[nxt][lc+2][lr]=vb.z; Bs[nxt][lc+3][lr]=vb.w;
            __syncthreads();
        }
    }
    int c = c0 + tc*4;
    float4 bz = *(const float4*)(bias + c);
    #pragma unroll
    for (int i = 0; i < 4; i++) {
        int r = r0 + tr*4 + i;
        *(float4*)(out + (size_t)r*Dm + c) =
            make_float4(acc[i][0]+bz.x, acc[i][1]+bz.y, acc[i][2]+bz.z, acc[i][3]+bz.w);
    }
}

// ------------------------- host driver ---------------------------------------
extern "C" void kernel_launch(void* const* d_in, const int* in_sizes, int n_in,
                              void* d_out, int out_size)
{
    const float* coords = (const float*)d_in[0];
    const float* in_W   = (const float*)d_in[1];
    const float* in_b   = (const float*)d_in[2];
    const float* gnode  = (const float*)d_in[3];
    const float* Wq     = (const float*)d_in[4];
    const float* Wk     = (const float*)d_in[5];
    const float* Wv     = (const float*)d_in[6];
    const float* Wo     = (const float*)d_in[7];
    const float* emb    = (const float*)d_in[8];
    const float* W1     = (const float*)d_in[9];
    const float* b1     = (const float*)d_in[10];
    const float* W2     = (const float*)d_in[11];
    const float* b2     = (const float*)d_in[12];
    const float* n1w    = (const float*)d_in[13];
    const float* n1b    = (const float*)d_in[14];
    const float* n2w    = (const float*)d_in[15];
    const float* n2b    = (const float*)d_in[16];
    const float* outW   = (const float*)d_in[17];
    const float* outb   = (const float*)d_in[18];
    float* out = (float*)d_out;

    float *HG, *Y, *T1, *T2;
    cudaGetSymbolAddress((void**)&HG,  d_HG);
    cudaGetSymbolAddress((void**)&Y,   d_Y);
    cudaGetSymbolAddress((void**)&T1,  d_T1);
    cudaGetSymbolAddress((void**)&T2,  d_T2);

    const int Mall = Bsz*N1;  // 2050

    k_input<<<(Bsz*N1*Dm + 255)/256, 256>>>(coords, in_W, in_b, gnode);
    k_colmean<<<Bsz, 1024>>>();                            // layer-0 g update

    for (int l = 0; l < 3; l++) {
        k_par1<<<983, 256>>>(Wq + (size_t)l*Dm*Dm, Wk + (size_t)l*Dm*Dm, Wv + (size_t)l*Dm*Dm);
        k_par2<<<769, 256>>>(emb + (size_t)l*NBk*Dm);
        { dim3 ga(25, Hh, Bsz); k_attn<<<ga, 128>>>(coords); }

        { dim3 gq(Dm/64, (Mall + 31)/32);
          k_gemmC<<<gq, 256>>>(Wo + (size_t)l*Dm*Dm, Y); }
        { dim3 gs(Bsz, NCH); k_istat<<<gs, 256>>>(Y); }
        { dim3 gi(Bsz, 4, 8); k_iapply<<<gi, 1024>>>(Y, Y, n1w + l*Dm, n1b + l*Dm, 0); }

        { dim3 g1(Dff/64, (Mall + 63)/64);
          k_gemm<<<g1, 256>>>(Y,  W1 + (size_t)l*Dff*Dm, b1 + l*Dff, nullptr, T1, Mall, Dff, Dm, 1|4); }
        { dim3 g2(Dm/64, (Mall + 31)/32);
          k_gemmS<<<g2, 256>>>(T1, W2 + (size_t)l*Dm*Dff, b2 + l*Dm, Y, T2, Mall, Dm, Dff, 1|2); }
        { dim3 gs(Bsz, NCH); k_istat<<<gs, 256>>>(T2); }
        { dim3 gi(Bsz, 4, 8); k_iapply<<<gi, 1024>>>(T2, HG, n2w + l*Dm, n2b + l*Dm, 1); }
    }

    { dim3 ge(Dm/64, (Bsz*Nn)/64); k_fgemm<<<ge, 256>>>(outW, outb, out); }
}